// round 7
// baseline (speedup 1.0000x reference)
#include <cuda_runtime.h>
#include <math.h>
#include <stdint.h>

#define BATCH   4
#define LSEQ    2048
#define ROWS    (BATCH*LSEQ)      // 8192
#define DMODEL  768
#define DINNER  1536
#define NHEADS  24
#define HEADDIM 64
#define DSTATE  128
#define CONVDIM 1792
#define DPROJ   3352              // 2*DINNER + 2*DSTATE + NHEADS

#define NSEG    16
#define SEGLEN  (LSEQ/NSEG)       // 128
#define STATESZ (HEADDIM*DSTATE)  // 8192

// -------- scratch (device globals; no allocation allowed) --------
__device__ float g_zxbcdt[(size_t)ROWS * DPROJ];   // in_proj output
__device__ float g_xBC[(size_t)ROWS * CONVDIM];    // conv+silu output
__device__ float g_dt[ROWS * NHEADS];
__device__ float g_y[(size_t)ROWS * DINNER];       // scan output -> gated/normed
__device__ float g_states[(size_t)BATCH*NHEADS*NSEG*STATESZ];  // segment end states
__device__ float g_hstart[(size_t)BATCH*NHEADS*NSEG*STATESZ];  // segment start states

// =================================================================
// common PTX helpers
// =================================================================
__device__ __forceinline__ uint32_t f2tf32(float x) {
    uint32_t r;
    asm("cvt.rna.tf32.f32 %0, %1;" : "=r"(r) : "f"(x));
    return r;
}
// split fp32 into tf32 hi + tf32 lo (3xTF32 error compensation)
__device__ __forceinline__ void tsplit(float v, uint32_t& hi, uint32_t& lo) {
    hi = f2tf32(v);
    lo = f2tf32(v - __uint_as_float(hi));
}

#define CPA16(dst, src) \
    asm volatile("cp.async.cg.shared.global [%0], [%1], 16;\n" \
                 :: "r"(dst), "l"(src))
#define CPA16P(dst, src, valid) \
    asm volatile("cp.async.cg.shared.global [%0], [%1], 16, %2;\n" \
                 :: "r"(dst), "l"(src), "r"((valid) ? 16 : 0))
#define CPA_COMMIT() asm volatile("cp.async.commit_group;\n" ::: "memory")
#define CPA_WAIT0()  asm volatile("cp.async.wait_group 0;\n" ::: "memory")
#define CPA_WAIT1()  asm volatile("cp.async.wait_group 1;\n" ::: "memory")

#define MMA_TF32(d, a, b) \
    asm volatile("mma.sync.aligned.m16n8k8.row.col.f32.tf32.tf32.f32 " \
                 "{%0,%1,%2,%3},{%4,%5,%6,%7},{%8,%9},{%0,%1,%2,%3};\n" \
                 : "+f"((d)[0]), "+f"((d)[1]), "+f"((d)[2]), "+f"((d)[3]) \
                 : "r"((a)[0]), "r"((a)[1]), "r"((a)[2]), "r"((a)[3]), \
                   "r"((b)[0]), "r"((b)[1]))

// 3xTF32: d += a*b with error compensation
#define MMA3(d, ah, al, bhv, blv) do { \
    MMA_TF32(d, al, bhv); \
    MMA_TF32(d, ah, blv); \
    MMA_TF32(d, ah, bhv); } while (0)

// =================================================================
// TF32 tensor-core GEMM (NT): C[M,N] = A[M,K] * B[N,K]^T
// BM=128, BN=128, BK=32, 3-stage cp.async pipeline, 256 threads
// =================================================================
#define BM 128
#define BN 128
#define BKT 32
#define GSTRIDE 36
#define GT_FLOATS (128*GSTRIDE)                 // 4608 floats per tile
#define GEMM_SMEM_FLOATS (3*2*GT_FLOATS)        // 27648 floats = 108KB

__global__ __launch_bounds__(256) void gemm_tf32(
    const float* __restrict__ A, const float* __restrict__ B,
    float* __restrict__ C, int M, int N, int K,
    const float* __restrict__ gate)
{
    extern __shared__ float gsm[];

    const int tid  = threadIdx.x;
    const int lane = tid & 31;
    const int warp = tid >> 5;
    const int wm   = warp >> 2;
    const int wn   = warp & 3;
    const int m0   = blockIdx.y * BM;
    const int n0   = blockIdx.x * BN;
    const int qr   = lane >> 2;
    const int ql   = lane & 3;

    // load mapping: 1024 16B-chunks per tile, 4 per thread
    int arow[4], acol[4];
    bool bval[4];
    const float* Agp[4];
    const float* Bgp[4];
    #pragma unroll
    for (int q = 0; q < 4; q++) {
        int c = tid + q * 256;
        arow[q] = c >> 3;
        acol[q] = (c & 7) * 4;
        Agp[q]  = A + (size_t)(m0 + arow[q]) * K + acol[q];
        bval[q] = (n0 + arow[q]) < N;
        Bgp[q]  = B + (size_t)min(n0 + arow[q], N - 1) * K + acol[q];
    }

    float acc[4][4][4];
    #pragma unroll
    for (int i = 0; i < 4; i++)
        #pragma unroll
        for (int j = 0; j < 4; j++)
            #pragma unroll
            for (int r = 0; r < 4; r++) acc[i][j][r] = 0.f;

    const int KT = K / BKT;

    #define G_ISSUE(kt, s)                                                     \
    {                                                                          \
        float* As_ = gsm + (s) * 2 * GT_FLOATS;                                \
        float* Bs_ = As_ + GT_FLOATS;                                          \
        const size_t ko = (size_t)(kt) * BKT;                                  \
        _Pragma("unroll")                                                      \
        for (int q = 0; q < 4; q++) {                                          \
            CPA16((uint32_t)__cvta_generic_to_shared(                         \
                      &As_[arow[q]*GSTRIDE + acol[q]]), Agp[q] + ko);          \
            CPA16P((uint32_t)__cvta_generic_to_shared(                        \
                      &Bs_[arow[q]*GSTRIDE + acol[q]]), Bgp[q] + ko, bval[q]); \
        }                                                                      \
        CPA_COMMIT();                                                          \
    }

    G_ISSUE(0, 0);
    if (KT > 1) G_ISSUE(1, 1);

    int st = 0;
    for (int kt = 0; kt < KT; kt++) {
        if (kt + 1 < KT) { CPA_WAIT1(); } else { CPA_WAIT0(); }
        __syncthreads();

        if (kt + 2 < KT) {
            int ns = st + 2; if (ns >= 3) ns -= 3;
            G_ISSUE(kt + 2, ns);
        }

        const float* As_ = gsm + st * 2 * GT_FLOATS;
        const float* Bs_ = As_ + GT_FLOATS;

        #pragma unroll
        for (int kk = 0; kk < BKT; kk += 8) {
            uint32_t a[4][4], b[4][2];
            const int qc = kk + ql;
            #pragma unroll
            for (int mf = 0; mf < 4; mf++) {
                const int r = wm * 64 + mf * 16 + qr;
                a[mf][0] = f2tf32(As_[r*GSTRIDE + qc]);
                a[mf][1] = f2tf32(As_[(r+8)*GSTRIDE + qc]);
                a[mf][2] = f2tf32(As_[r*GSTRIDE + qc + 4]);
                a[mf][3] = f2tf32(As_[(r+8)*GSTRIDE + qc + 4]);
            }
            #pragma unroll
            for (int nf = 0; nf < 4; nf++) {
                const int r = wn * 32 + nf * 8 + qr;
                b[nf][0] = f2tf32(Bs_[r*GSTRIDE + qc]);
                b[nf][1] = f2tf32(Bs_[r*GSTRIDE + qc + 4]);
            }
            #pragma unroll
            for (int mf = 0; mf < 4; mf++)
                #pragma unroll
                for (int nf = 0; nf < 4; nf++)
                    MMA_TF32(acc[mf][nf], a[mf], b[nf]);
        }

        __syncthreads();     // stage free for reuse by G_ISSUE 2 iters later
        st++; if (st >= 3) st = 0;
    }
    #undef G_ISSUE

    float scale = 1.f;
    if (gate) { float g = *gate; scale = 1.f / (1.f + expf(-g)); }

    #pragma unroll
    for (int mf = 0; mf < 4; mf++) {
        const int r = m0 + wm * 64 + mf * 16 + qr;
        #pragma unroll
        for (int nf = 0; nf < 4; nf++) {
            const int c = n0 + wn * 32 + nf * 8 + ql * 2;
            if (c < N) {
                float2 v0 = make_float2(acc[mf][nf][0] * scale, acc[mf][nf][1] * scale);
                float2 v1 = make_float2(acc[mf][nf][2] * scale, acc[mf][nf][3] * scale);
                *(float2*)&C[(size_t)r * N + c]       = v0;
                *(float2*)&C[(size_t)(r + 8) * N + c] = v1;
            }
        }
    }
}

// =================================================================
// Causal depthwise conv1d (width 4) + bias + SiLU on xBC slice
// =================================================================
__global__ __launch_bounds__(256) void conv_silu_kernel(
    const float* __restrict__ conv_w, const float* __restrict__ conv_b)
{
    const long idx = (long)blockIdx.x * 256 + threadIdx.x;
    const int  c   = (int)(idx % CONVDIM);
    const long row = idx / CONVDIM;
    const int  l   = (int)(row % LSEQ);

    float acc = conv_b[c];
    const float w0 = conv_w[c*4+0], w1 = conv_w[c*4+1];
    const float w2 = conv_w[c*4+2], w3 = conv_w[c*4+3];
    const float* base = g_zxbcdt + (size_t)row * DPROJ + DINNER + c;
    if (l >= 3) acc = fmaf(base[-3*DPROJ], w0, acc);
    if (l >= 2) acc = fmaf(base[-2*DPROJ], w1, acc);
    if (l >= 1) acc = fmaf(base[-1*DPROJ], w2, acc);
    acc = fmaf(base[0], w3, acc);
    g_xBC[idx] = acc / (1.f + expf(-acc));
}

// =================================================================
// dt = softplus(dt_raw + dt_bias)
// =================================================================
__global__ __launch_bounds__(256) void dt_kernel(const float* __restrict__ dt_bias)
{
    const int idx = blockIdx.x * 256 + threadIdx.x;
    const int h   = idx % NHEADS;
    const int row = idx / NHEADS;
    float v  = g_zxbcdt[(size_t)row * DPROJ + (DINNER + CONVDIM) + h] + dt_bias[h];
    float sp = (v > 20.f) ? v : log1pf(expf(v));
    g_dt[idx] = sp;
}

// =================================================================
// K1: fused per-chunk tensor-core kernel (3xTF32).
// =================================================================
#define K1_SMEM_FLOATS 42628
#define K3_SMEM_FLOATS 25476

__global__ __launch_bounds__(256) void chunk_fused_kernel(
    const float* __restrict__ A_log, const float* __restrict__ Dvec)
{
    extern __shared__ float sm[];
    float* Csm = sm;
    float* Bsm = sm + 16896;
    float* xT  = sm + 33792;
    float* sa  = sm + 42240;
    float* sdt = sm + 42368;
    float* sw  = sm + 42496;
    float* wsum4 = sm + 42624;

    const int blk = blockIdx.x;
    const int bh = blk >> 4, seg = blk & (NSEG - 1);
    const int b = bh / NHEADS, h = bh % NHEADS;
    const int tid = threadIdx.x, lane = tid & 31, warp = tid >> 5;
    const int qr = lane >> 2, ql = lane & 3;
    const size_t rowbase = (size_t)b * LSEQ + seg * SEGLEN;

    // ---- cp.async: B tile [t][n] and C tile [t][n] (128 rows x 32 chunks) ----
    #pragma unroll
    for (int i = 0; i < 16; i++) {
        int e = tid + i * 256;            // < 4096
        int t = e >> 5, ch = (e & 31) * 4;
        const float* srcB = g_xBC + (rowbase + t) * CONVDIM + DINNER + ch;   // B cols
        CPA16((uint32_t)__cvta_generic_to_shared(&Bsm[t*132 + ch]), srcB);
        CPA16((uint32_t)__cvta_generic_to_shared(&Csm[t*132 + ch]), srcB + DSTATE);
    }
    CPA_COMMIT();

    // ---- dt cumsum / weights ----
    const float Aneg = -expf(A_log[h]);
    float vdt = 0.f, acs = 0.f;
    if (tid < SEGLEN) {
        vdt = g_dt[(rowbase + tid) * NHEADS + h];
        acs = vdt;
        #pragma unroll
        for (int o = 1; o < 32; o <<= 1) {
            float nv = __shfl_up_sync(0xffffffffu, acs, o);
            if (lane >= o) acs += nv;
        }
        if (lane == 31) wsum4[warp] = acs;
    }
    __syncthreads();
    if (tid < SEGLEN) {
        float tot = wsum4[0] + wsum4[1] + wsum4[2] + wsum4[3];
        float pre = 0.f;
        #pragma unroll
        for (int w2 = 0; w2 < 4; w2++) if (w2 < warp) pre += wsum4[w2];
        float a = acs + pre;
        sa[tid]  = a;
        sdt[tid] = vdt;
        sw[tid]  = vdt * __expf(Aneg * (tot - a));
    }

    // ---- x load + transpose into xT[p][s] ----
    #pragma unroll
    for (int i = 0; i < 8; i++) {
        int e = tid + i * 256;            // < 2048 (128 s x 16 p-chunks)
        int s = e >> 4, p0 = (e & 15) * 4;
        float4 v = *(const float4*)(g_xBC + (rowbase + s) * CONVDIM + h * HEADDIM + p0);
        xT[(p0+0)*132 + s] = v.x;
        xT[(p0+1)*132 + s] = v.y;
        xT[(p0+2)*132 + s] = v.z;
        xT[(p0+3)*132 + s] = v.w;
    }

    CPA_WAIT0();
    __syncthreads();

    // ================= GEMM1: M = C @ B^T =================
    float mreg[4][4][4];
    #pragma unroll
    for (int i = 0; i < 4; i++)
        #pragma unroll
        for (int j = 0; j < 4; j++)
            #pragma unroll
            for (int r = 0; r < 4; r++) mreg[i][j][r] = 0.f;

    const int m1 = (warp >> 2) * 64, n1 = (warp & 3) * 32;
    #pragma unroll 2
    for (int k = 0; k < 128; k += 8) {
        uint32_t ah[4][4], al[4][4], bh2[4][2], bl2[4][2];
        #pragma unroll
        for (int mf = 0; mf < 4; mf++) {
            int r = m1 + mf*16 + qr;
            tsplit(Csm[r*132 + k + ql],         ah[mf][0], al[mf][0]);
            tsplit(Csm[(r+8)*132 + k + ql],     ah[mf][1], al[mf][1]);
            tsplit(Csm[r*132 + k + 4 + ql],     ah[mf][2], al[mf][2]);
            tsplit(Csm[(r+8)*132 + k + 4 + ql], ah[mf][3], al[mf][3]);
        }
        #pragma unroll
        for (int nf = 0; nf < 4; nf++) {
            int r = n1 + nf*8 + qr;
            tsplit(Bsm[r*132 + k + ql],     bh2[nf][0], bl2[nf][0]);
            tsplit(Bsm[r*132 + k + 4 + ql], bh2[nf][1], bl2[nf][1]);
        }
        #pragma unroll
        for (int mf = 0; mf < 4; mf++)
            #pragma unroll
            for (int nf = 0; nf < 4; nf++)
                MMA3(mreg[mf][nf], ah[mf], al[mf], bh2[nf], bl2[nf]);
    }
    __syncthreads();   // all warps done reading Csm

    // ---- mask + store M~ over Csm ----
    #pragma unroll
    for (int mf = 0; mf < 4; mf++) {
        int tA = m1 + mf*16 + qr, tB = tA + 8;
        float aA = sa[tA], aB = sa[tB];
        #pragma unroll
        for (int nf = 0; nf < 4; nf++) {
            int s0 = n1 + nf*8 + ql*2, s1 = s0 + 1;
            float as0 = sa[s0], as1 = sa[s1];
            float d0 = sdt[s0], d1 = sdt[s1];
            float v00 = (s0 <= tA) ? mreg[mf][nf][0] * __expf(Aneg*(aA-as0)) * d0 : 0.f;
            float v01 = (s1 <= tA) ? mreg[mf][nf][1] * __expf(Aneg*(aA-as1)) * d1 : 0.f;
            float v10 = (s0 <= tB) ? mreg[mf][nf][2] * __expf(Aneg*(aB-as0)) * d0 : 0.f;
            float v11 = (s1 <= tB) ? mreg[mf][nf][3] * __expf(Aneg*(aB-as1)) * d1 : 0.f;
            Csm[tA*132 + s0] = v00;  Csm[tA*132 + s1] = v01;
            Csm[tB*132 + s0] = v10;  Csm[tB*132 + s1] = v11;
        }
    }
    __syncthreads();

    // ================= GEMM2: Y = M~ @ X (B-op = xT[p][s]) =================
    {
        float yreg[2][4][4];
        #pragma unroll
        for (int i = 0; i < 2; i++)
            #pragma unroll
            for (int j = 0; j < 4; j++)
                #pragma unroll
                for (int r = 0; r < 4; r++) yreg[i][j][r] = 0.f;

        const int m2 = (warp >> 1) * 32, n2 = (warp & 1) * 32;
        #pragma unroll 2
        for (int k = 0; k < 128; k += 8) {
            uint32_t ah[2][4], al[2][4], bh2[4][2], bl2[4][2];
            #pragma unroll
            for (int mf = 0; mf < 2; mf++) {
                int r = m2 + mf*16 + qr;
                tsplit(Csm[r*132 + k + ql],         ah[mf][0], al[mf][0]);
                tsplit(Csm[(r+8)*132 + k + ql],     ah[mf][1], al[mf][1]);
                tsplit(Csm[r*132 + k + 4 + ql],     ah[mf][2], al[mf][2]);
                tsplit(Csm[(r+8)*132 + k + 4 + ql], ah[mf][3], al[mf][3]);
            }
            #pragma unroll
            for (int nf = 0; nf < 4; nf++) {
                int r = n2 + nf*8 + qr;
                tsplit(xT[r*132 + k + ql],     bh2[nf][0], bl2[nf][0]);
                tsplit(xT[r*132 + k + 4 + ql], bh2[nf][1], bl2[nf][1]);
            }
            #pragma unroll
            for (int mf = 0; mf < 2; mf++)
                #pragma unroll
                for (int nf = 0; nf < 4; nf++)
                    MMA3(yreg[mf][nf], ah[mf], al[mf], bh2[nf], bl2[nf]);
        }

        const float Dh = Dvec[h];
        #pragma unroll
        for (int mf = 0; mf < 2; mf++) {
            int t = m2 + mf*16 + qr;
            #pragma unroll
            for (int nf = 0; nf < 4; nf++) {
                int p0 = n2 + nf*8 + ql*2;
                float2 o;
                o.x = yreg[mf][nf][0] + Dh * xT[p0*132 + t];
                o.y = yreg[mf][nf][1] + Dh * xT[(p0+1)*132 + t];
                *(float2*)&g_y[(rowbase + t)*DINNER + h*HEADDIM + p0] = o;
                o.x = yreg[mf][nf][2] + Dh * xT[p0*132 + t + 8];
                o.y = yreg[mf][nf][3] + Dh * xT[(p0+1)*132 + t + 8];
                *(float2*)&g_y[(rowbase + t + 8)*DINNER + h*HEADDIM + p0] = o;
            }
        }
    }

    // ================= GEMM3: S = (w.X)^T @ B =================
    {
        float sreg[2][4][4];
        #pragma unroll
        for (int i = 0; i < 2; i++)
            #pragma unroll
            for (int j = 0; j < 4; j++)
                #pragma unroll
                for (int r = 0; r < 4; r++) sreg[i][j][r] = 0.f;

        const int m3 = (warp >> 2) * 32, n3 = (warp & 3) * 32;
        #pragma unroll 2
        for (int k = 0; k < 128; k += 8) {
            float w0 = sw[k + ql], w4 = sw[k + 4 + ql];
            uint32_t ah[2][4], al[2][4], bh2[4][2], bl2[4][2];
            #pragma unroll
            for (int mf = 0; mf < 2; mf++) {
                int r = m3 + mf*16 + qr;
                tsplit(xT[r*132 + k + ql] * w0,         ah[mf][0], al[mf][0]);
                tsplit(xT[(r+8)*132 + k + ql] * w0,     ah[mf][1], al[mf][1]);
                tsplit(xT[r*132 + k + 4 + ql] * w4,     ah[mf][2], al[mf][2]);
                tsplit(xT[(r+8)*132 + k + 4 + ql] * w4, ah[mf][3], al[mf][3]);
            }
            #pragma unroll
            for (int nf = 0; nf < 4; nf++) {
                int n = n3 + nf*8 + qr;
                tsplit(Bsm[(k + ql)*132 + n],     bh2[nf][0], bl2[nf][0]);   // NN-indexed
                tsplit(Bsm[(k + 4 + ql)*132 + n], bh2[nf][1], bl2[nf][1]);
            }
            #pragma unroll
            for (int mf = 0; mf < 2; mf++)
                #pragma unroll
                for (int nf = 0; nf < 4; nf++)
                    MMA3(sreg[mf][nf], ah[mf], al[mf], bh2[nf], bl2[nf]);
        }

        const size_t sbase = ((size_t)bh * NSEG + seg) * STATESZ;
        #pragma unroll
        for (int mf = 0; mf < 2; mf++) {
            int p = m3 + mf*16 + qr;
            #pragma unroll
            for (int nf = 0; nf < 4; nf++) {
                int n0 = n3 + nf*8 + ql*2;
                float2 o0 = make_float2(sreg[mf][nf][0], sreg[mf][nf][1]);
                float2 o1 = make_float2(sreg[mf][nf][2], sreg[mf][nf][3]);
                *(float2*)&g_states[sbase + (size_t)p * DSTATE + n0]       = o0;
                *(float2*)&g_states[sbase + (size_t)(p + 8) * DSTATE + n0] = o1;
            }
        }
    }
}

// =================================================================
// K2: combine: h_start[seg+1] = E_seg * h_start[seg] + S_seg
// =================================================================
__global__ __launch_bounds__(256) void combine_kernel(const float* __restrict__ A_log)
{
    const int bh = blockIdx.x;
    const int b = bh / NHEADS, h = bh % NHEADS;
    const int tid = threadIdx.x;

    __shared__ float part[256];
    __shared__ float Esh[NSEG];

    {
        const int k = tid >> 4, i = tid & 15;
        float s = 0.f;
        const size_t base = ((size_t)b*LSEQ + k*SEGLEN + i*8)*NHEADS + h;
        #pragma unroll
        for (int t = 0; t < 8; t++) s += g_dt[base + (size_t)t*NHEADS];
        part[tid] = s;
    }
    __syncthreads();
    if (tid < NSEG) {
        float s = 0.f;
        #pragma unroll
        for (int i = 0; i < 16; i++) s += part[tid*16 + i];
        Esh[tid] = expf(-expf(A_log[h]) * s);
    }
    __syncthreads();

    float hs[32];
    #pragma unroll
    for (int k2 = 0; k2 < 32; k2++) hs[k2] = 0.f;

    for (int seg = 0; seg < NSEG; seg++) {
        const size_t base = ((size_t)bh*NSEG + seg)*STATESZ;
        const float E = Esh[seg];
        #pragma unroll
        for (int k2 = 0; k2 < 32; k2++) {
            const size_t e = base + k2*256 + tid;
            g_hstart[e] = hs[k2];
            hs[k2] = fmaf(hs[k2], E, g_states[e]);
        }
    }
}

// =================================================================
// K3: inter-chunk: Y += exp(A*a_t) * (C @ hstart^T)   (3xTF32)
// =================================================================
__global__ __launch_bounds__(256) void inter_kernel(const float* __restrict__ A_log)
{
    extern __shared__ float sm[];
    float* Csm = sm;
    float* Hsm = sm + 16896;
    float* su  = sm + 25344;
    float* wsum4 = sm + 25472;

    const int blk = blockIdx.x;
    const int bh = blk >> 4, seg = blk & (NSEG - 1);
    const int b = bh / NHEADS, h = bh % NHEADS;
    const int tid = threadIdx.x, lane = tid & 31, warp = tid >> 5;
    const int qr = lane >> 2, ql = lane & 3;
    const size_t rowbase = (size_t)b * LSEQ + seg * SEGLEN;
    const size_t hbase = ((size_t)bh * NSEG + seg) * STATESZ;

    // C tile: 128 rows x 32 chunks
    #pragma unroll
    for (int i = 0; i < 16; i++) {
        int e = tid + i * 256;            // < 4096
        int t = e >> 5, ch = (e & 31) * 4;
        const float* srcC = g_xBC + (rowbase + t) * CONVDIM + DINNER + DSTATE + ch;
        CPA16((uint32_t)__cvta_generic_to_shared(&Csm[t*132 + ch]), srcC);
    }
    // H tile: 64 rows x 32 chunks
    #pragma unroll
    for (int i = 0; i < 8; i++) {
        int e = tid + i * 256;            // < 2048
        int p = e >> 5, ch = (e & 31) * 4;
        const float* srcH = g_hstart + hbase + (size_t)p * DSTATE + ch;
        CPA16((uint32_t)__cvta_generic_to_shared(&Hsm[p*132 + ch]), srcH);
    }
    CPA_COMMIT();

    // cumsum -> u_t = exp(A * a_t)
    const float Aneg = -expf(A_log[h]);
    float vdt = 0.f, acs = 0.f;
    if (tid < SEGLEN) {
        vdt = g_dt[(rowbase + tid) * NHEADS + h];
        acs = vdt;
        #pragma unroll
        for (int o = 1; o < 32; o <<= 1) {
            float nv = __shfl_up_sync(0xffffffffu, acs, o);
            if (lane >= o) acs += nv;
        }
        if (lane == 31) wsum4[warp] = acs;
    }
    __syncthreads();
    if (tid < SEGLEN) {
        float pre = 0.f;
        #pragma unroll
        for (int w2 = 0; w2 < 4; w2++) if (w2 < warp) pre += wsum4[w2];
        su[tid] = __expf(Aneg * (acs + pre));
    }

    CPA_WAIT0();
    __syncthreads();

    float yreg[2][4][4];
    #pragma unroll
    for (int i = 0; i < 2; i++)
        #pragma unroll
        for (int j = 0; j < 4; j++)
            #pragma unroll
            for (int r = 0; r < 4; r++) yreg[i][j][r] = 0.f;

    const int m2 = (warp >> 1) * 32, n2 = (warp & 1) * 32;
    #pragma unroll 2
    for (int k = 0; k < 128; k += 8) {
        uint32_t ah[2][4], al[2][4], bh2[4][2], bl2[4][2];
        #pragma unroll
        for (int mf = 0; mf < 2; mf++) {
            int r = m2 + mf*16 + qr;
            tsplit(Csm[r*132 + k + ql],         ah[mf][0], al[mf][0]);
            tsplit(Csm[(r+8)*132 + k + ql],     ah[mf][1], al[mf][1]);
            tsplit(Csm[r*132 + k + 4 + ql],     ah[mf][2], al[mf][2]);
            tsplit(Csm[(r+8)*132 + k + 4 + ql], ah[mf][3], al[mf][3]);
        }
        #pragma unroll
        for (int nf = 0; nf < 4; nf++) {
            int r = n2 + nf*8 + qr;
            tsplit(Hsm[r*132 + k + ql],     bh2[nf][0], bl2[nf][0]);
            tsplit(Hsm[r*132 + k + 4 + ql], bh2[nf][1], bl2[nf][1]);
        }
        #pragma unroll
        for (int mf = 0; mf < 2; mf++)
            #pragma unroll
            for (int nf = 0; nf < 4; nf++)
                MMA3(yreg[mf][nf], ah[mf], al[mf], bh2[nf], bl2[nf]);
    }

    #pragma unroll
    for (int mf = 0; mf < 2; mf++) {
        int t = m2 + mf*16 + qr;
        float u0 = su[t], u1 = su[t + 8];
        #pragma unroll
        for (int nf = 0; nf < 4; nf++) {
            int p0 = n2 + nf*8 + ql*2;
            float* addr0 = &g_y[(rowbase + t)*DINNER + h*HEADDIM + p0];
            float* addr1 = &g_y[(rowbase + t + 8)*DINNER + h*HEADDIM + p0];
            float2 o0 = *(float2*)addr0;
            float2 o1 = *(float2*)addr1;
            o0.x += u0 * yreg[mf][nf][0];  o0.y += u0 * yreg[mf][nf][1];
            o1.x += u1 * yreg[mf][nf][2];  o1.y += u1 * yreg[mf][nf][3];
            *(float2*)addr0 = o0;
            *(float2*)addr1 = o1;
        }
    }
}

// =================================================================
// y = y * silu(z); y = y * rsqrt(mean(y^2)+eps) * norm_w   (in place)
// =================================================================
__global__ __launch_bounds__(256) void gate_norm_kernel(const float* __restrict__ norm_w)
{
    const int row = blockIdx.x;
    const int tid = threadIdx.x;
    const float* zrow = g_zxbcdt + (size_t)row * DPROJ;
    float* yrow = g_y + (size_t)row * DINNER;

    float v[6];
    float ss = 0.f;
    #pragma unroll
    for (int i = 0; i < 6; i++) {
        int c = tid + i*256;
        float z  = zrow[c];
        float yg = yrow[c] * (z / (1.f + expf(-z)));
        v[i] = yg;
        ss += yg * yg;
    }
    #pragma unroll
    for (int o = 16; o > 0; o >>= 1) ss += __shfl_xor_sync(0xffffffffu, ss, o);
    __shared__ float red[8];
    if ((tid & 31) == 0) red[tid >> 5] = ss;
    __syncthreads();
    if (tid < 32) {
        float s2 = (tid < 8) ? red[tid] : 0.f;
        #pragma unroll
        for (int o = 4; o > 0; o >>= 1) s2 += __shfl_xor_sync(0xffffffffu, s2, o);
        if (tid == 0) red[0] = s2;
    }
    __syncthreads();
    const float rstd = rsqrtf(red[0] * (1.f/1536.f) + 1e-5f);
    #pragma unroll
    for (int i = 0; i < 6; i++) {
        int c = tid + i*256;
        yrow[c] = v[i] * rstd * norm_w[c];
    }
}

// =================================================================
extern "C" void kernel_launch(void* const* d_in, const int* in_sizes, int n_in,
                              void* d_out, int out_size)
{
    const float* feature   = (const float*)d_in[0];
    const float* in_proj_w = (const float*)d_in[1];
    const float* conv_w    = (const float*)d_in[2];
    const float* conv_b    = (const float*)d_in[3];
    const float* dt_bias   = (const float*)d_in[4];
    const float* A_log     = (const float*)d_in[5];
    const float* Dvec      = (const float*)d_in[6];
    const float* norm_w    = (const float*)d_in[7];
    const float* out_projw = (const float*)d_in[8];
    const float* gate1     = (const float*)d_in[9];
    float* out = (float*)d_out;

    float *zx, *y;
    cudaGetSymbolAddress((void**)&zx, g_zxbcdt);
    cudaGetSymbolAddress((void**)&y,  g_y);

    cudaFuncSetAttribute(gemm_tf32,
        cudaFuncAttributeMaxDynamicSharedMemorySize, GEMM_SMEM_FLOATS * 4);
    cudaFuncSetAttribute(chunk_fused_kernel,
        cudaFuncAttributeMaxDynamicSharedMemorySize, K1_SMEM_FLOATS * 4);
    cudaFuncSetAttribute(inter_kernel,
        cudaFuncAttributeMaxDynamicSharedMemorySize, K3_SMEM_FLOATS * 4);

    dim3 blk(256);

    gemm_tf32<<<dim3((DPROJ + BN - 1)/BN, ROWS/BM), blk, GEMM_SMEM_FLOATS * 4>>>(
        feature, in_proj_w, zx, ROWS, DPROJ, DMODEL, nullptr);

    conv_silu_kernel<<<(int)(((long)ROWS * CONVDIM) / 256), blk>>>(conv_w, conv_b);

    dt_kernel<<<(ROWS * NHEADS) / 256, blk>>>(dt_bias);

    chunk_fused_kernel<<<BATCH * NHEADS * NSEG, blk, K1_SMEM_FLOATS * 4>>>(A_log, Dvec);
    combine_kernel<<<BATCH * NHEADS, blk>>>(A_log);
    inter_kernel<<<BATCH * NHEADS * NSEG, blk, K3_SMEM_FLOATS * 4>>>(A_log);

    gate_norm_kernel<<<ROWS, blk>>>(norm_w);

    gemm_tf32<<<dim3(DMODEL/BN, ROWS/BM), blk, GEMM_SMEM_FLOATS * 4>>>(
        y, out_projw, out, ROWS, DMODEL, DINNER, gate1);
}

// round 8
// speedup vs baseline: 1.1283x; 1.1283x over previous
#include <cuda_runtime.h>
#include <math.h>
#include <stdint.h>

#define BATCH   4
#define LSEQ    2048
#define ROWS    (BATCH*LSEQ)      // 8192
#define DMODEL  768
#define DINNER  1536
#define NHEADS  24
#define HEADDIM 64
#define DSTATE  128
#define CONVDIM 1792
#define DPROJ   3352              // 2*DINNER + 2*DSTATE + NHEADS

#define NSEG    16
#define SEGLEN  (LSEQ/NSEG)       // 128
#define STATESZ (HEADDIM*DSTATE)  // 8192

// -------- scratch (device globals; no allocation allowed) --------
__device__ float g_zxbcdt[(size_t)ROWS * DPROJ];   // in_proj output
__device__ float g_xBC[(size_t)ROWS * CONVDIM];    // conv+silu output
__device__ float g_dt[ROWS * NHEADS];
__device__ float g_y[(size_t)ROWS * DINNER];       // scan output -> gated/normed
__device__ float g_states[(size_t)BATCH*NHEADS*NSEG*STATESZ];  // segment end states
__device__ float g_hstart[(size_t)BATCH*NHEADS*NSEG*STATESZ];  // segment start states

// =================================================================
// common PTX helpers
// =================================================================
__device__ __forceinline__ uint32_t f2tf32(float x) {
    uint32_t r;
    asm("cvt.rna.tf32.f32 %0, %1;" : "=r"(r) : "f"(x));
    return r;
}

// pack two floats to bf16x2: lo half = f0 (even k), hi half = f1 (odd k)
__device__ __forceinline__ uint32_t packbf2(float f0, float f1) {
    uint32_t r;
    asm("cvt.rn.bf16x2.f32 %0, %1, %2;" : "=r"(r) : "f"(f1), "f"(f0));
    return r;
}
// split (f0,f1) into bf16x2 hi word + bf16x2 residual word
__device__ __forceinline__ void bsplit2(float f0, float f1, uint32_t& H, uint32_t& L) {
    H = packbf2(f0, f1);
    float h0 = __uint_as_float(H << 16);
    float h1 = __uint_as_float(H & 0xffff0000u);
    L = packbf2(f0 - h0, f1 - h1);
}

#define CPA16(dst, src) \
    asm volatile("cp.async.cg.shared.global [%0], [%1], 16;\n" \
                 :: "r"(dst), "l"(src))
#define CPA16P(dst, src, valid) \
    asm volatile("cp.async.cg.shared.global [%0], [%1], 16, %2;\n" \
                 :: "r"(dst), "l"(src), "r"((valid) ? 16 : 0))
#define CPA_COMMIT() asm volatile("cp.async.commit_group;\n" ::: "memory")
#define CPA_WAIT0()  asm volatile("cp.async.wait_group 0;\n" ::: "memory")

#define MMA_TF32(d, a, b) \
    asm volatile("mma.sync.aligned.m16n8k8.row.col.f32.tf32.tf32.f32 " \
                 "{%0,%1,%2,%3},{%4,%5,%6,%7},{%8,%9},{%0,%1,%2,%3};\n" \
                 : "+f"((d)[0]), "+f"((d)[1]), "+f"((d)[2]), "+f"((d)[3]) \
                 : "r"((a)[0]), "r"((a)[1]), "r"((a)[2]), "r"((a)[3]), \
                   "r"((b)[0]), "r"((b)[1]))

#define MMA_BF16(d, a, b) \
    asm volatile("mma.sync.aligned.m16n8k16.row.col.f32.bf16.bf16.f32 " \
                 "{%0,%1,%2,%3},{%4,%5,%6,%7},{%8,%9},{%0,%1,%2,%3};\n" \
                 : "+f"((d)[0]), "+f"((d)[1]), "+f"((d)[2]), "+f"((d)[3]) \
                 : "r"((a)[0]), "r"((a)[1]), "r"((a)[2]), "r"((a)[3]), \
                   "r"((b)[0]), "r"((b)[1]))

// 3-term bf16 split MMA: D += (AH+AL)*(BH+BL) - AL*BL
#define MMA3B(d, aH, aL, bH, bL) do { \
    MMA_BF16(d, aL, bH); \
    MMA_BF16(d, aH, bL); \
    MMA_BF16(d, aH, bH); } while (0)

// =================================================================
// TF32 tensor-core GEMM (NT): C[M,N] = A[M,K] * B[N,K]^T   (R6 version)
// =================================================================
#define BM 128
#define BN 128
#define BKT 16

__global__ __launch_bounds__(256) void gemm_tf32(
    const float* __restrict__ A, const float* __restrict__ B,
    float* __restrict__ C, int M, int N, int K,
    const float* __restrict__ gate)
{
    __shared__ float As[2][BM][20];
    __shared__ float Bs[2][BN][20];

    const int tid  = threadIdx.x;
    const int lane = tid & 31;
    const int warp = tid >> 5;
    const int wm   = warp >> 2;
    const int wn   = warp & 3;
    const int m0   = blockIdx.y * BM;
    const int n0   = blockIdx.x * BN;

    const int lr = tid >> 2;
    const int lc = (tid & 3) * 4;

    const float* Ag0 = A + (size_t)(m0 + lr) * K + lc;
    const float* Ag1 = Ag0 + (size_t)64 * K;
    const bool  bv0 = (n0 + lr) < N;
    const bool  bv1 = (n0 + lr + 64) < N;
    const int   br0 = min(n0 + lr, N - 1);
    const int   br1 = min(n0 + lr + 64, N - 1);
    const float* Bg0 = B + (size_t)br0 * K + lc;
    const float* Bg1 = B + (size_t)br1 * K + lc;

    float acc[4][4][4];
    #pragma unroll
    for (int i = 0; i < 4; i++)
        #pragma unroll
        for (int j = 0; j < 4; j++)
            #pragma unroll
            for (int r = 0; r < 4; r++) acc[i][j][r] = 0.f;

    const int KT = K / BKT;

    {
        uint32_t sA0 = (uint32_t)__cvta_generic_to_shared(&As[0][lr][lc]);
        uint32_t sA1 = (uint32_t)__cvta_generic_to_shared(&As[0][lr + 64][lc]);
        uint32_t sB0 = (uint32_t)__cvta_generic_to_shared(&Bs[0][lr][lc]);
        uint32_t sB1 = (uint32_t)__cvta_generic_to_shared(&Bs[0][lr + 64][lc]);
        CPA16(sA0, Ag0);
        CPA16(sA1, Ag1);
        CPA16P(sB0, Bg0, bv0);
        CPA16P(sB1, Bg1, bv1);
        CPA_COMMIT();
    }

    for (int kt = 0; kt < KT; kt++) {
        const int st = kt & 1;
        CPA_WAIT0();
        __syncthreads();

        if (kt + 1 < KT) {
            const int ns = st ^ 1;
            const size_t ko = (size_t)(kt + 1) * BKT;
            uint32_t sA0 = (uint32_t)__cvta_generic_to_shared(&As[ns][lr][lc]);
            uint32_t sA1 = (uint32_t)__cvta_generic_to_shared(&As[ns][lr + 64][lc]);
            uint32_t sB0 = (uint32_t)__cvta_generic_to_shared(&Bs[ns][lr][lc]);
            uint32_t sB1 = (uint32_t)__cvta_generic_to_shared(&Bs[ns][lr + 64][lc]);
            CPA16(sA0, Ag0 + ko);
            CPA16(sA1, Ag1 + ko);
            CPA16P(sB0, Bg0 + ko, bv0);
            CPA16P(sB1, Bg1 + ko, bv1);
            CPA_COMMIT();
        }

        #pragma unroll
        for (int kk = 0; kk < BKT; kk += 8) {
            uint32_t a[4][4], b[4][2];
            const int qr = lane >> 2;
            const int qc = kk + (lane & 3);
            #pragma unroll
            for (int mf = 0; mf < 4; mf++) {
                const int r = wm * 64 + mf * 16 + qr;
                a[mf][0] = f2tf32(As[st][r][qc]);
                a[mf][1] = f2tf32(As[st][r + 8][qc]);
                a[mf][2] = f2tf32(As[st][r][qc + 4]);
                a[mf][3] = f2tf32(As[st][r + 8][qc + 4]);
            }
            #pragma unroll
            for (int nf = 0; nf < 4; nf++) {
                const int r = wn * 32 + nf * 8 + qr;
                b[nf][0] = f2tf32(Bs[st][r][qc]);
                b[nf][1] = f2tf32(Bs[st][r][qc + 4]);
            }
            #pragma unroll
            for (int mf = 0; mf < 4; mf++)
                #pragma unroll
                for (int nf = 0; nf < 4; nf++)
                    MMA_TF32(acc[mf][nf], a[mf], b[nf]);
        }
    }

    float scale = 1.f;
    if (gate) { float g = *gate; scale = 1.f / (1.f + expf(-g)); }

    #pragma unroll
    for (int mf = 0; mf < 4; mf++) {
        const int r = m0 + wm * 64 + mf * 16 + (lane >> 2);
        #pragma unroll
        for (int nf = 0; nf < 4; nf++) {
            const int c = n0 + wn * 32 + nf * 8 + (lane & 3) * 2;
            if (c < N) {
                float2 v0 = make_float2(acc[mf][nf][0] * scale, acc[mf][nf][1] * scale);
                float2 v1 = make_float2(acc[mf][nf][2] * scale, acc[mf][nf][3] * scale);
                *(float2*)&C[(size_t)r * N + c]       = v0;
                *(float2*)&C[(size_t)(r + 8) * N + c] = v1;
            }
        }
    }
}

// =================================================================
// Causal depthwise conv1d (width 4) + bias + SiLU on xBC slice
// =================================================================
__global__ __launch_bounds__(256) void conv_silu_kernel(
    const float* __restrict__ conv_w, const float* __restrict__ conv_b)
{
    const long idx = (long)blockIdx.x * 256 + threadIdx.x;
    const int  c   = (int)(idx % CONVDIM);
    const long row = idx / CONVDIM;
    const int  l   = (int)(row % LSEQ);

    float acc = conv_b[c];
    const float w0 = conv_w[c*4+0], w1 = conv_w[c*4+1];
    const float w2 = conv_w[c*4+2], w3 = conv_w[c*4+3];
    const float* base = g_zxbcdt + (size_t)row * DPROJ + DINNER + c;
    if (l >= 3) acc = fmaf(base[-3*DPROJ], w0, acc);
    if (l >= 2) acc = fmaf(base[-2*DPROJ], w1, acc);
    if (l >= 1) acc = fmaf(base[-1*DPROJ], w2, acc);
    acc = fmaf(base[0], w3, acc);
    g_xBC[idx] = acc / (1.f + expf(-acc));
}

// =================================================================
// dt = softplus(dt_raw + dt_bias)
// =================================================================
__global__ __launch_bounds__(256) void dt_kernel(const float* __restrict__ dt_bias)
{
    const int idx = blockIdx.x * 256 + threadIdx.x;
    const int h   = idx % NHEADS;
    const int row = idx / NHEADS;
    float v  = g_zxbcdt[(size_t)row * DPROJ + (DINNER + CONVDIM) + h] + dt_bias[h];
    float sp = (v > 20.f) ? v : log1pf(expf(v));
    g_dt[idx] = sp;
}

// =================================================================
// K1: fused per-chunk kernel, bf16x2-split (3-term) tensor GEMMs.
// All packed tiles stored k-pair-major: arr[kpair][mn].
//   CH/CL [64][132]: C packed along staten      -> later M~ packed along s
//   BH/BL [64][132]: B packed along staten      -> later (w*B)^T packed along s
//   XH/XL [64][68] : x packed along s ([sp][p])
//   XF    [64][132]: x float [p][t] (for D*x epilogue)
// =================================================================
#define K1_SMEM_U32 51332
#define K3_SMEM_U32 25732

__global__ __launch_bounds__(256) void chunk_fused_kernel(
    const float* __restrict__ A_log, const float* __restrict__ Dvec)
{
    extern __shared__ uint32_t smu[];
    uint32_t* CHs = smu;                 // [64][132]
    uint32_t* CLs = smu + 8448;
    uint32_t* BHs = smu + 16896;         // [64][132]
    uint32_t* BLs = smu + 25344;
    uint32_t* XHs = smu + 33792;         // [64][68]
    uint32_t* XLs = smu + 38144;
    float*    XF  = (float*)(smu + 42496);   // [64][132] floats [p][t]
    float*    sa  = (float*)(smu + 50944);
    float*    sdt = (float*)(smu + 51072);
    float*    sw  = (float*)(smu + 51200);
    float*    wsum4 = (float*)(smu + 51328);

    const int blk = blockIdx.x;
    const int bh = blk >> 4, seg = blk & (NSEG - 1);
    const int b = bh / NHEADS, h = bh % NHEADS;
    const int tid = threadIdx.x, lane = tid & 31, warp = tid >> 5;
    const int qr = lane >> 2, ql = lane & 3;
    const size_t rowbase = (size_t)b * LSEQ + seg * SEGLEN;

    // ---- fill C,B tiles (packed along staten) ----
    #pragma unroll
    for (int i = 0; i < 32; i++) {
        int e = tid + i * 256;           // < 8192
        int np = e & 63, t = e >> 6;
        const float* src = g_xBC + (rowbase + t) * CONVDIM + DINNER + 2*np;
        float2 bv = *(const float2*)src;
        float2 cv = *(const float2*)(src + DSTATE);
        uint32_t hh, ll;
        bsplit2(bv.x, bv.y, hh, ll); BHs[np*132 + t] = hh; BLs[np*132 + t] = ll;
        bsplit2(cv.x, cv.y, hh, ll); CHs[np*132 + t] = hh; CLs[np*132 + t] = ll;
    }
    // ---- fill x (packed along s) + float copy ----
    #pragma unroll
    for (int i = 0; i < 16; i++) {
        int e = tid + i * 256;           // < 4096
        int p = e & 63, sp = e >> 6;
        const float* s0 = g_xBC + (rowbase + 2*sp) * CONVDIM + h * HEADDIM + p;
        float f0 = s0[0], f1 = s0[CONVDIM];
        uint32_t hh, ll;
        bsplit2(f0, f1, hh, ll);
        XHs[sp*68 + p] = hh; XLs[sp*68 + p] = ll;
        XF[p*132 + 2*sp] = f0; XF[p*132 + 2*sp + 1] = f1;
    }

    // ---- dt cumsum / weights ----
    const float Aneg = -expf(A_log[h]);
    float vdt = 0.f, acs = 0.f;
    if (tid < SEGLEN) {
        vdt = g_dt[(rowbase + tid) * NHEADS + h];
        acs = vdt;
        #pragma unroll
        for (int o = 1; o < 32; o <<= 1) {
            float nv = __shfl_up_sync(0xffffffffu, acs, o);
            if (lane >= o) acs += nv;
        }
        if (lane == 31) wsum4[warp] = acs;
    }
    __syncthreads();
    if (tid < SEGLEN) {
        float tot = wsum4[0] + wsum4[1] + wsum4[2] + wsum4[3];
        float pre = 0.f;
        #pragma unroll
        for (int w2 = 0; w2 < 4; w2++) if (w2 < warp) pre += wsum4[w2];
        float a = acs + pre;
        sa[tid]  = a;
        sdt[tid] = vdt;
        sw[tid]  = vdt * __expf(Aneg * (tot - a));
    }
    __syncthreads();

    // ================= GEMM1: M = C @ B^T (k = staten) =================
    float mreg[4][4][4];
    #pragma unroll
    for (int i = 0; i < 4; i++)
        #pragma unroll
        for (int j = 0; j < 4; j++)
            #pragma unroll
            for (int r = 0; r < 4; r++) mreg[i][j][r] = 0.f;

    const int m1 = (warp >> 2) * 64, n1 = (warp & 3) * 32;
    #pragma unroll
    for (int kb = 0; kb < 8; kb++) {
        const int k0 = kb*8 + ql, k4 = k0 + 4;
        uint32_t aH[4][4], aL[4][4], bHf[4][2], bLf[4][2];
        #pragma unroll
        for (int mf = 0; mf < 4; mf++) {
            int r = m1 + mf*16 + qr;
            aH[mf][0] = CHs[k0*132 + r];     aL[mf][0] = CLs[k0*132 + r];
            aH[mf][1] = CHs[k0*132 + r + 8]; aL[mf][1] = CLs[k0*132 + r + 8];
            aH[mf][2] = CHs[k4*132 + r];     aL[mf][2] = CLs[k4*132 + r];
            aH[mf][3] = CHs[k4*132 + r + 8]; aL[mf][3] = CLs[k4*132 + r + 8];
        }
        #pragma unroll
        for (int nf = 0; nf < 4; nf++) {
            int c = n1 + nf*8 + qr;
            bHf[nf][0] = BHs[k0*132 + c];  bHf[nf][1] = BHs[k4*132 + c];
            bLf[nf][0] = BLs[k0*132 + c];  bLf[nf][1] = BLs[k4*132 + c];
        }
        #pragma unroll
        for (int mf = 0; mf < 4; mf++)
            #pragma unroll
            for (int nf = 0; nf < 4; nf++)
                MMA3B(mreg[mf][nf], aH[mf], aL[mf], bHf[nf], bLf[nf]);
    }
    __syncthreads();   // all warps done reading CHs/BHs

    // ---- mask + store M~ packed along s into CHs/CLs ([sp][t]) ----
    #pragma unroll
    for (int mf = 0; mf < 4; mf++) {
        int tA = m1 + mf*16 + qr, tB = tA + 8;
        float aA = sa[tA], aB = sa[tB];
        #pragma unroll
        for (int nf = 0; nf < 4; nf++) {
            int sp = (n1 >> 1) + nf*4 + ql;
            int s0 = 2*sp, s1 = s0 + 1;
            float as0 = sa[s0], as1 = sa[s1];
            float d0 = sdt[s0], d1 = sdt[s1];
            float v00 = (s0 <= tA) ? mreg[mf][nf][0] * __expf(Aneg*(aA-as0)) * d0 : 0.f;
            float v01 = (s1 <= tA) ? mreg[mf][nf][1] * __expf(Aneg*(aA-as1)) * d1 : 0.f;
            float v10 = (s0 <= tB) ? mreg[mf][nf][2] * __expf(Aneg*(aB-as0)) * d0 : 0.f;
            float v11 = (s1 <= tB) ? mreg[mf][nf][3] * __expf(Aneg*(aB-as1)) * d1 : 0.f;
            uint32_t hh, ll;
            bsplit2(v00, v01, hh, ll); CHs[sp*132 + tA] = hh; CLs[sp*132 + tA] = ll;
            bsplit2(v10, v11, hh, ll); CHs[sp*132 + tB] = hh; CLs[sp*132 + tB] = ll;
        }
    }

    // ---- refill BHs/BLs as (w*B) packed along s ([sp][staten]) ----
    #pragma unroll
    for (int i = 0; i < 32; i++) {
        int e = tid + i * 256;           // < 8192
        int n = e & 127, sp = e >> 7;
        const float* s0 = g_xBC + (rowbase + 2*sp) * CONVDIM + DINNER + n;
        float f0 = s0[0] * sw[2*sp];
        float f1 = s0[CONVDIM] * sw[2*sp + 1];
        uint32_t hh, ll;
        bsplit2(f0, f1, hh, ll);
        BHs[sp*132 + n] = hh; BLs[sp*132 + n] = ll;
    }
    __syncthreads();

    // ================= GEMM2: Y = M~ @ X  (k = s) =================
    {
        float yreg[2][4][4];
        #pragma unroll
        for (int i = 0; i < 2; i++)
            #pragma unroll
            for (int j = 0; j < 4; j++)
                #pragma unroll
                for (int r = 0; r < 4; r++) yreg[i][j][r] = 0.f;

        const int m2 = (warp >> 1) * 32, n2 = (warp & 1) * 32;
        #pragma unroll
        for (int kb = 0; kb < 8; kb++) {
            const int k0 = kb*8 + ql, k4 = k0 + 4;
            uint32_t aH[2][4], aL[2][4], bHf[4][2], bLf[4][2];
            #pragma unroll
            for (int mf = 0; mf < 2; mf++) {
                int r = m2 + mf*16 + qr;
                aH[mf][0] = CHs[k0*132 + r];     aL[mf][0] = CLs[k0*132 + r];
                aH[mf][1] = CHs[k0*132 + r + 8]; aL[mf][1] = CLs[k0*132 + r + 8];
                aH[mf][2] = CHs[k4*132 + r];     aL[mf][2] = CLs[k4*132 + r];
                aH[mf][3] = CHs[k4*132 + r + 8]; aL[mf][3] = CLs[k4*132 + r + 8];
            }
            #pragma unroll
            for (int nf = 0; nf < 4; nf++) {
                int c = n2 + nf*8 + qr;
                bHf[nf][0] = XHs[k0*68 + c];  bHf[nf][1] = XHs[k4*68 + c];
                bLf[nf][0] = XLs[k0*68 + c];  bLf[nf][1] = XLs[k4*68 + c];
            }
            #pragma unroll
            for (int mf = 0; mf < 2; mf++)
                #pragma unroll
                for (int nf = 0; nf < 4; nf++)
                    MMA3B(yreg[mf][nf], aH[mf], aL[mf], bHf[nf], bLf[nf]);
        }

        const float Dh = Dvec[h];
        #pragma unroll
        for (int mf = 0; mf < 2; mf++) {
            int t = m2 + mf*16 + qr;
            #pragma unroll
            for (int nf = 0; nf < 4; nf++) {
                int p0 = n2 + nf*8 + ql*2;
                float2 o;
                o.x = yreg[mf][nf][0] + Dh * XF[p0*132 + t];
                o.y = yreg[mf][nf][1] + Dh * XF[(p0+1)*132 + t];
                *(float2*)&g_y[(rowbase + t)*DINNER + h*HEADDIM + p0] = o;
                o.x = yreg[mf][nf][2] + Dh * XF[p0*132 + t + 8];
                o.y = yreg[mf][nf][3] + Dh * XF[(p0+1)*132 + t + 8];
                *(float2*)&g_y[(rowbase + t + 8)*DINNER + h*HEADDIM + p0] = o;
            }
        }
    }

    // ================= GEMM3: S = X^T @ (w*B)  (k = s) =================
    {
        float sreg[2][4][4];
        #pragma unroll
        for (int i = 0; i < 2; i++)
            #pragma unroll
            for (int j = 0; j < 4; j++)
                #pragma unroll
                for (int r = 0; r < 4; r++) sreg[i][j][r] = 0.f;

        const int m3 = (warp >> 2) * 32, n3 = (warp & 3) * 32;
        #pragma unroll
        for (int kb = 0; kb < 8; kb++) {
            const int k0 = kb*8 + ql, k4 = k0 + 4;
            uint32_t aH[2][4], aL[2][4], bHf[4][2], bLf[4][2];
            #pragma unroll
            for (int mf = 0; mf < 2; mf++) {
                int r = m3 + mf*16 + qr;
                aH[mf][0] = XHs[k0*68 + r];     aL[mf][0] = XLs[k0*68 + r];
                aH[mf][1] = XHs[k0*68 + r + 8]; aL[mf][1] = XLs[k0*68 + r + 8];
                aH[mf][2] = XHs[k4*68 + r];     aL[mf][2] = XLs[k4*68 + r];
                aH[mf][3] = XHs[k4*68 + r + 8]; aL[mf][3] = XLs[k4*68 + r + 8];
            }
            #pragma unroll
            for (int nf = 0; nf < 4; nf++) {
                int c = n3 + nf*8 + qr;
                bHf[nf][0] = BHs[k0*132 + c];  bHf[nf][1] = BHs[k4*132 + c];
                bLf[nf][0] = BLs[k0*132 + c];  bLf[nf][1] = BLs[k4*132 + c];
            }
            #pragma unroll
            for (int mf = 0; mf < 2; mf++)
                #pragma unroll
                for (int nf = 0; nf < 4; nf++)
                    MMA3B(sreg[mf][nf], aH[mf], aL[mf], bHf[nf], bLf[nf]);
        }

        const size_t sbase = ((size_t)bh * NSEG + seg) * STATESZ;
        #pragma unroll
        for (int mf = 0; mf < 2; mf++) {
            int p = m3 + mf*16 + qr;
            #pragma unroll
            for (int nf = 0; nf < 4; nf++) {
                int n0 = n3 + nf*8 + ql*2;
                float2 o0 = make_float2(sreg[mf][nf][0], sreg[mf][nf][1]);
                float2 o1 = make_float2(sreg[mf][nf][2], sreg[mf][nf][3]);
                *(float2*)&g_states[sbase + (size_t)p * DSTATE + n0]       = o0;
                *(float2*)&g_states[sbase + (size_t)(p + 8) * DSTATE + n0] = o1;
            }
        }
    }
}

// =================================================================
// K2: combine: h_start[seg+1] = E_seg * h_start[seg] + S_seg
// =================================================================
__global__ __launch_bounds__(256) void combine_kernel(const float* __restrict__ A_log)
{
    const int bh = blockIdx.x;
    const int b = bh / NHEADS, h = bh % NHEADS;
    const int tid = threadIdx.x;

    __shared__ float part[256];
    __shared__ float Esh[NSEG];

    {
        const int k = tid >> 4, i = tid & 15;
        float s = 0.f;
        const size_t base = ((size_t)b*LSEQ + k*SEGLEN + i*8)*NHEADS + h;
        #pragma unroll
        for (int t = 0; t < 8; t++) s += g_dt[base + (size_t)t*NHEADS];
        part[tid] = s;
    }
    __syncthreads();
    if (tid < NSEG) {
        float s = 0.f;
        #pragma unroll
        for (int i = 0; i < 16; i++) s += part[tid*16 + i];
        Esh[tid] = expf(-expf(A_log[h]) * s);
    }
    __syncthreads();

    float hs[32];
    #pragma unroll
    for (int k2 = 0; k2 < 32; k2++) hs[k2] = 0.f;

    for (int seg = 0; seg < NSEG; seg++) {
        const size_t base = ((size_t)bh*NSEG + seg)*STATESZ;
        const float E = Esh[seg];
        #pragma unroll
        for (int k2 = 0; k2 < 32; k2++) {
            const size_t e = base + k2*256 + tid;
            g_hstart[e] = hs[k2];
            hs[k2] = fmaf(hs[k2], E, g_states[e]);
        }
    }
}

// =================================================================
// K3: inter-chunk: Y += exp(A*a_t) * (C @ hstart^T)   (bf16x2 split)
// CH2/CL2 [64][132]: C packed along staten; HH/HL [64][68]: h packed
// =================================================================
__global__ __launch_bounds__(256) void inter_kernel(const float* __restrict__ A_log)
{
    extern __shared__ uint32_t smu[];
    uint32_t* CH2 = smu;                 // [64][132]
    uint32_t* CL2 = smu + 8448;
    uint32_t* HHs = smu + 16896;         // [64][68]
    uint32_t* HLs = smu + 21248;
    float*    su  = (float*)(smu + 25600);
    float*    wsum4 = (float*)(smu + 25728);

    const int blk = blockIdx.x;
    const int bh = blk >> 4, seg = blk & (NSEG - 1);
    const int b = bh / NHEADS, h = bh % NHEADS;
    const int tid = threadIdx.x, lane = tid & 31, warp = tid >> 5;
    const int qr = lane >> 2, ql = lane & 3;
    const size_t rowbase = (size_t)b * LSEQ + seg * SEGLEN;
    const size_t hbase = ((size_t)bh * NSEG + seg) * STATESZ;

    // C tile packed along staten
    #pragma unroll
    for (int i = 0; i < 32; i++) {
        int e = tid + i * 256;           // < 8192
        int np = e & 63, t = e >> 6;
        const float* src = g_xBC + (rowbase + t) * CONVDIM + DINNER + DSTATE + 2*np;
        float2 cv = *(const float2*)src;
        uint32_t hh, ll;
        bsplit2(cv.x, cv.y, hh, ll);
        CH2[np*132 + t] = hh; CL2[np*132 + t] = ll;
    }
    // H tile packed along staten ([np][p])
    #pragma unroll
    for (int i = 0; i < 16; i++) {
        int e = tid + i * 256;           // < 4096
        int np = e & 63, p = e >> 6;
        const float* src = g_hstart + hbase + (size_t)p * DSTATE + 2*np;
        float2 hv = *(const float2*)src;
        uint32_t hh, ll;
        bsplit2(hv.x, hv.y, hh, ll);
        HHs[np*68 + p] = hh; HLs[np*68 + p] = ll;
    }

    // cumsum -> u_t = exp(A * a_t)
    const float Aneg = -expf(A_log[h]);
    float vdt = 0.f, acs = 0.f;
    if (tid < SEGLEN) {
        vdt = g_dt[(rowbase + tid) * NHEADS + h];
        acs = vdt;
        #pragma unroll
        for (int o = 1; o < 32; o <<= 1) {
            float nv = __shfl_up_sync(0xffffffffu, acs, o);
            if (lane >= o) acs += nv;
        }
        if (lane == 31) wsum4[warp] = acs;
    }
    __syncthreads();
    if (tid < SEGLEN) {
        float pre = 0.f;
        #pragma unroll
        for (int w2 = 0; w2 < 4; w2++) if (w2 < warp) pre += wsum4[w2];
        su[tid] = __expf(Aneg * (acs + pre));
    }
    __syncthreads();

    float yreg[2][4][4];
    #pragma unroll
    for (int i = 0; i < 2; i++)
        #pragma unroll
        for (int j = 0; j < 4; j++)
            #pragma unroll
            for (int r = 0; r < 4; r++) yreg[i][j][r] = 0.f;

    const int m2 = (warp >> 1) * 32, n2 = (warp & 1) * 32;
    #pragma unroll
    for (int kb = 0; kb < 8; kb++) {
        const int k0 = kb*8 + ql, k4 = k0 + 4;
        uint32_t aH[2][4], aL[2][4], bHf[4][2], bLf[4][2];
        #pragma unroll
        for (int mf = 0; mf < 2; mf++) {
            int r = m2 + mf*16 + qr;
            aH[mf][0] = CH2[k0*132 + r];     aL[mf][0] = CL2[k0*132 + r];
            aH[mf][1] = CH2[k0*132 + r + 8]; aL[mf][1] = CL2[k0*132 + r + 8];
            aH[mf][2] = CH2[k4*132 + r];     aL[mf][2] = CL2[k4*132 + r];
            aH[mf][3] = CH2[k4*132 + r + 8]; aL[mf][3] = CL2[k4*132 + r + 8];
        }
        #pragma unroll
        for (int nf = 0; nf < 4; nf++) {
            int c = n2 + nf*8 + qr;
            bHf[nf][0] = HHs[k0*68 + c];  bHf[nf][1] = HHs[k4*68 + c];
            bLf[nf][0] = HLs[k0*68 + c];  bLf[nf][1] = HLs[k4*68 + c];
        }
        #pragma unroll
        for (int mf = 0; mf < 2; mf++)
            #pragma unroll
            for (int nf = 0; nf < 4; nf++)
                MMA3B(yreg[mf][nf], aH[mf], aL[mf], bHf[nf], bLf[nf]);
    }

    #pragma unroll
    for (int mf = 0; mf < 2; mf++) {
        int t = m2 + mf*16 + qr;
        float u0 = su[t], u1 = su[t + 8];
        #pragma unroll
        for (int nf = 0; nf < 4; nf++) {
            int p0 = n2 + nf*8 + ql*2;
            float* addr0 = &g_y[(rowbase + t)*DINNER + h*HEADDIM + p0];
            float* addr1 = &g_y[(rowbase + t + 8)*DINNER + h*HEADDIM + p0];
            float2 o0 = *(float2*)addr0;
            float2 o1 = *(float2*)addr1;
            o0.x += u0 * yreg[mf][nf][0];  o0.y += u0 * yreg[mf][nf][1];
            o1.x += u1 * yreg[mf][nf][2];  o1.y += u1 * yreg[mf][nf][3];
            *(float2*)addr0 = o0;
            *(float2*)addr1 = o1;
        }
    }
}

// =================================================================
// y = y * silu(z); y = y * rsqrt(mean(y^2)+eps) * norm_w   (in place)
// =================================================================
__global__ __launch_bounds__(256) void gate_norm_kernel(const float* __restrict__ norm_w)
{
    const int row = blockIdx.x;
    const int tid = threadIdx.x;
    const float* zrow = g_zxbcdt + (size_t)row * DPROJ;
    float* yrow = g_y + (size_t)row * DINNER;

    float v[6];
    float ss = 0.f;
    #pragma unroll
    for (int i = 0; i < 6; i++) {
        int c = tid + i*256;
        float z  = zrow[c];
        float yg = yrow[c] * (z / (1.f + expf(-z)));
        v[i] = yg;
        ss += yg * yg;
    }
    #pragma unroll
    for (int o = 16; o > 0; o >>= 1) ss += __shfl_xor_sync(0xffffffffu, ss, o);
    __shared__ float red[8];
    if ((tid & 31) == 0) red[tid >> 5] = ss;
    __syncthreads();
    if (tid < 32) {
        float s2 = (tid < 8) ? red[tid] : 0.f;
        #pragma unroll
        for (int o = 4; o > 0; o >>= 1) s2 += __shfl_xor_sync(0xffffffffu, s2, o);
        if (tid == 0) red[0] = s2;
    }
    __syncthreads();
    const float rstd = rsqrtf(red[0] * (1.f/1536.f) + 1e-5f);
    #pragma unroll
    for (int i = 0; i < 6; i++) {
        int c = tid + i*256;
        yrow[c] = v[i] * rstd * norm_w[c];
    }
}

// =================================================================
extern "C" void kernel_launch(void* const* d_in, const int* in_sizes, int n_in,
                              void* d_out, int out_size)
{
    const float* feature   = (const float*)d_in[0];
    const float* in_proj_w = (const float*)d_in[1];
    const float* conv_w    = (const float*)d_in[2];
    const float* conv_b    = (const float*)d_in[3];
    const float* dt_bias   = (const float*)d_in[4];
    const float* A_log     = (const float*)d_in[5];
    const float* Dvec      = (const float*)d_in[6];
    const float* norm_w    = (const float*)d_in[7];
    const float* out_projw = (const float*)d_in[8];
    const float* gate1     = (const float*)d_in[9];
    float* out = (float*)d_out;

    float *zx, *y;
    cudaGetSymbolAddress((void**)&zx, g_zxbcdt);
    cudaGetSymbolAddress((void**)&y,  g_y);

    cudaFuncSetAttribute(chunk_fused_kernel,
        cudaFuncAttributeMaxDynamicSharedMemorySize, K1_SMEM_U32 * 4);
    cudaFuncSetAttribute(inter_kernel,
        cudaFuncAttributeMaxDynamicSharedMemorySize, K3_SMEM_U32 * 4);

    dim3 blk(256);

    gemm_tf32<<<dim3((DPROJ + BN - 1)/BN, ROWS/BM), blk>>>(
        feature, in_proj_w, zx, ROWS, DPROJ, DMODEL, nullptr);

    conv_silu_kernel<<<(int)(((long)ROWS * CONVDIM) / 256), blk>>>(conv_w, conv_b);

    dt_kernel<<<(ROWS * NHEADS) / 256, blk>>>(dt_bias);

    chunk_fused_kernel<<<BATCH * NHEADS * NSEG, blk, K1_SMEM_U32 * 4>>>(A_log, Dvec);
    combine_kernel<<<BATCH * NHEADS, blk>>>(A_log);
    inter_kernel<<<BATCH * NHEADS * NSEG, blk, K3_SMEM_U32 * 4>>>(A_log);

    gate_norm_kernel<<<ROWS, blk>>>(norm_w);

    gemm_tf32<<<dim3(DMODEL/BN, ROWS/BM), blk>>>(
        y, out_projw, out, ROWS, DMODEL, DINNER, gate1);
}

// round 10
// speedup vs baseline: 1.5053x; 1.3341x over previous
#include <cuda_runtime.h>
#include <cuda_fp16.h>
#include <math.h>
#include <stdint.h>

#define BATCH   4
#define LSEQ    2048
#define ROWS    (BATCH*LSEQ)      // 8192
#define DMODEL  768
#define DINNER  1536
#define NHEADS  24
#define HEADDIM 64
#define DSTATE  128
#define CONVDIM 1792
#define DPROJ   3352

#define NSEG    16
#define SEGLEN  (LSEQ/NSEG)       // 128
#define STATESZ (HEADDIM*DSTATE)  // 8192

// -------- scratch (device globals; no allocation allowed) --------
__device__ float g_zxbcdt[(size_t)ROWS * DPROJ];
__device__ float g_xBC[(size_t)ROWS * CONVDIM];
__device__ float g_dt[ROWS * NHEADS];
__device__ float g_y[(size_t)ROWS * DINNER];
__device__ float g_states[(size_t)BATCH*NHEADS*NSEG*STATESZ];
__device__ float g_hstart[(size_t)BATCH*NHEADS*NSEG*STATESZ];
// fp16 packed-pair operands for projection GEMMs
__device__ uint32_t g_feat16[(size_t)ROWS*DMODEL/2];
__device__ uint32_t g_ipw16[(size_t)DPROJ*DMODEL/2];
__device__ uint32_t g_opw16[(size_t)DMODEL*DINNER/2];
__device__ uint32_t g_y16[(size_t)ROWS*DINNER/2];

// =================================================================
// helpers
// =================================================================
__device__ __forceinline__ uint32_t packbf2(float f0, float f1) {
    uint32_t r;
    asm("cvt.rn.bf16x2.f32 %0, %1, %2;" : "=r"(r) : "f"(f1), "f"(f0));
    return r;
}
__device__ __forceinline__ void bsplit2(float f0, float f1, uint32_t& H, uint32_t& L) {
    H = packbf2(f0, f1);
    float h0 = __uint_as_float(H << 16);
    float h1 = __uint_as_float(H & 0xffff0000u);
    L = packbf2(f0 - h0, f1 - h1);
}
__device__ __forceinline__ uint32_t packh2(float f0, float f1) {
    __half2 h = __float22half2_rn(make_float2(f0, f1));   // f0 -> low half
    return *(uint32_t*)&h;
}

#define CPA16(dst, src) \
    asm volatile("cp.async.cg.shared.global [%0], [%1], 16;\n" \
                 :: "r"(dst), "l"(src))
#define CPA16P(dst, src, valid) \
    asm volatile("cp.async.cg.shared.global [%0], [%1], 16, %2;\n" \
                 :: "r"(dst), "l"(src), "r"((valid) ? 16 : 0))
#define CPA_COMMIT() asm volatile("cp.async.commit_group;\n" ::: "memory")
#define CPA_WAIT0()  asm volatile("cp.async.wait_group 0;\n" ::: "memory")

#define MMA_BF16(d, a, b) \
    asm volatile("mma.sync.aligned.m16n8k16.row.col.f32.bf16.bf16.f32 " \
                 "{%0,%1,%2,%3},{%4,%5,%6,%7},{%8,%9},{%0,%1,%2,%3};\n" \
                 : "+f"((d)[0]), "+f"((d)[1]), "+f"((d)[2]), "+f"((d)[3]) \
                 : "r"((a)[0]), "r"((a)[1]), "r"((a)[2]), "r"((a)[3]), \
                   "r"((b)[0]), "r"((b)[1]))
#define MMA_F16(d, a, b) \
    asm volatile("mma.sync.aligned.m16n8k16.row.col.f32.f16.f16.f32 " \
                 "{%0,%1,%2,%3},{%4,%5,%6,%7},{%8,%9},{%0,%1,%2,%3};\n" \
                 : "+f"((d)[0]), "+f"((d)[1]), "+f"((d)[2]), "+f"((d)[3]) \
                 : "r"((a)[0]), "r"((a)[1]), "r"((a)[2]), "r"((a)[3]), \
                   "r"((b)[0]), "r"((b)[1]))
#define MMA3B(d, aH, aL, bH, bL) do { \
    MMA_BF16(d, aL, bH); \
    MMA_BF16(d, aH, bL); \
    MMA_BF16(d, aH, bH); } while (0)

// =================================================================
// fp32 -> packed fp16 pair conversion
// =================================================================
__global__ __launch_bounds__(256) void tofp16_kernel(
    const float* __restrict__ src, uint32_t* __restrict__ dst)
{
    const int idx = blockIdx.x * 256 + threadIdx.x;
    float2 v = ((const float2*)src)[idx];
    dst[idx] = packh2(v.x, v.y);
}

// =================================================================
// fp16 tensor-core GEMM (NT): C[M,N] = A[M,K] @ B[N,K]^T
// A16/B16: packed fp16 pairs, Kp = K/2 pairs per row.
// BM=128, BN=128, BK=16 pairs (32 elems), 256 thr, 2-stage cp.async.
// Row-major smem tiles [row][kpair], stride 20 words (conflict-free).
// =================================================================
__global__ __launch_bounds__(256) void gemm_fp16(
    const uint32_t* __restrict__ A16, const uint32_t* __restrict__ B16,
    float* __restrict__ C, int M, int N, int Kp,
    const float* __restrict__ gate)
{
    __shared__ uint32_t As[2][128][20];
    __shared__ uint32_t Bs[2][128][20];

    const int tid  = threadIdx.x;
    const int lane = tid & 31;
    const int warp = tid >> 5;
    const int wm   = warp >> 2;
    const int wn   = warp & 3;
    const int m0   = blockIdx.y * 128;
    const int n0   = blockIdx.x * 128;
    const int qr   = lane >> 2;
    const int ql   = lane & 3;

    // fill mapping: 1024 chunks of 16B (4 kpairs); 4 per thread
    const uint32_t* csrc[4];
    int crow[4], cg[4];
    bool cbt[4], cval[4];
    #pragma unroll
    for (int q = 0; q < 4; q++) {
        int e = tid + q * 256;
        bool isB = e >= 512;
        int r = (e & 511) >> 2;
        int g = (e & 3) * 4;
        cbt[q] = isB; crow[q] = r; cg[q] = g;
        int grow = isB ? min(n0 + r, N - 1) : (m0 + r);
        cval[q] = isB ? ((n0 + r) < N) : true;
        csrc[q] = (isB ? B16 : A16) + (size_t)grow * Kp + g;
    }

    float acc[4][4][4];
    #pragma unroll
    for (int i = 0; i < 4; i++)
        #pragma unroll
        for (int j = 0; j < 4; j++)
            #pragma unroll
            for (int r = 0; r < 4; r++) acc[i][j][r] = 0.f;

    const int KT = Kp / 16;

    #define GF_FILL(kt, s)                                                       \
    {                                                                            \
        const size_t ko = (size_t)(kt) * 16;                                     \
        _Pragma("unroll")                                                        \
        for (int q = 0; q < 4; q++) {                                            \
            uint32_t d = (uint32_t)__cvta_generic_to_shared(                     \
                cbt[q] ? &Bs[s][crow[q]][cg[q]] : &As[s][crow[q]][cg[q]]);       \
            CPA16P(d, csrc[q] + ko, cval[q]);                                    \
        }                                                                        \
        CPA_COMMIT();                                                            \
    }

    GF_FILL(0, 0);

    for (int kt = 0; kt < KT; kt++) {
        const int st = kt & 1;
        CPA_WAIT0();
        __syncthreads();

        if (kt + 1 < KT) GF_FILL(kt + 1, st ^ 1);

        #pragma unroll
        for (int kb = 0; kb < 2; kb++) {
            const int k0 = kb * 8 + ql;
            uint32_t a[4][4], b[4][2];
            #pragma unroll
            for (int mf = 0; mf < 4; mf++) {
                const int r = wm * 64 + mf * 16 + qr;
                a[mf][0] = As[st][r][k0];
                a[mf][1] = As[st][r + 8][k0];
                a[mf][2] = As[st][r][k0 + 4];
                a[mf][3] = As[st][r + 8][k0 + 4];
            }
            #pragma unroll
            for (int nf = 0; nf < 4; nf++) {
                const int c = wn * 32 + nf * 8 + qr;
                b[nf][0] = Bs[st][c][k0];
                b[nf][1] = Bs[st][c][k0 + 4];
            }
            #pragma unroll
            for (int mf = 0; mf < 4; mf++)
                #pragma unroll
                for (int nf = 0; nf < 4; nf++)
                    MMA_F16(acc[mf][nf], a[mf], b[nf]);
        }
    }
    #undef GF_FILL

    float scale = 1.f;
    if (gate) { float g = *gate; scale = 1.f / (1.f + expf(-g)); }

    #pragma unroll
    for (int mf = 0; mf < 4; mf++) {
        const int r = m0 + wm * 64 + mf * 16 + qr;
        #pragma unroll
        for (int nf = 0; nf < 4; nf++) {
            const int c = n0 + wn * 32 + nf * 8 + ql * 2;
            if (c < N) {
                float2 v0 = make_float2(acc[mf][nf][0] * scale, acc[mf][nf][1] * scale);
                float2 v1 = make_float2(acc[mf][nf][2] * scale, acc[mf][nf][3] * scale);
                *(float2*)&C[(size_t)r * N + c]       = v0;
                *(float2*)&C[(size_t)(r + 8) * N + c] = v1;
            }
        }
    }
}

// =================================================================
// Causal depthwise conv1d (width 4) + bias + SiLU on xBC slice
// =================================================================
__global__ __launch_bounds__(256) void conv_silu_kernel(
    const float* __restrict__ conv_w, const float* __restrict__ conv_b)
{
    const long idx = (long)blockIdx.x * 256 + threadIdx.x;
    const int  c   = (int)(idx % CONVDIM);
    const long row = idx / CONVDIM;
    const int  l   = (int)(row % LSEQ);

    float acc = conv_b[c];
    const float w0 = conv_w[c*4+0], w1 = conv_w[c*4+1];
    const float w2 = conv_w[c*4+2], w3 = conv_w[c*4+3];
    const float* base = g_zxbcdt + (size_t)row * DPROJ + DINNER + c;
    if (l >= 3) acc = fmaf(base[-3*DPROJ], w0, acc);
    if (l >= 2) acc = fmaf(base[-2*DPROJ], w1, acc);
    if (l >= 1) acc = fmaf(base[-1*DPROJ], w2, acc);
    acc = fmaf(base[0], w3, acc);
    g_xBC[idx] = acc / (1.f + expf(-acc));
}

// =================================================================
// dt = softplus(dt_raw + dt_bias)
// =================================================================
__global__ __launch_bounds__(256) void dt_kernel(const float* __restrict__ dt_bias)
{
    const int idx = blockIdx.x * 256 + threadIdx.x;
    const int h   = idx % NHEADS;
    const int row = idx / NHEADS;
    float v  = g_zxbcdt[(size_t)row * DPROJ + (DINNER + CONVDIM) + h] + dt_bias[h];
    float sp = (v > 20.f) ? v : log1pf(expf(v));
    g_dt[idx] = sp;
}

// =================================================================
// K1: fused per-chunk kernel, bf16x2-split (3-term) legacy MMAs (R8)
// =================================================================
#define K1_SMEM_U32 51332
#define K3_SMEM_U32 25732

__global__ __launch_bounds__(256) void chunk_fused_kernel(
    const float* __restrict__ A_log, const float* __restrict__ Dvec)
{
    extern __shared__ uint32_t smu[];
    uint32_t* CHs = smu;
    uint32_t* CLs = smu + 8448;
    uint32_t* BHs = smu + 16896;
    uint32_t* BLs = smu + 25344;
    uint32_t* XHs = smu + 33792;
    uint32_t* XLs = smu + 38144;
    float*    XF  = (float*)(smu + 42496);
    float*    sa  = (float*)(smu + 50944);
    float*    sdt = (float*)(smu + 51072);
    float*    sw  = (float*)(smu + 51200);
    float*    wsum4 = (float*)(smu + 51328);

    const int blk = blockIdx.x;
    const int bh = blk >> 4, seg = blk & (NSEG - 1);
    const int b = bh / NHEADS, h = bh % NHEADS;
    const int tid = threadIdx.x, lane = tid & 31, warp = tid >> 5;
    const int qr = lane >> 2, ql = lane & 3;
    const size_t rowbase = (size_t)b * LSEQ + seg * SEGLEN;

    #pragma unroll
    for (int i = 0; i < 32; i++) {
        int e = tid + i * 256;
        int np = e & 63, t = e >> 6;
        const float* src = g_xBC + (rowbase + t) * CONVDIM + DINNER + 2*np;
        float2 bv = *(const float2*)src;
        float2 cv = *(const float2*)(src + DSTATE);
        uint32_t hh, ll;
        bsplit2(bv.x, bv.y, hh, ll); BHs[np*132 + t] = hh; BLs[np*132 + t] = ll;
        bsplit2(cv.x, cv.y, hh, ll); CHs[np*132 + t] = hh; CLs[np*132 + t] = ll;
    }
    #pragma unroll
    for (int i = 0; i < 16; i++) {
        int e = tid + i * 256;
        int p = e & 63, sp = e >> 6;
        const float* s0 = g_xBC + (rowbase + 2*sp) * CONVDIM + h * HEADDIM + p;
        float f0 = s0[0], f1 = s0[CONVDIM];
        uint32_t hh, ll;
        bsplit2(f0, f1, hh, ll);
        XHs[sp*68 + p] = hh; XLs[sp*68 + p] = ll;
        XF[p*132 + 2*sp] = f0; XF[p*132 + 2*sp + 1] = f1;
    }

    const float Aneg = -expf(A_log[h]);
    float vdt = 0.f, acs = 0.f;
    if (tid < SEGLEN) {
        vdt = g_dt[(rowbase + tid) * NHEADS + h];
        acs = vdt;
        #pragma unroll
        for (int o = 1; o < 32; o <<= 1) {
            float nv = __shfl_up_sync(0xffffffffu, acs, o);
            if (lane >= o) acs += nv;
        }
        if (lane == 31) wsum4[warp] = acs;
    }
    __syncthreads();
    if (tid < SEGLEN) {
        float tot = wsum4[0] + wsum4[1] + wsum4[2] + wsum4[3];
        float pre = 0.f;
        #pragma unroll
        for (int w2 = 0; w2 < 4; w2++) if (w2 < warp) pre += wsum4[w2];
        float a = acs + pre;
        sa[tid]  = a;
        sdt[tid] = vdt;
        sw[tid]  = vdt * __expf(Aneg * (tot - a));
    }
    __syncthreads();

    // GEMM1: M = C @ B^T
    float mreg[4][4][4];
    #pragma unroll
    for (int i = 0; i < 4; i++)
        #pragma unroll
        for (int j = 0; j < 4; j++)
            #pragma unroll
            for (int r = 0; r < 4; r++) mreg[i][j][r] = 0.f;

    const int m1 = (warp >> 2) * 64, n1 = (warp & 3) * 32;
    #pragma unroll
    for (int kb = 0; kb < 8; kb++) {
        const int k0 = kb*8 + ql, k4 = k0 + 4;
        uint32_t aH[4][4], aL[4][4], bHf[4][2], bLf[4][2];
        #pragma unroll
        for (int mf = 0; mf < 4; mf++) {
            int r = m1 + mf*16 + qr;
            aH[mf][0] = CHs[k0*132 + r];     aL[mf][0] = CLs[k0*132 + r];
            aH[mf][1] = CHs[k0*132 + r + 8]; aL[mf][1] = CLs[k0*132 + r + 8];
            aH[mf][2] = CHs[k4*132 + r];     aL[mf][2] = CLs[k4*132 + r];
            aH[mf][3] = CHs[k4*132 + r + 8]; aL[mf][3] = CLs[k4*132 + r + 8];
        }
        #pragma unroll
        for (int nf = 0; nf < 4; nf++) {
            int c = n1 + nf*8 + qr;
            bHf[nf][0] = BHs[k0*132 + c];  bHf[nf][1] = BHs[k4*132 + c];
            bLf[nf][0] = BLs[k0*132 + c];  bLf[nf][1] = BLs[k4*132 + c];
        }
        #pragma unroll
        for (int mf = 0; mf < 4; mf++)
            #pragma unroll
            for (int nf = 0; nf < 4; nf++)
                MMA3B(mreg[mf][nf], aH[mf], aL[mf], bHf[nf], bLf[nf]);
    }
    __syncthreads();

    #pragma unroll
    for (int mf = 0; mf < 4; mf++) {
        int tA = m1 + mf*16 + qr, tB = tA + 8;
        float aA = sa[tA], aB = sa[tB];
        #pragma unroll
        for (int nf = 0; nf < 4; nf++) {
            int sp = (n1 >> 1) + nf*4 + ql;
            int s0 = 2*sp, s1 = s0 + 1;
            float as0 = sa[s0], as1 = sa[s1];
            float d0 = sdt[s0], d1 = sdt[s1];
            float v00 = (s0 <= tA) ? mreg[mf][nf][0] * __expf(Aneg*(aA-as0)) * d0 : 0.f;
            float v01 = (s1 <= tA) ? mreg[mf][nf][1] * __expf(Aneg*(aA-as1)) * d1 : 0.f;
            float v10 = (s0 <= tB) ? mreg[mf][nf][2] * __expf(Aneg*(aB-as0)) * d0 : 0.f;
            float v11 = (s1 <= tB) ? mreg[mf][nf][3] * __expf(Aneg*(aB-as1)) * d1 : 0.f;
            uint32_t hh, ll;
            bsplit2(v00, v01, hh, ll); CHs[sp*132 + tA] = hh; CLs[sp*132 + tA] = ll;
            bsplit2(v10, v11, hh, ll); CHs[sp*132 + tB] = hh; CLs[sp*132 + tB] = ll;
        }
    }

    #pragma unroll
    for (int i = 0; i < 32; i++) {
        int e = tid + i * 256;
        int n = e & 127, sp = e >> 7;
        const float* s0 = g_xBC + (rowbase + 2*sp) * CONVDIM + DINNER + n;
        float f0 = s0[0] * sw[2*sp];
        float f1 = s0[CONVDIM] * sw[2*sp + 1];
        uint32_t hh, ll;
        bsplit2(f0, f1, hh, ll);
        BHs[sp*132 + n] = hh; BLs[sp*132 + n] = ll;
    }
    __syncthreads();

    // GEMM2: Y = M~ @ X
    {
        float yreg[2][4][4];
        #pragma unroll
        for (int i = 0; i < 2; i++)
            #pragma unroll
            for (int j = 0; j < 4; j++)
                #pragma unroll
                for (int r = 0; r < 4; r++) yreg[i][j][r] = 0.f;

        const int m2 = (warp >> 1) * 32, n2 = (warp & 1) * 32;
        #pragma unroll
        for (int kb = 0; kb < 8; kb++) {
            const int k0 = kb*8 + ql, k4 = k0 + 4;
            uint32_t aH[2][4], aL[2][4], bHf[4][2], bLf[4][2];
            #pragma unroll
            for (int mf = 0; mf < 2; mf++) {
                int r = m2 + mf*16 + qr;
                aH[mf][0] = CHs[k0*132 + r];     aL[mf][0] = CLs[k0*132 + r];
                aH[mf][1] = CHs[k0*132 + r + 8]; aL[mf][1] = CLs[k0*132 + r + 8];
                aH[mf][2] = CHs[k4*132 + r];     aL[mf][2] = CLs[k4*132 + r];
                aH[mf][3] = CHs[k4*132 + r + 8]; aL[mf][3] = CLs[k4*132 + r + 8];
            }
            #pragma unroll
            for (int nf = 0; nf < 4; nf++) {
                int c = n2 + nf*8 + qr;
                bHf[nf][0] = XHs[k0*68 + c];  bHf[nf][1] = XHs[k4*68 + c];
                bLf[nf][0] = XLs[k0*68 + c];  bLf[nf][1] = XLs[k4*68 + c];
            }
            #pragma unroll
            for (int mf = 0; mf < 2; mf++)
                #pragma unroll
                for (int nf = 0; nf < 4; nf++)
                    MMA3B(yreg[mf][nf], aH[mf], aL[mf], bHf[nf], bLf[nf]);
        }

        const float Dh = Dvec[h];
        #pragma unroll
        for (int mf = 0; mf < 2; mf++) {
            int t = m2 + mf*16 + qr;
            #pragma unroll
            for (int nf = 0; nf < 4; nf++) {
                int p0 = n2 + nf*8 + ql*2;
                float2 o;
                o.x = yreg[mf][nf][0] + Dh * XF[p0*132 + t];
                o.y = yreg[mf][nf][1] + Dh * XF[(p0+1)*132 + t];
                *(float2*)&g_y[(rowbase + t)*DINNER + h*HEADDIM + p0] = o;
                o.x = yreg[mf][nf][2] + Dh * XF[p0*132 + t + 8];
                o.y = yreg[mf][nf][3] + Dh * XF[(p0+1)*132 + t + 8];
                *(float2*)&g_y[(rowbase + t + 8)*DINNER + h*HEADDIM + p0] = o;
            }
        }
    }

    // GEMM3: S = X^T @ (w*B)
    {
        float sreg[2][4][4];
        #pragma unroll
        for (int i = 0; i < 2; i++)
            #pragma unroll
            for (int j = 0; j < 4; j++)
                #pragma unroll
                for (int r = 0; r < 4; r++) sreg[i][j][r] = 0.f;

        const int m3 = (warp >> 2) * 32, n3 = (warp & 3) * 32;
        #pragma unroll
        for (int kb = 0; kb < 8; kb++) {
            const int k0 = kb*8 + ql, k4 = k0 + 4;
            uint32_t aH[2][4], aL[2][4], bHf[4][2], bLf[4][2];
            #pragma unroll
            for (int mf = 0; mf < 2; mf++) {
                int r = m3 + mf*16 + qr;
                aH[mf][0] = XHs[k0*68 + r];     aL[mf][0] = XLs[k0*68 + r];
                aH[mf][1] = XHs[k0*68 + r + 8]; aL[mf][1] = XLs[k0*68 + r + 8];
                aH[mf][2] = XHs[k4*68 + r];     aL[mf][2] = XLs[k4*68 + r];
                aH[mf][3] = XHs[k4*68 + r + 8]; aL[mf][3] = XLs[k4*68 + r + 8];
            }
            #pragma unroll
            for (int nf = 0; nf < 4; nf++) {
                int c = n3 + nf*8 + qr;
                bHf[nf][0] = BHs[k0*132 + c];  bHf[nf][1] = BHs[k4*132 + c];
                bLf[nf][0] = BLs[k0*132 + c];  bLf[nf][1] = BLs[k4*132 + c];
            }
            #pragma unroll
            for (int mf = 0; mf < 2; mf++)
                #pragma unroll
                for (int nf = 0; nf < 4; nf++)
                    MMA3B(sreg[mf][nf], aH[mf], aL[mf], bHf[nf], bLf[nf]);
        }

        const size_t sbase = ((size_t)bh * NSEG + seg) * STATESZ;
        #pragma unroll
        for (int mf = 0; mf < 2; mf++) {
            int p = m3 + mf*16 + qr;
            #pragma unroll
            for (int nf = 0; nf < 4; nf++) {
                int n0 = n3 + nf*8 + ql*2;
                float2 o0 = make_float2(sreg[mf][nf][0], sreg[mf][nf][1]);
                float2 o1 = make_float2(sreg[mf][nf][2], sreg[mf][nf][3]);
                *(float2*)&g_states[sbase + (size_t)p * DSTATE + n0]       = o0;
                *(float2*)&g_states[sbase + (size_t)(p + 8) * DSTATE + n0] = o1;
            }
        }
    }
}

// =================================================================
// K2: combine
// =================================================================
__global__ __launch_bounds__(256) void combine_kernel(const float* __restrict__ A_log)
{
    const int bh = blockIdx.x;
    const int b = bh / NHEADS, h = bh % NHEADS;
    const int tid = threadIdx.x;

    __shared__ float part[256];
    __shared__ float Esh[NSEG];

    {
        const int k = tid >> 4, i = tid & 15;
        float s = 0.f;
        const size_t base = ((size_t)b*LSEQ + k*SEGLEN + i*8)*NHEADS + h;
        #pragma unroll
        for (int t = 0; t < 8; t++) s += g_dt[base + (size_t)t*NHEADS];
        part[tid] = s;
    }
    __syncthreads();
    if (tid < NSEG) {
        float s = 0.f;
        #pragma unroll
        for (int i = 0; i < 16; i++) s += part[tid*16 + i];
        Esh[tid] = expf(-expf(A_log[h]) * s);
    }
    __syncthreads();

    float hs[32];
    #pragma unroll
    for (int k2 = 0; k2 < 32; k2++) hs[k2] = 0.f;

    for (int seg = 0; seg < NSEG; seg++) {
        const size_t base = ((size_t)bh*NSEG + seg)*STATESZ;
        const float E = Esh[seg];
        #pragma unroll
        for (int k2 = 0; k2 < 32; k2++) {
            const size_t e = base + k2*256 + tid;
            g_hstart[e] = hs[k2];
            hs[k2] = fmaf(hs[k2], E, g_states[e]);
        }
    }
}

// =================================================================
// K3: inter-chunk (R8)
// =================================================================
__global__ __launch_bounds__(256) void inter_kernel(const float* __restrict__ A_log)
{
    extern __shared__ uint32_t smu[];
    uint32_t* CH2 = smu;
    uint32_t* CL2 = smu + 8448;
    uint32_t* HHs = smu + 16896;
    uint32_t* HLs = smu + 21248;
    float*    su  = (float*)(smu + 25600);
    float*    wsum4 = (float*)(smu + 25728);

    const int blk = blockIdx.x;
    const int bh = blk >> 4, seg = blk & (NSEG - 1);
    const int b = bh / NHEADS, h = bh % NHEADS;
    const int tid = threadIdx.x, lane = tid & 31, warp = tid >> 5;
    const int qr = lane >> 2, ql = lane & 3;
    const size_t rowbase = (size_t)b * LSEQ + seg * SEGLEN;
    const size_t hbase = ((size_t)bh * NSEG + seg) * STATESZ;

    #pragma unroll
    for (int i = 0; i < 32; i++) {
        int e = tid + i * 256;
        int np = e & 63, t = e >> 6;
        const float* src = g_xBC + (rowbase + t) * CONVDIM + DINNER + DSTATE + 2*np;
        float2 cv = *(const float2*)src;
        uint32_t hh, ll;
        bsplit2(cv.x, cv.y, hh, ll);
        CH2[np*132 + t] = hh; CL2[np*132 + t] = ll;
    }
    #pragma unroll
    for (int i = 0; i < 16; i++) {
        int e = tid + i * 256;
        int np = e & 63, p = e >> 6;
        const float* src = g_hstart + hbase + (size_t)p * DSTATE + 2*np;
        float2 hv = *(const float2*)src;
        uint32_t hh, ll;
        bsplit2(hv.x, hv.y, hh, ll);
        HHs[np*68 + p] = hh; HLs[np*68 + p] = ll;
    }

    const float Aneg = -expf(A_log[h]);
    float vdt = 0.f, acs = 0.f;
    if (tid < SEGLEN) {
        vdt = g_dt[(rowbase + tid) * NHEADS + h];
        acs = vdt;
        #pragma unroll
        for (int o = 1; o < 32; o <<= 1) {
            float nv = __shfl_up_sync(0xffffffffu, acs, o);
            if (lane >= o) acs += nv;
        }
        if (lane == 31) wsum4[warp] = acs;
    }
    __syncthreads();
    if (tid < SEGLEN) {
        float pre = 0.f;
        #pragma unroll
        for (int w2 = 0; w2 < 4; w2++) if (w2 < warp) pre += wsum4[w2];
        su[tid] = __expf(Aneg * (acs + pre));
    }
    __syncthreads();

    float yreg[2][4][4];
    #pragma unroll
    for (int i = 0; i < 2; i++)
        #pragma unroll
        for (int j = 0; j < 4; j++)
            #pragma unroll
            for (int r = 0; r < 4; r++) yreg[i][j][r] = 0.f;

    const int m2 = (warp >> 1) * 32, n2 = (warp & 1) * 32;
    #pragma unroll
    for (int kb = 0; kb < 8; kb++) {
        const int k0 = kb*8 + ql, k4 = k0 + 4;
        uint32_t aH[2][4], aL[2][4], bHf[4][2], bLf[4][2];
        #pragma unroll
        for (int mf = 0; mf < 2; mf++) {
            int r = m2 + mf*16 + qr;
            aH[mf][0] = CH2[k0*132 + r];     aL[mf][0] = CL2[k0*132 + r];
            aH[mf][1] = CH2[k0*132 + r + 8]; aL[mf][1] = CL2[k0*132 + r + 8];
            aH[mf][2] = CH2[k4*132 + r];     aL[mf][2] = CL2[k4*132 + r];
            aH[mf][3] = CH2[k4*132 + r + 8]; aL[mf][3] = CL2[k4*132 + r + 8];
        }
        #pragma unroll
        for (int nf = 0; nf < 4; nf++) {
            int c = n2 + nf*8 + qr;
            bHf[nf][0] = HHs[k0*68 + c];  bHf[nf][1] = HHs[k4*68 + c];
            bLf[nf][0] = HLs[k0*68 + c];  bLf[nf][1] = HLs[k4*68 + c];
        }
        #pragma unroll
        for (int mf = 0; mf < 2; mf++)
            #pragma unroll
            for (int nf = 0; nf < 4; nf++)
                MMA3B(yreg[mf][nf], aH[mf], aL[mf], bHf[nf], bLf[nf]);
    }

    #pragma unroll
    for (int mf = 0; mf < 2; mf++) {
        int t = m2 + mf*16 + qr;
        float u0 = su[t], u1 = su[t + 8];
        #pragma unroll
        for (int nf = 0; nf < 4; nf++) {
            int p0 = n2 + nf*8 + ql*2;
            float* addr0 = &g_y[(rowbase + t)*DINNER + h*HEADDIM + p0];
            float* addr1 = &g_y[(rowbase + t + 8)*DINNER + h*HEADDIM + p0];
            float2 o0 = *(float2*)addr0;
            float2 o1 = *(float2*)addr1;
            o0.x += u0 * yreg[mf][nf][0];  o0.y += u0 * yreg[mf][nf][1];
            o1.x += u1 * yreg[mf][nf][2];  o1.y += u1 * yreg[mf][nf][3];
            *(float2*)addr0 = o0;
            *(float2*)addr1 = o1;
        }
    }
}

// =================================================================
// gate+norm: y = y*silu(z); rmsnorm; emit packed fp16 pairs for out_proj
// =================================================================
__global__ __launch_bounds__(256) void gate_norm_kernel(const float* __restrict__ norm_w)
{
    const int row = blockIdx.x;
    const int tid = threadIdx.x;
    const float* zrow = g_zxbcdt + (size_t)row * DPROJ;
    const float* yrow = g_y + (size_t)row * DINNER;

    float2 v[3];
    float ss = 0.f;
    #pragma unroll
    for (int i = 0; i < 3; i++) {
        int p = tid + i*256;            // pair index < 768
        float2 z2 = *(const float2*)&zrow[2*p];
        float2 y2 = *(const float2*)&yrow[2*p];
        float g0 = y2.x * (z2.x / (1.f + expf(-z2.x)));
        float g1 = y2.y * (z2.y / (1.f + expf(-z2.y)));
        v[i] = make_float2(g0, g1);
        ss += g0*g0 + g1*g1;
    }
    #pragma unroll
    for (int o = 16; o > 0; o >>= 1) ss += __shfl_xor_sync(0xffffffffu, ss, o);
    __shared__ float red[8];
    if ((tid & 31) == 0) red[tid >> 5] = ss;
    __syncthreads();
    if (tid < 32) {
        float s2 = (tid < 8) ? red[tid] : 0.f;
        #pragma unroll
        for (int o = 4; o > 0; o >>= 1) s2 += __shfl_xor_sync(0xffffffffu, s2, o);
        if (tid == 0) red[0] = s2;
    }
    __syncthreads();
    const float rstd = rsqrtf(red[0] * (1.f/1536.f) + 1e-5f);
    #pragma unroll
    for (int i = 0; i < 3; i++) {
        int p = tid + i*256;
        float2 w2 = *(const float2*)&norm_w[2*p];
        g_y16[(size_t)row * (DINNER/2) + p] =
            packh2(v[i].x * rstd * w2.x, v[i].y * rstd * w2.y);
    }
}

// =================================================================
extern "C" void kernel_launch(void* const* d_in, const int* in_sizes, int n_in,
                              void* d_out, int out_size)
{
    const float* feature   = (const float*)d_in[0];
    const float* in_proj_w = (const float*)d_in[1];
    const float* conv_w    = (const float*)d_in[2];
    const float* conv_b    = (const float*)d_in[3];
    const float* dt_bias   = (const float*)d_in[4];
    const float* A_log     = (const float*)d_in[5];
    const float* Dvec      = (const float*)d_in[6];
    const float* norm_w    = (const float*)d_in[7];
    const float* out_projw = (const float*)d_in[8];
    const float* gate1     = (const float*)d_in[9];
    float* out = (float*)d_out;

    float *zx;
    uint32_t *f16, *iw16, *ow16, *y16;
    cudaGetSymbolAddress((void**)&zx,   g_zxbcdt);
    cudaGetSymbolAddress((void**)&f16,  g_feat16);
    cudaGetSymbolAddress((void**)&iw16, g_ipw16);
    cudaGetSymbolAddress((void**)&ow16, g_opw16);
    cudaGetSymbolAddress((void**)&y16,  g_y16);

    cudaFuncSetAttribute(chunk_fused_kernel,
        cudaFuncAttributeMaxDynamicSharedMemorySize, K1_SMEM_U32 * 4);
    cudaFuncSetAttribute(inter_kernel,
        cudaFuncAttributeMaxDynamicSharedMemorySize, K3_SMEM_U32 * 4);

    dim3 blk(256);

    // operand conversions (fp32 -> packed fp16)
    tofp16_kernel<<<(ROWS*DMODEL/2)/256, blk>>>(feature, f16);
    tofp16_kernel<<<(DPROJ*DMODEL/2)/256, blk>>>(in_proj_w, iw16);
    tofp16_kernel<<<(DMODEL*DINNER/2)/256, blk>>>(out_projw, ow16);

    // in_proj (fp16 tensor cores)
    gemm_fp16<<<dim3((DPROJ + 127)/128, ROWS/128), blk>>>(
        f16, iw16, zx, ROWS, DPROJ, DMODEL/2, nullptr);

    conv_silu_kernel<<<(int)(((long)ROWS * CONVDIM) / 256), blk>>>(conv_w, conv_b);
    dt_kernel<<<(ROWS * NHEADS) / 256, blk>>>(dt_bias);

    chunk_fused_kernel<<<BATCH * NHEADS * NSEG, blk, K1_SMEM_U32 * 4>>>(A_log, Dvec);
    combine_kernel<<<BATCH * NHEADS, blk>>>(A_log);
    inter_kernel<<<BATCH * NHEADS * NSEG, blk, K3_SMEM_U32 * 4>>>(A_log);

    gate_norm_kernel<<<ROWS, blk>>>(norm_w);

    // out_proj (fp16 tensor cores)
    gemm_fp16<<<dim3(DMODEL/128, ROWS/128), blk>>>(
        y16, ow16, out, ROWS, DMODEL, DINNER/2, gate1);
}

// round 11
// speedup vs baseline: 1.5141x; 1.0059x over previous
#include <cuda_runtime.h>
#include <cuda_fp16.h>
#include <math.h>
#include <stdint.h>

#define BATCH   4
#define LSEQ    2048
#define ROWS    (BATCH*LSEQ)      // 8192
#define DMODEL  768
#define DINNER  1536
#define NHEADS  24
#define HEADDIM 64
#define DSTATE  128
#define CONVDIM 1792
#define DPROJ   3352

#define NSEG    16
#define SEGLEN  (LSEQ/NSEG)       // 128
#define STATESZ (HEADDIM*DSTATE)  // 8192

// -------- scratch (device globals; no allocation allowed) --------
__device__ float g_zxbcdt[(size_t)ROWS * DPROJ];
__device__ float g_xBC[(size_t)ROWS * CONVDIM];
__device__ float g_dt[ROWS * NHEADS];
__device__ float g_y[(size_t)ROWS * DINNER];
__device__ float g_states[(size_t)BATCH*NHEADS*NSEG*STATESZ];
__device__ float g_hstart[(size_t)BATCH*NHEADS*NSEG*STATESZ];
// fp16 packed-pair operands for projection GEMMs
__device__ uint32_t g_feat16[(size_t)ROWS*DMODEL/2];
__device__ uint32_t g_ipw16[(size_t)DPROJ*DMODEL/2];
__device__ uint32_t g_opw16[(size_t)DMODEL*DINNER/2];
__device__ uint32_t g_y16[(size_t)ROWS*DINNER/2];

// =================================================================
// helpers
// =================================================================
__device__ __forceinline__ uint32_t packbf2(float f0, float f1) {
    uint32_t r;
    asm("cvt.rn.bf16x2.f32 %0, %1, %2;" : "=r"(r) : "f"(f1), "f"(f0));
    return r;
}
__device__ __forceinline__ void bsplit2(float f0, float f1, uint32_t& H, uint32_t& L) {
    H = packbf2(f0, f1);
    float h0 = __uint_as_float(H << 16);
    float h1 = __uint_as_float(H & 0xffff0000u);
    L = packbf2(f0 - h0, f1 - h1);
}
__device__ __forceinline__ uint32_t packh2(float f0, float f1) {
    __half2 h = __float22half2_rn(make_float2(f0, f1));   // f0 -> low half
    return *(uint32_t*)&h;
}

#define CPA16(dst, src) \
    asm volatile("cp.async.cg.shared.global [%0], [%1], 16;\n" \
                 :: "r"(dst), "l"(src))
#define CPA16P(dst, src, valid) \
    asm volatile("cp.async.cg.shared.global [%0], [%1], 16, %2;\n" \
                 :: "r"(dst), "l"(src), "r"((valid) ? 16 : 0))
#define CPA_COMMIT() asm volatile("cp.async.commit_group;\n" ::: "memory")
#define CPA_WAIT0()  asm volatile("cp.async.wait_group 0;\n" ::: "memory")

#define MMA_BF16(d, a, b) \
    asm volatile("mma.sync.aligned.m16n8k16.row.col.f32.bf16.bf16.f32 " \
                 "{%0,%1,%2,%3},{%4,%5,%6,%7},{%8,%9},{%0,%1,%2,%3};\n" \
                 : "+f"((d)[0]), "+f"((d)[1]), "+f"((d)[2]), "+f"((d)[3]) \
                 : "r"((a)[0]), "r"((a)[1]), "r"((a)[2]), "r"((a)[3]), \
                   "r"((b)[0]), "r"((b)[1]))
#define MMA_F16(d, a, b) \
    asm volatile("mma.sync.aligned.m16n8k16.row.col.f32.f16.f16.f32 " \
                 "{%0,%1,%2,%3},{%4,%5,%6,%7},{%8,%9},{%0,%1,%2,%3};\n" \
                 : "+f"((d)[0]), "+f"((d)[1]), "+f"((d)[2]), "+f"((d)[3]) \
                 : "r"((a)[0]), "r"((a)[1]), "r"((a)[2]), "r"((a)[3]), \
                   "r"((b)[0]), "r"((b)[1]))
#define MMA3B(d, aH, aL, bH, bL) do { \
    MMA_BF16(d, aL, bH); \
    MMA_BF16(d, aH, bL); \
    MMA_BF16(d, aH, bH); } while (0)

#define LDSM_X4(r0, r1, r2, r3, a) \
    asm volatile("ldmatrix.sync.aligned.m8n8.x4.shared.b16 {%0,%1,%2,%3}, [%4];" \
                 : "=r"(r0), "=r"(r1), "=r"(r2), "=r"(r3) : "r"(a))

// =================================================================
// fp32 -> packed fp16 pair conversion
// =================================================================
__global__ __launch_bounds__(256) void tofp16_kernel(
    const float* __restrict__ src, uint32_t* __restrict__ dst)
{
    const int idx = blockIdx.x * 256 + threadIdx.x;
    float2 v = ((const float2*)src)[idx];
    dst[idx] = packh2(v.x, v.y);
}

// =================================================================
// fp16 tensor-core GEMM (NT): C[M,N] = A[M,K] @ B[N,K]^T
// A16/B16: packed fp16 pairs, Kp = K/2 pairs per row.
// BM=128, BN=128, BK=16 pairs (32 elems), 256 thr, 2-stage cp.async.
// Row-major smem tiles [row][kpair], stride 20 words; ldmatrix frags.
// =================================================================
__global__ __launch_bounds__(256) void gemm_fp16(
    const uint32_t* __restrict__ A16, const uint32_t* __restrict__ B16,
    float* __restrict__ C, int M, int N, int Kp,
    const float* __restrict__ gate)
{
    __shared__ uint32_t As[2][128][20];
    __shared__ uint32_t Bs[2][128][20];

    const int tid  = threadIdx.x;
    const int lane = tid & 31;
    const int warp = tid >> 5;
    const int wm   = warp >> 2;
    const int wn   = warp & 3;
    const int m0   = blockIdx.y * 128;
    const int n0   = blockIdx.x * 128;
    const int qr   = lane >> 2;
    const int ql   = lane & 3;

    // fill mapping: 1024 chunks of 16B (4 kpairs); 4 per thread
    const uint32_t* csrc[4];
    int crow[4], cg[4];
    bool cbt[4], cval[4];
    #pragma unroll
    for (int q = 0; q < 4; q++) {
        int e = tid + q * 256;
        bool isB = e >= 512;
        int r = (e & 511) >> 2;
        int g = (e & 3) * 4;
        cbt[q] = isB; crow[q] = r; cg[q] = g;
        int grow = isB ? min(n0 + r, N - 1) : (m0 + r);
        cval[q] = isB ? ((n0 + r) < N) : true;
        csrc[q] = (isB ? B16 : A16) + (size_t)grow * Kp + g;
    }

    // ldmatrix lane addressing (within the warp's tile)
    const int a_row = wm * 64 + (lane & 15);            // + mf*16
    const int a_kp  = (lane >> 4) << 2;                 // + kb*8
    const int b_row = wn * 32 + ((lane >> 4) << 3) + (lane & 7);  // + nf2*16
    const int b_kp  = ((lane >> 3) & 1) << 2;           // + kb*8

    float acc[4][4][4];
    #pragma unroll
    for (int i = 0; i < 4; i++)
        #pragma unroll
        for (int j = 0; j < 4; j++)
            #pragma unroll
            for (int r = 0; r < 4; r++) acc[i][j][r] = 0.f;

    const int KT = Kp / 16;

    #define GF_FILL(kt, s)                                                       \
    {                                                                            \
        const size_t ko = (size_t)(kt) * 16;                                     \
        _Pragma("unroll")                                                        \
        for (int q = 0; q < 4; q++) {                                            \
            uint32_t d = (uint32_t)__cvta_generic_to_shared(                     \
                cbt[q] ? &Bs[s][crow[q]][cg[q]] : &As[s][crow[q]][cg[q]]);       \
            CPA16P(d, csrc[q] + ko, cval[q]);                                    \
        }                                                                        \
        CPA_COMMIT();                                                            \
    }

    GF_FILL(0, 0);

    for (int kt = 0; kt < KT; kt++) {
        const int st = kt & 1;
        CPA_WAIT0();
        __syncthreads();

        if (kt + 1 < KT) GF_FILL(kt + 1, st ^ 1);

        #pragma unroll
        for (int kb = 0; kb < 2; kb++) {
            const int kp0 = kb * 8;
            uint32_t a[4][4], b[4][2];
            #pragma unroll
            for (int mf = 0; mf < 4; mf++) {
                uint32_t ad = (uint32_t)__cvta_generic_to_shared(
                    &As[st][a_row + mf * 16][kp0 + a_kp]);
                LDSM_X4(a[mf][0], a[mf][1], a[mf][2], a[mf][3], ad);
            }
            #pragma unroll
            for (int nf2 = 0; nf2 < 2; nf2++) {
                uint32_t bd = (uint32_t)__cvta_generic_to_shared(
                    &Bs[st][b_row + nf2 * 16][kp0 + b_kp]);
                LDSM_X4(b[2*nf2][0], b[2*nf2][1], b[2*nf2+1][0], b[2*nf2+1][1], bd);
            }
            #pragma unroll
            for (int mf = 0; mf < 4; mf++)
                #pragma unroll
                for (int nf = 0; nf < 4; nf++)
                    MMA_F16(acc[mf][nf], a[mf], b[nf]);
        }
    }
    #undef GF_FILL

    float scale = 1.f;
    if (gate) { float g = *gate; scale = 1.f / (1.f + expf(-g)); }

    #pragma unroll
    for (int mf = 0; mf < 4; mf++) {
        const int r = m0 + wm * 64 + mf * 16 + qr;
        #pragma unroll
        for (int nf = 0; nf < 4; nf++) {
            const int c = n0 + wn * 32 + nf * 8 + ql * 2;
            if (c < N) {
                float2 v0 = make_float2(acc[mf][nf][0] * scale, acc[mf][nf][1] * scale);
                float2 v1 = make_float2(acc[mf][nf][2] * scale, acc[mf][nf][3] * scale);
                *(float2*)&C[(size_t)r * N + c]       = v0;
                *(float2*)&C[(size_t)(r + 8) * N + c] = v1;
            }
        }
    }
}

// =================================================================
// Causal depthwise conv1d (width 4) + bias + SiLU on xBC slice
// =================================================================
__global__ __launch_bounds__(256) void conv_silu_kernel(
    const float* __restrict__ conv_w, const float* __restrict__ conv_b)
{
    const long idx = (long)blockIdx.x * 256 + threadIdx.x;
    const int  c   = (int)(idx % CONVDIM);
    const long row = idx / CONVDIM;
    const int  l   = (int)(row % LSEQ);

    float acc = conv_b[c];
    const float w0 = conv_w[c*4+0], w1 = conv_w[c*4+1];
    const float w2 = conv_w[c*4+2], w3 = conv_w[c*4+3];
    const float* base = g_zxbcdt + (size_t)row * DPROJ + DINNER + c;
    if (l >= 3) acc = fmaf(base[-3*DPROJ], w0, acc);
    if (l >= 2) acc = fmaf(base[-2*DPROJ], w1, acc);
    if (l >= 1) acc = fmaf(base[-1*DPROJ], w2, acc);
    acc = fmaf(base[0], w3, acc);
    g_xBC[idx] = acc / (1.f + expf(-acc));
}

// =================================================================
// dt = softplus(dt_raw + dt_bias)
// =================================================================
__global__ __launch_bounds__(256) void dt_kernel(const float* __restrict__ dt_bias)
{
    const int idx = blockIdx.x * 256 + threadIdx.x;
    const int h   = idx % NHEADS;
    const int row = idx / NHEADS;
    float v  = g_zxbcdt[(size_t)row * DPROJ + (DINNER + CONVDIM) + h] + dt_bias[h];
    float sp = (v > 20.f) ? v : log1pf(expf(v));
    g_dt[idx] = sp;
}

// =================================================================
// K1: fused per-chunk kernel, bf16x2-split (3-term) legacy MMAs (R8)
// =================================================================
#define K1_SMEM_U32 51332
#define K3_SMEM_U32 25732

__global__ __launch_bounds__(256) void chunk_fused_kernel(
    const float* __restrict__ A_log, const float* __restrict__ Dvec)
{
    extern __shared__ uint32_t smu[];
    uint32_t* CHs = smu;
    uint32_t* CLs = smu + 8448;
    uint32_t* BHs = smu + 16896;
    uint32_t* BLs = smu + 25344;
    uint32_t* XHs = smu + 33792;
    uint32_t* XLs = smu + 38144;
    float*    XF  = (float*)(smu + 42496);
    float*    sa  = (float*)(smu + 50944);
    float*    sdt = (float*)(smu + 51072);
    float*    sw  = (float*)(smu + 51200);
    float*    wsum4 = (float*)(smu + 51328);

    const int blk = blockIdx.x;
    const int bh = blk >> 4, seg = blk & (NSEG - 1);
    const int b = bh / NHEADS, h = bh % NHEADS;
    const int tid = threadIdx.x, lane = tid & 31, warp = tid >> 5;
    const int qr = lane >> 2, ql = lane & 3;
    const size_t rowbase = (size_t)b * LSEQ + seg * SEGLEN;

    #pragma unroll
    for (int i = 0; i < 32; i++) {
        int e = tid + i * 256;
        int np = e & 63, t = e >> 6;
        const float* src = g_xBC + (rowbase + t) * CONVDIM + DINNER + 2*np;
        float2 bv = *(const float2*)src;
        float2 cv = *(const float2*)(src + DSTATE);
        uint32_t hh, ll;
        bsplit2(bv.x, bv.y, hh, ll); BHs[np*132 + t] = hh; BLs[np*132 + t] = ll;
        bsplit2(cv.x, cv.y, hh, ll); CHs[np*132 + t] = hh; CLs[np*132 + t] = ll;
    }
    #pragma unroll
    for (int i = 0; i < 16; i++) {
        int e = tid + i * 256;
        int p = e & 63, sp = e >> 6;
        const float* s0 = g_xBC + (rowbase + 2*sp) * CONVDIM + h * HEADDIM + p;
        float f0 = s0[0], f1 = s0[CONVDIM];
        uint32_t hh, ll;
        bsplit2(f0, f1, hh, ll);
        XHs[sp*68 + p] = hh; XLs[sp*68 + p] = ll;
        XF[p*132 + 2*sp] = f0; XF[p*132 + 2*sp + 1] = f1;
    }

    const float Aneg = -expf(A_log[h]);
    float vdt = 0.f, acs = 0.f;
    if (tid < SEGLEN) {
        vdt = g_dt[(rowbase + tid) * NHEADS + h];
        acs = vdt;
        #pragma unroll
        for (int o = 1; o < 32; o <<= 1) {
            float nv = __shfl_up_sync(0xffffffffu, acs, o);
            if (lane >= o) acs += nv;
        }
        if (lane == 31) wsum4[warp] = acs;
    }
    __syncthreads();
    if (tid < SEGLEN) {
        float tot = wsum4[0] + wsum4[1] + wsum4[2] + wsum4[3];
        float pre = 0.f;
        #pragma unroll
        for (int w2 = 0; w2 < 4; w2++) if (w2 < warp) pre += wsum4[w2];
        float a = acs + pre;
        sa[tid]  = a;
        sdt[tid] = vdt;
        sw[tid]  = vdt * __expf(Aneg * (tot - a));
    }
    __syncthreads();

    // GEMM1: M = C @ B^T
    float mreg[4][4][4];
    #pragma unroll
    for (int i = 0; i < 4; i++)
        #pragma unroll
        for (int j = 0; j < 4; j++)
            #pragma unroll
            for (int r = 0; r < 4; r++) mreg[i][j][r] = 0.f;

    const int m1 = (warp >> 2) * 64, n1 = (warp & 3) * 32;
    #pragma unroll
    for (int kb = 0; kb < 8; kb++) {
        const int k0 = kb*8 + ql, k4 = k0 + 4;
        uint32_t aH[4][4], aL[4][4], bHf[4][2], bLf[4][2];
        #pragma unroll
        for (int mf = 0; mf < 4; mf++) {
            int r = m1 + mf*16 + qr;
            aH[mf][0] = CHs[k0*132 + r];     aL[mf][0] = CLs[k0*132 + r];
            aH[mf][1] = CHs[k0*132 + r + 8]; aL[mf][1] = CLs[k0*132 + r + 8];
            aH[mf][2] = CHs[k4*132 + r];     aL[mf][2] = CLs[k4*132 + r];
            aH[mf][3] = CHs[k4*132 + r + 8]; aL[mf][3] = CLs[k4*132 + r + 8];
        }
        #pragma unroll
        for (int nf = 0; nf < 4; nf++) {
            int c = n1 + nf*8 + qr;
            bHf[nf][0] = BHs[k0*132 + c];  bHf[nf][1] = BHs[k4*132 + c];
            bLf[nf][0] = BLs[k0*132 + c];  bLf[nf][1] = BLs[k4*132 + c];
        }
        #pragma unroll
        for (int mf = 0; mf < 4; mf++)
            #pragma unroll
            for (int nf = 0; nf < 4; nf++)
                MMA3B(mreg[mf][nf], aH[mf], aL[mf], bHf[nf], bLf[nf]);
    }
    __syncthreads();

    #pragma unroll
    for (int mf = 0; mf < 4; mf++) {
        int tA = m1 + mf*16 + qr, tB = tA + 8;
        float aA = sa[tA], aB = sa[tB];
        #pragma unroll
        for (int nf = 0; nf < 4; nf++) {
            int sp = (n1 >> 1) + nf*4 + ql;
            int s0 = 2*sp, s1 = s0 + 1;
            float as0 = sa[s0], as1 = sa[s1];
            float d0 = sdt[s0], d1 = sdt[s1];
            float v00 = (s0 <= tA) ? mreg[mf][nf][0] * __expf(Aneg*(aA-as0)) * d0 : 0.f;
            float v01 = (s1 <= tA) ? mreg[mf][nf][1] * __expf(Aneg*(aA-as1)) * d1 : 0.f;
            float v10 = (s0 <= tB) ? mreg[mf][nf][2] * __expf(Aneg*(aB-as0)) * d0 : 0.f;
            float v11 = (s1 <= tB) ? mreg[mf][nf][3] * __expf(Aneg*(aB-as1)) * d1 : 0.f;
            uint32_t hh, ll;
            bsplit2(v00, v01, hh, ll); CHs[sp*132 + tA] = hh; CLs[sp*132 + tA] = ll;
            bsplit2(v10, v11, hh, ll); CHs[sp*132 + tB] = hh; CLs[sp*132 + tB] = ll;
        }
    }

    #pragma unroll
    for (int i = 0; i < 32; i++) {
        int e = tid + i * 256;
        int n = e & 127, sp = e >> 7;
        const float* s0 = g_xBC + (rowbase + 2*sp) * CONVDIM + DINNER + n;
        float f0 = s0[0] * sw[2*sp];
        float f1 = s0[CONVDIM] * sw[2*sp + 1];
        uint32_t hh, ll;
        bsplit2(f0, f1, hh, ll);
        BHs[sp*132 + n] = hh; BLs[sp*132 + n] = ll;
    }
    __syncthreads();

    // GEMM2: Y = M~ @ X
    {
        float yreg[2][4][4];
        #pragma unroll
        for (int i = 0; i < 2; i++)
            #pragma unroll
            for (int j = 0; j < 4; j++)
                #pragma unroll
                for (int r = 0; r < 4; r++) yreg[i][j][r] = 0.f;

        const int m2 = (warp >> 1) * 32, n2 = (warp & 1) * 32;
        #pragma unroll
        for (int kb = 0; kb < 8; kb++) {
            const int k0 = kb*8 + ql, k4 = k0 + 4;
            uint32_t aH[2][4], aL[2][4], bHf[4][2], bLf[4][2];
            #pragma unroll
            for (int mf = 0; mf < 2; mf++) {
                int r = m2 + mf*16 + qr;
                aH[mf][0] = CHs[k0*132 + r];     aL[mf][0] = CLs[k0*132 + r];
                aH[mf][1] = CHs[k0*132 + r + 8]; aL[mf][1] = CLs[k0*132 + r + 8];
                aH[mf][2] = CHs[k4*132 + r];     aL[mf][2] = CLs[k4*132 + r];
                aH[mf][3] = CHs[k4*132 + r + 8]; aL[mf][3] = CLs[k4*132 + r + 8];
            }
            #pragma unroll
            for (int nf = 0; nf < 4; nf++) {
                int c = n2 + nf*8 + qr;
                bHf[nf][0] = XHs[k0*68 + c];  bHf[nf][1] = XHs[k4*68 + c];
                bLf[nf][0] = XLs[k0*68 + c];  bLf[nf][1] = XLs[k4*68 + c];
            }
            #pragma unroll
            for (int mf = 0; mf < 2; mf++)
                #pragma unroll
                for (int nf = 0; nf < 4; nf++)
                    MMA3B(yreg[mf][nf], aH[mf], aL[mf], bHf[nf], bLf[nf]);
        }

        const float Dh = Dvec[h];
        #pragma unroll
        for (int mf = 0; mf < 2; mf++) {
            int t = m2 + mf*16 + qr;
            #pragma unroll
            for (int nf = 0; nf < 4; nf++) {
                int p0 = n2 + nf*8 + ql*2;
                float2 o;
                o.x = yreg[mf][nf][0] + Dh * XF[p0*132 + t];
                o.y = yreg[mf][nf][1] + Dh * XF[(p0+1)*132 + t];
                *(float2*)&g_y[(rowbase + t)*DINNER + h*HEADDIM + p0] = o;
                o.x = yreg[mf][nf][2] + Dh * XF[p0*132 + t + 8];
                o.y = yreg[mf][nf][3] + Dh * XF[(p0+1)*132 + t + 8];
                *(float2*)&g_y[(rowbase + t + 8)*DINNER + h*HEADDIM + p0] = o;
            }
        }
    }

    // GEMM3: S = X^T @ (w*B)
    {
        float sreg[2][4][4];
        #pragma unroll
        for (int i = 0; i < 2; i++)
            #pragma unroll
            for (int j = 0; j < 4; j++)
                #pragma unroll
                for (int r = 0; r < 4; r++) sreg[i][j][r] = 0.f;

        const int m3 = (warp >> 2) * 32, n3 = (warp & 3) * 32;
        #pragma unroll
        for (int kb = 0; kb < 8; kb++) {
            const int k0 = kb*8 + ql, k4 = k0 + 4;
            uint32_t aH[2][4], aL[2][4], bHf[4][2], bLf[4][2];
            #pragma unroll
            for (int mf = 0; mf < 2; mf++) {
                int r = m3 + mf*16 + qr;
                aH[mf][0] = XHs[k0*68 + r];     aL[mf][0] = XLs[k0*68 + r];
                aH[mf][1] = XHs[k0*68 + r + 8]; aL[mf][1] = XLs[k0*68 + r + 8];
                aH[mf][2] = XHs[k4*68 + r];     aL[mf][2] = XLs[k4*68 + r];
                aH[mf][3] = XHs[k4*68 + r + 8]; aL[mf][3] = XLs[k4*68 + r + 8];
            }
            #pragma unroll
            for (int nf = 0; nf < 4; nf++) {
                int c = n3 + nf*8 + qr;
                bHf[nf][0] = BHs[k0*132 + c];  bHf[nf][1] = BHs[k4*132 + c];
                bLf[nf][0] = BLs[k0*132 + c];  bLf[nf][1] = BLs[k4*132 + c];
            }
            #pragma unroll
            for (int mf = 0; mf < 2; mf++)
                #pragma unroll
                for (int nf = 0; nf < 4; nf++)
                    MMA3B(sreg[mf][nf], aH[mf], aL[mf], bHf[nf], bLf[nf]);
        }

        const size_t sbase = ((size_t)bh * NSEG + seg) * STATESZ;
        #pragma unroll
        for (int mf = 0; mf < 2; mf++) {
            int p = m3 + mf*16 + qr;
            #pragma unroll
            for (int nf = 0; nf < 4; nf++) {
                int n0 = n3 + nf*8 + ql*2;
                float2 o0 = make_float2(sreg[mf][nf][0], sreg[mf][nf][1]);
                float2 o1 = make_float2(sreg[mf][nf][2], sreg[mf][nf][3]);
                *(float2*)&g_states[sbase + (size_t)p * DSTATE + n0]       = o0;
                *(float2*)&g_states[sbase + (size_t)(p + 8) * DSTATE + n0] = o1;
            }
        }
    }
}

// =================================================================
// K2: combine
// =================================================================
__global__ __launch_bounds__(256) void combine_kernel(const float* __restrict__ A_log)
{
    const int bh = blockIdx.x;
    const int b = bh / NHEADS, h = bh % NHEADS;
    const int tid = threadIdx.x;

    __shared__ float part[256];
    __shared__ float Esh[NSEG];

    {
        const int k = tid >> 4, i = tid & 15;
        float s = 0.f;
        const size_t base = ((size_t)b*LSEQ + k*SEGLEN + i*8)*NHEADS + h;
        #pragma unroll
        for (int t = 0; t < 8; t++) s += g_dt[base + (size_t)t*NHEADS];
        part[tid] = s;
    }
    __syncthreads();
    if (tid < NSEG) {
        float s = 0.f;
        #pragma unroll
        for (int i = 0; i < 16; i++) s += part[tid*16 + i];
        Esh[tid] = expf(-expf(A_log[h]) * s);
    }
    __syncthreads();

    float hs[32];
    #pragma unroll
    for (int k2 = 0; k2 < 32; k2++) hs[k2] = 0.f;

    for (int seg = 0; seg < NSEG; seg++) {
        const size_t base = ((size_t)bh*NSEG + seg)*STATESZ;
        const float E = Esh[seg];
        #pragma unroll
        for (int k2 = 0; k2 < 32; k2++) {
            const size_t e = base + k2*256 + tid;
            g_hstart[e] = hs[k2];
            hs[k2] = fmaf(hs[k2], E, g_states[e]);
        }
    }
}

// =================================================================
// K3: inter-chunk (R8)
// =================================================================
__global__ __launch_bounds__(256) void inter_kernel(const float* __restrict__ A_log)
{
    extern __shared__ uint32_t smu[];
    uint32_t* CH2 = smu;
    uint32_t* CL2 = smu + 8448;
    uint32_t* HHs = smu + 16896;
    uint32_t* HLs = smu + 21248;
    float*    su  = (float*)(smu + 25600);
    float*    wsum4 = (float*)(smu + 25728);

    const int blk = blockIdx.x;
    const int bh = blk >> 4, seg = blk & (NSEG - 1);
    const int b = bh / NHEADS, h = bh % NHEADS;
    const int tid = threadIdx.x, lane = tid & 31, warp = tid >> 5;
    const int qr = lane >> 2, ql = lane & 3;
    const size_t rowbase = (size_t)b * LSEQ + seg * SEGLEN;
    const size_t hbase = ((size_t)bh * NSEG + seg) * STATESZ;

    #pragma unroll
    for (int i = 0; i < 32; i++) {
        int e = tid + i * 256;
        int np = e & 63, t = e >> 6;
        const float* src = g_xBC + (rowbase + t) * CONVDIM + DINNER + DSTATE + 2*np;
        float2 cv = *(const float2*)src;
        uint32_t hh, ll;
        bsplit2(cv.x, cv.y, hh, ll);
        CH2[np*132 + t] = hh; CL2[np*132 + t] = ll;
    }
    #pragma unroll
    for (int i = 0; i < 16; i++) {
        int e = tid + i * 256;
        int np = e & 63, p = e >> 6;
        const float* src = g_hstart + hbase + (size_t)p * DSTATE + 2*np;
        float2 hv = *(const float2*)src;
        uint32_t hh, ll;
        bsplit2(hv.x, hv.y, hh, ll);
        HHs[np*68 + p] = hh; HLs[np*68 + p] = ll;
    }

    const float Aneg = -expf(A_log[h]);
    float vdt = 0.f, acs = 0.f;
    if (tid < SEGLEN) {
        vdt = g_dt[(rowbase + tid) * NHEADS + h];
        acs = vdt;
        #pragma unroll
        for (int o = 1; o < 32; o <<= 1) {
            float nv = __shfl_up_sync(0xffffffffu, acs, o);
            if (lane >= o) acs += nv;
        }
        if (lane == 31) wsum4[warp] = acs;
    }
    __syncthreads();
    if (tid < SEGLEN) {
        float pre = 0.f;
        #pragma unroll
        for (int w2 = 0; w2 < 4; w2++) if (w2 < warp) pre += wsum4[w2];
        su[tid] = __expf(Aneg * (acs + pre));
    }
    __syncthreads();

    float yreg[2][4][4];
    #pragma unroll
    for (int i = 0; i < 2; i++)
        #pragma unroll
        for (int j = 0; j < 4; j++)
            #pragma unroll
            for (int r = 0; r < 4; r++) yreg[i][j][r] = 0.f;

    const int m2 = (warp >> 1) * 32, n2 = (warp & 1) * 32;
    #pragma unroll
    for (int kb = 0; kb < 8; kb++) {
        const int k0 = kb*8 + ql, k4 = k0 + 4;
        uint32_t aH[2][4], aL[2][4], bHf[4][2], bLf[4][2];
        #pragma unroll
        for (int mf = 0; mf < 2; mf++) {
            int r = m2 + mf*16 + qr;
            aH[mf][0] = CH2[k0*132 + r];     aL[mf][0] = CL2[k0*132 + r];
            aH[mf][1] = CH2[k0*132 + r + 8]; aL[mf][1] = CL2[k0*132 + r + 8];
            aH[mf][2] = CH2[k4*132 + r];     aL[mf][2] = CL2[k4*132 + r];
            aH[mf][3] = CH2[k4*132 + r + 8]; aL[mf][3] = CL2[k4*132 + r + 8];
        }
        #pragma unroll
        for (int nf = 0; nf < 4; nf++) {
            int c = n2 + nf*8 + qr;
            bHf[nf][0] = HHs[k0*68 + c];  bHf[nf][1] = HHs[k4*68 + c];
            bLf[nf][0] = HLs[k0*68 + c];  bLf[nf][1] = HLs[k4*68 + c];
        }
        #pragma unroll
        for (int mf = 0; mf < 2; mf++)
            #pragma unroll
            for (int nf = 0; nf < 4; nf++)
                MMA3B(yreg[mf][nf], aH[mf], aL[mf], bHf[nf], bLf[nf]);
    }

    #pragma unroll
    for (int mf = 0; mf < 2; mf++) {
        int t = m2 + mf*16 + qr;
        float u0 = su[t], u1 = su[t + 8];
        #pragma unroll
        for (int nf = 0; nf < 4; nf++) {
            int p0 = n2 + nf*8 + ql*2;
            float* addr0 = &g_y[(rowbase + t)*DINNER + h*HEADDIM + p0];
            float* addr1 = &g_y[(rowbase + t + 8)*DINNER + h*HEADDIM + p0];
            float2 o0 = *(float2*)addr0;
            float2 o1 = *(float2*)addr1;
            o0.x += u0 * yreg[mf][nf][0];  o0.y += u0 * yreg[mf][nf][1];
            o1.x += u1 * yreg[mf][nf][2];  o1.y += u1 * yreg[mf][nf][3];
            *(float2*)addr0 = o0;
            *(float2*)addr1 = o1;
        }
    }
}

// =================================================================
// gate+norm: y = y*silu(z); rmsnorm; emit packed fp16 pairs for out_proj
// =================================================================
__global__ __launch_bounds__(256) void gate_norm_kernel(const float* __restrict__ norm_w)
{
    const int row = blockIdx.x;
    const int tid = threadIdx.x;
    const float* zrow = g_zxbcdt + (size_t)row * DPROJ;
    const float* yrow = g_y + (size_t)row * DINNER;

    float2 v[3];
    float ss = 0.f;
    #pragma unroll
    for (int i = 0; i < 3; i++) {
        int p = tid + i*256;            // pair index < 768
        float2 z2 = *(const float2*)&zrow[2*p];
        float2 y2 = *(const float2*)&yrow[2*p];
        float g0 = y2.x * (z2.x / (1.f + expf(-z2.x)));
        float g1 = y2.y * (z2.y / (1.f + expf(-z2.y)));
        v[i] = make_float2(g0, g1);
        ss += g0*g0 + g1*g1;
    }
    #pragma unroll
    for (int o = 16; o > 0; o >>= 1) ss += __shfl_xor_sync(0xffffffffu, ss, o);
    __shared__ float red[8];
    if ((tid & 31) == 0) red[tid >> 5] = ss;
    __syncthreads();
    if (tid < 32) {
        float s2 = (tid < 8) ? red[tid] : 0.f;
        #pragma unroll
        for (int o = 4; o > 0; o >>= 1) s2 += __shfl_xor_sync(0xffffffffu, s2, o);
        if (tid == 0) red[0] = s2;
    }
    __syncthreads();
    const float rstd = rsqrtf(red[0] * (1.f/1536.f) + 1e-5f);
    #pragma unroll
    for (int i = 0; i < 3; i++) {
        int p = tid + i*256;
        float2 w2 = *(const float2*)&norm_w[2*p];
        g_y16[(size_t)row * (DINNER/2) + p] =
            packh2(v[i].x * rstd * w2.x, v[i].y * rstd * w2.y);
    }
}

// =================================================================
extern "C" void kernel_launch(void* const* d_in, const int* in_sizes, int n_in,
                              void* d_out, int out_size)
{
    const float* feature   = (const float*)d_in[0];
    const float* in_proj_w = (const float*)d_in[1];
    const float* conv_w    = (const float*)d_in[2];
    const float* conv_b    = (const float*)d_in[3];
    const float* dt_bias   = (const float*)d_in[4];
    const float* A_log     = (const float*)d_in[5];
    const float* Dvec      = (const float*)d_in[6];
    const float* norm_w    = (const float*)d_in[7];
    const float* out_projw = (const float*)d_in[8];
    const float* gate1     = (const float*)d_in[9];
    float* out = (float*)d_out;

    float *zx;
    uint32_t *f16, *iw16, *ow16, *y16;
    cudaGetSymbolAddress((void**)&zx,   g_zxbcdt);
    cudaGetSymbolAddress((void**)&f16,  g_feat16);
    cudaGetSymbolAddress((void**)&iw16, g_ipw16);
    cudaGetSymbolAddress((void**)&ow16, g_opw16);
    cudaGetSymbolAddress((void**)&y16,  g_y16);

    cudaFuncSetAttribute(chunk_fused_kernel,
        cudaFuncAttributeMaxDynamicSharedMemorySize, K1_SMEM_U32 * 4);
    cudaFuncSetAttribute(inter_kernel,
        cudaFuncAttributeMaxDynamicSharedMemorySize, K3_SMEM_U32 * 4);

    dim3 blk(256);

    // operand conversions (fp32 -> packed fp16)
    tofp16_kernel<<<(ROWS*DMODEL/2)/256, blk>>>(feature, f16);
    tofp16_kernel<<<(DPROJ*DMODEL/2)/256, blk>>>(in_proj_w, iw16);
    tofp16_kernel<<<(DMODEL*DINNER/2)/256, blk>>>(out_projw, ow16);

    // in_proj (fp16 tensor cores, ldmatrix)
    gemm_fp16<<<dim3((DPROJ + 127)/128, ROWS/128), blk>>>(
        f16, iw16, zx, ROWS, DPROJ, DMODEL/2, nullptr);

    conv_silu_kernel<<<(int)(((long)ROWS * CONVDIM) / 256), blk>>>(conv_w, conv_b);
    dt_kernel<<<(ROWS * NHEADS) / 256, blk>>>(dt_bias);

    chunk_fused_kernel<<<BATCH * NHEADS * NSEG, blk, K1_SMEM_U32 * 4>>>(A_log, Dvec);
    combine_kernel<<<BATCH * NHEADS, blk>>>(A_log);
    inter_kernel<<<BATCH * NHEADS * NSEG, blk, K3_SMEM_U32 * 4>>>(A_log);

    gate_norm_kernel<<<ROWS, blk>>>(norm_w);

    // out_proj (fp16 tensor cores, ldmatrix)
    gemm_fp16<<<dim3(DMODEL/128, ROWS/128), blk>>>(
        y16, ow16, out, ROWS, DMODEL, DINNER/2, gate1);
}

// round 12
// speedup vs baseline: 1.5812x; 1.0443x over previous
#include <cuda_runtime.h>
#include <cuda_fp16.h>
#include <math.h>
#include <stdint.h>

#define BATCH   4
#define LSEQ    2048
#define ROWS    (BATCH*LSEQ)      // 8192
#define DMODEL  768
#define DINNER  1536
#define NHEADS  24
#define HEADDIM 64
#define DSTATE  128
#define CONVDIM 1792
#define DPROJ   3352

#define NSEG    16
#define SEGLEN  (LSEQ/NSEG)       // 128
#define STATESZ (HEADDIM*DSTATE)  // 8192

// -------- scratch (device globals; no allocation allowed) --------
__device__ float g_zxbcdt[(size_t)ROWS * DPROJ];
__device__ float g_xBC[(size_t)ROWS * CONVDIM];
__device__ float g_dt[ROWS * NHEADS];
__device__ float g_y[(size_t)ROWS * DINNER];
__device__ float g_states[(size_t)BATCH*NHEADS*NSEG*STATESZ];
__device__ float g_hstart[(size_t)BATCH*NHEADS*NSEG*STATESZ];
// fp16 packed-pair operands for projection GEMMs
__device__ uint32_t g_feat16[(size_t)ROWS*DMODEL/2];
__device__ uint32_t g_ipw16[(size_t)DPROJ*DMODEL/2];
__device__ uint32_t g_opw16[(size_t)DMODEL*DINNER/2];
__device__ uint32_t g_y16[(size_t)ROWS*DINNER/2];

// =================================================================
// helpers
// =================================================================
__device__ __forceinline__ uint32_t packbf2(float f0, float f1) {
    uint32_t r;
    asm("cvt.rn.bf16x2.f32 %0, %1, %2;" : "=r"(r) : "f"(f1), "f"(f0));
    return r;
}
__device__ __forceinline__ void bsplit2(float f0, float f1, uint32_t& H, uint32_t& L) {
    H = packbf2(f0, f1);
    float h0 = __uint_as_float(H << 16);
    float h1 = __uint_as_float(H & 0xffff0000u);
    L = packbf2(f0 - h0, f1 - h1);
}
__device__ __forceinline__ uint32_t packh2(float f0, float f1) {
    __half2 h = __float22half2_rn(make_float2(f0, f1));
    return *(uint32_t*)&h;
}
// unpack half (idx 0 = low, 1 = high) of bf16x2 word to float
__device__ __forceinline__ float ubf(uint32_t w, int hi) {
    return __uint_as_float(hi ? (w & 0xffff0000u) : (w << 16));
}

#define CPA16P(dst, src, valid) \
    asm volatile("cp.async.cg.shared.global [%0], [%1], 16, %2;\n" \
                 :: "r"(dst), "l"(src), "r"((valid) ? 16 : 0))
#define CPA_COMMIT() asm volatile("cp.async.commit_group;\n" ::: "memory")
#define CPA_WAIT0()  asm volatile("cp.async.wait_group 0;\n" ::: "memory")

#define MMA_BF16(d, a, b) \
    asm volatile("mma.sync.aligned.m16n8k16.row.col.f32.bf16.bf16.f32 " \
                 "{%0,%1,%2,%3},{%4,%5,%6,%7},{%8,%9},{%0,%1,%2,%3};\n" \
                 : "+f"((d)[0]), "+f"((d)[1]), "+f"((d)[2]), "+f"((d)[3]) \
                 : "r"((a)[0]), "r"((a)[1]), "r"((a)[2]), "r"((a)[3]), \
                   "r"((b)[0]), "r"((b)[1]))
#define MMA_F16(d, a, b) \
    asm volatile("mma.sync.aligned.m16n8k16.row.col.f32.f16.f16.f32 " \
                 "{%0,%1,%2,%3},{%4,%5,%6,%7},{%8,%9},{%0,%1,%2,%3};\n" \
                 : "+f"((d)[0]), "+f"((d)[1]), "+f"((d)[2]), "+f"((d)[3]) \
                 : "r"((a)[0]), "r"((a)[1]), "r"((a)[2]), "r"((a)[3]), \
                   "r"((b)[0]), "r"((b)[1]))
#define MMA3B(d, aH, aL, bH, bL) do { \
    MMA_BF16(d, aL, bH); \
    MMA_BF16(d, aH, bL); \
    MMA_BF16(d, aH, bH); } while (0)

#define LDSM_X4(r0, r1, r2, r3, a) \
    asm volatile("ldmatrix.sync.aligned.m8n8.x4.shared.b16 {%0,%1,%2,%3}, [%4];" \
                 : "=r"(r0), "=r"(r1), "=r"(r2), "=r"(r3) : "r"(a))

#define TSTRIDE 68   // words per tile row in chunk/inter kernels

// =================================================================
// fp32 -> packed fp16 pair conversion
// =================================================================
__global__ __launch_bounds__(256) void tofp16_kernel(
    const float* __restrict__ src, uint32_t* __restrict__ dst)
{
    const int idx = blockIdx.x * 256 + threadIdx.x;
    float2 v = ((const float2*)src)[idx];
    dst[idx] = packh2(v.x, v.y);
}

// =================================================================
// fp16 tensor-core GEMM (NT) — R11 version (passing)
// =================================================================
__global__ __launch_bounds__(256) void gemm_fp16(
    const uint32_t* __restrict__ A16, const uint32_t* __restrict__ B16,
    float* __restrict__ C, int M, int N, int Kp,
    const float* __restrict__ gate)
{
    __shared__ uint32_t As[2][128][20];
    __shared__ uint32_t Bs[2][128][20];

    const int tid  = threadIdx.x;
    const int lane = tid & 31;
    const int warp = tid >> 5;
    const int wm   = warp >> 2;
    const int wn   = warp & 3;
    const int m0   = blockIdx.y * 128;
    const int n0   = blockIdx.x * 128;
    const int qr   = lane >> 2;
    const int ql   = lane & 3;

    const uint32_t* csrc[4];
    int crow[4], cg[4];
    bool cbt[4], cval[4];
    #pragma unroll
    for (int q = 0; q < 4; q++) {
        int e = tid + q * 256;
        bool isB = e >= 512;
        int r = (e & 511) >> 2;
        int g = (e & 3) * 4;
        cbt[q] = isB; crow[q] = r; cg[q] = g;
        int grow = isB ? min(n0 + r, N - 1) : (m0 + r);
        cval[q] = isB ? ((n0 + r) < N) : true;
        csrc[q] = (isB ? B16 : A16) + (size_t)grow * Kp + g;
    }

    const int a_row = wm * 64 + (lane & 15);
    const int a_kp  = (lane >> 4) << 2;
    const int b_row = wn * 32 + ((lane >> 4) << 3) + (lane & 7);
    const int b_kp  = ((lane >> 3) & 1) << 2;

    float acc[4][4][4];
    #pragma unroll
    for (int i = 0; i < 4; i++)
        #pragma unroll
        for (int j = 0; j < 4; j++)
            #pragma unroll
            for (int r = 0; r < 4; r++) acc[i][j][r] = 0.f;

    const int KT = Kp / 16;

    #define GF_FILL(kt, s)                                                       \
    {                                                                            \
        const size_t ko = (size_t)(kt) * 16;                                     \
        _Pragma("unroll")                                                        \
        for (int q = 0; q < 4; q++) {                                            \
            uint32_t d = (uint32_t)__cvta_generic_to_shared(                     \
                cbt[q] ? &Bs[s][crow[q]][cg[q]] : &As[s][crow[q]][cg[q]]);       \
            CPA16P(d, csrc[q] + ko, cval[q]);                                    \
        }                                                                        \
        CPA_COMMIT();                                                            \
    }

    GF_FILL(0, 0);

    for (int kt = 0; kt < KT; kt++) {
        const int st = kt & 1;
        CPA_WAIT0();
        __syncthreads();

        if (kt + 1 < KT) GF_FILL(kt + 1, st ^ 1);

        #pragma unroll
        for (int kb = 0; kb < 2; kb++) {
            const int kp0 = kb * 8;
            uint32_t a[4][4], b[4][2];
            #pragma unroll
            for (int mf = 0; mf < 4; mf++) {
                uint32_t ad = (uint32_t)__cvta_generic_to_shared(
                    &As[st][a_row + mf * 16][kp0 + a_kp]);
                LDSM_X4(a[mf][0], a[mf][1], a[mf][2], a[mf][3], ad);
            }
            #pragma unroll
            for (int nf2 = 0; nf2 < 2; nf2++) {
                uint32_t bd = (uint32_t)__cvta_generic_to_shared(
                    &Bs[st][b_row + nf2 * 16][kp0 + b_kp]);
                LDSM_X4(b[2*nf2][0], b[2*nf2][1], b[2*nf2+1][0], b[2*nf2+1][1], bd);
            }
            #pragma unroll
            for (int mf = 0; mf < 4; mf++)
                #pragma unroll
                for (int nf = 0; nf < 4; nf++)
                    MMA_F16(acc[mf][nf], a[mf], b[nf]);
        }
    }
    #undef GF_FILL

    float scale = 1.f;
    if (gate) { float g = *gate; scale = 1.f / (1.f + expf(-g)); }

    #pragma unroll
    for (int mf = 0; mf < 4; mf++) {
        const int r = m0 + wm * 64 + mf * 16 + qr;
        #pragma unroll
        for (int nf = 0; nf < 4; nf++) {
            const int c = n0 + wn * 32 + nf * 8 + ql * 2;
            if (c < N) {
                float2 v0 = make_float2(acc[mf][nf][0] * scale, acc[mf][nf][1] * scale);
                float2 v1 = make_float2(acc[mf][nf][2] * scale, acc[mf][nf][3] * scale);
                *(float2*)&C[(size_t)r * N + c]       = v0;
                *(float2*)&C[(size_t)(r + 8) * N + c] = v1;
            }
        }
    }
}

// =================================================================
// Causal depthwise conv1d (width 4) + bias + SiLU on xBC slice
// =================================================================
__global__ __launch_bounds__(256) void conv_silu_kernel(
    const float* __restrict__ conv_w, const float* __restrict__ conv_b)
{
    const long idx = (long)blockIdx.x * 256 + threadIdx.x;
    const int  c   = (int)(idx % CONVDIM);
    const long row = idx / CONVDIM;
    const int  l   = (int)(row % LSEQ);

    float acc = conv_b[c];
    const float w0 = conv_w[c*4+0], w1 = conv_w[c*4+1];
    const float w2 = conv_w[c*4+2], w3 = conv_w[c*4+3];
    const float* base = g_zxbcdt + (size_t)row * DPROJ + DINNER + c;
    if (l >= 3) acc = fmaf(base[-3*DPROJ], w0, acc);
    if (l >= 2) acc = fmaf(base[-2*DPROJ], w1, acc);
    if (l >= 1) acc = fmaf(base[-1*DPROJ], w2, acc);
    acc = fmaf(base[0], w3, acc);
    g_xBC[idx] = acc / (1.f + expf(-acc));
}

// =================================================================
// dt = softplus(dt_raw + dt_bias)
// =================================================================
__global__ __launch_bounds__(256) void dt_kernel(const float* __restrict__ dt_bias)
{
    const int idx = blockIdx.x * 256 + threadIdx.x;
    const int h   = idx % NHEADS;
    const int row = idx / NHEADS;
    float v  = g_zxbcdt[(size_t)row * DPROJ + (DINNER + CONVDIM) + h] + dt_bias[h];
    float sp = (v > 20.f) ? v : log1pf(expf(v));
    g_dt[idx] = sp;
}

// =================================================================
// K1: fused per-chunk kernel — [row][kpair] tiles + ldmatrix frags.
//   CH/CL [128][68]: C (rows t, kp staten) -> later M~ (rows t, kp s)
//   BH/BL [128][68]: B (rows t, kp staten) -> later (w*B) (rows n, kp s)
//   XH/XL [64][68] : x (rows p, kp s)
// =================================================================
#define K1_SMEM_U32 43908
#define K3_SMEM_U32 26244

__global__ __launch_bounds__(256) void chunk_fused_kernel(
    const float* __restrict__ A_log, const float* __restrict__ Dvec)
{
    extern __shared__ uint32_t smu[];
    uint32_t* CHs = smu;
    uint32_t* CLs = smu + 8704;
    uint32_t* BHs = smu + 17408;
    uint32_t* BLs = smu + 26112;
    uint32_t* XHs = smu + 34816;
    uint32_t* XLs = smu + 39168;
    float*    sa  = (float*)(smu + 43520);
    float*    sdt = (float*)(smu + 43648);
    float*    sw  = (float*)(smu + 43776);
    float*    wsum4 = (float*)(smu + 43904);

    const int blk = blockIdx.x;
    const int bh = blk >> 4, seg = blk & (NSEG - 1);
    const int b = bh / NHEADS, h = bh % NHEADS;
    const int tid = threadIdx.x, lane = tid & 31, warp = tid >> 5;
    const int qr = lane >> 2, ql = lane & 3;
    const size_t rowbase = (size_t)b * LSEQ + seg * SEGLEN;

    // ldmatrix lane addressing (shared by all 3 GEMMs)
    const int lrow = lane & 15;
    const int lkp  = (lane >> 4) << 2;
    const int brow = ((lane >> 4) << 3) + (lane & 7);
    const int bkp  = ((lane >> 3) & 1) << 2;

    // ---- fill C,B tiles rows t, kp = staten pair ----
    #pragma unroll
    for (int i = 0; i < 32; i++) {
        int e = tid + i * 256;           // < 8192
        int np = e & 63, t = e >> 6;
        const float* src = g_xBC + (rowbase + t) * CONVDIM + DINNER + 2*np;
        float2 bv = *(const float2*)src;
        float2 cv = *(const float2*)(src + DSTATE);
        uint32_t hh, ll;
        bsplit2(bv.x, bv.y, hh, ll); BHs[t*TSTRIDE + np] = hh; BLs[t*TSTRIDE + np] = ll;
        bsplit2(cv.x, cv.y, hh, ll); CHs[t*TSTRIDE + np] = hh; CLs[t*TSTRIDE + np] = ll;
    }
    // ---- fill X rows p, kp = s pair ----
    #pragma unroll
    for (int i = 0; i < 16; i++) {
        int e = tid + i * 256;           // < 4096
        int p = e & 63, sp = e >> 6;
        const float* s0 = g_xBC + (rowbase + 2*sp) * CONVDIM + h * HEADDIM + p;
        uint32_t hh, ll;
        bsplit2(s0[0], s0[CONVDIM], hh, ll);
        XHs[p*TSTRIDE + sp] = hh; XLs[p*TSTRIDE + sp] = ll;
    }

    // ---- dt cumsum / weights ----
    const float Aneg = -expf(A_log[h]);
    float vdt = 0.f, acs = 0.f;
    if (tid < SEGLEN) {
        vdt = g_dt[(rowbase + tid) * NHEADS + h];
        acs = vdt;
        #pragma unroll
        for (int o = 1; o < 32; o <<= 1) {
            float nv = __shfl_up_sync(0xffffffffu, acs, o);
            if (lane >= o) acs += nv;
        }
        if (lane == 31) wsum4[warp] = acs;
    }
    __syncthreads();
    if (tid < SEGLEN) {
        float tot = wsum4[0] + wsum4[1] + wsum4[2] + wsum4[3];
        float pre = 0.f;
        #pragma unroll
        for (int w2 = 0; w2 < 4; w2++) if (w2 < warp) pre += wsum4[w2];
        float a = acs + pre;
        sa[tid]  = a;
        sdt[tid] = vdt;
        sw[tid]  = vdt * __expf(Aneg * (tot - a));
    }
    __syncthreads();

    // ================= GEMM1: M = C @ B^T (k = staten) =================
    float mreg[4][4][4];
    #pragma unroll
    for (int i = 0; i < 4; i++)
        #pragma unroll
        for (int j = 0; j < 4; j++)
            #pragma unroll
            for (int r = 0; r < 4; r++) mreg[i][j][r] = 0.f;

    const int m1 = (warp >> 2) * 64, n1 = (warp & 3) * 32;
    #pragma unroll
    for (int kb = 0; kb < 8; kb++) {
        const int kp0 = kb * 8;
        uint32_t aH[4][4], aL[4][4], bH[4][2], bL[4][2];
        #pragma unroll
        for (int mf = 0; mf < 4; mf++) {
            const int r = (m1 + lrow + mf*16) * TSTRIDE + kp0 + lkp;
            uint32_t ad = (uint32_t)__cvta_generic_to_shared(&CHs[r]);
            LDSM_X4(aH[mf][0], aH[mf][1], aH[mf][2], aH[mf][3], ad);
            ad = (uint32_t)__cvta_generic_to_shared(&CLs[r]);
            LDSM_X4(aL[mf][0], aL[mf][1], aL[mf][2], aL[mf][3], ad);
        }
        #pragma unroll
        for (int nf2 = 0; nf2 < 2; nf2++) {
            const int r = (n1 + brow + nf2*16) * TSTRIDE + kp0 + bkp;
            uint32_t bd = (uint32_t)__cvta_generic_to_shared(&BHs[r]);
            LDSM_X4(bH[2*nf2][0], bH[2*nf2][1], bH[2*nf2+1][0], bH[2*nf2+1][1], bd);
            bd = (uint32_t)__cvta_generic_to_shared(&BLs[r]);
            LDSM_X4(bL[2*nf2][0], bL[2*nf2][1], bL[2*nf2+1][0], bL[2*nf2+1][1], bd);
        }
        #pragma unroll
        for (int mf = 0; mf < 4; mf++)
            #pragma unroll
            for (int nf = 0; nf < 4; nf++)
                MMA3B(mreg[mf][nf], aH[mf], aL[mf], bH[nf], bL[nf]);
    }
    __syncthreads();   // all warps done reading CHs/BHs

    // ---- mask + store M~ rows t, kp = s pair ----
    #pragma unroll
    for (int mf = 0; mf < 4; mf++) {
        int tA = m1 + mf*16 + qr, tB = tA + 8;
        float aA = sa[tA], aB = sa[tB];
        #pragma unroll
        for (int nf = 0; nf < 4; nf++) {
            int sp = (n1 >> 1) + nf*4 + ql;
            int s0 = 2*sp, s1 = s0 + 1;
            float as0 = sa[s0], as1 = sa[s1];
            float d0 = sdt[s0], d1 = sdt[s1];
            float v00 = (s0 <= tA) ? mreg[mf][nf][0] * __expf(Aneg*(aA-as0)) * d0 : 0.f;
            float v01 = (s1 <= tA) ? mreg[mf][nf][1] * __expf(Aneg*(aA-as1)) * d1 : 0.f;
            float v10 = (s0 <= tB) ? mreg[mf][nf][2] * __expf(Aneg*(aB-as0)) * d0 : 0.f;
            float v11 = (s1 <= tB) ? mreg[mf][nf][3] * __expf(Aneg*(aB-as1)) * d1 : 0.f;
            uint32_t hh, ll;
            bsplit2(v00, v01, hh, ll); CHs[tA*TSTRIDE + sp] = hh; CLs[tA*TSTRIDE + sp] = ll;
            bsplit2(v10, v11, hh, ll); CHs[tB*TSTRIDE + sp] = hh; CLs[tB*TSTRIDE + sp] = ll;
        }
    }

    // ---- refill BH/BL as (w*B) rows n, kp = s pair ----
    #pragma unroll
    for (int i = 0; i < 32; i++) {
        int e = tid + i * 256;           // < 8192
        int n = e & 127, sp = e >> 7;
        const float* s0 = g_xBC + (rowbase + 2*sp) * CONVDIM + DINNER + n;
        float f0 = s0[0] * sw[2*sp];
        float f1 = s0[CONVDIM] * sw[2*sp + 1];
        uint32_t hh, ll;
        bsplit2(f0, f1, hh, ll);
        BHs[n*TSTRIDE + sp] = hh; BLs[n*TSTRIDE + sp] = ll;
    }
    __syncthreads();

    // ================= GEMM2: Y = M~ @ X  (k = s) =================
    {
        float yreg[2][4][4];
        #pragma unroll
        for (int i = 0; i < 2; i++)
            #pragma unroll
            for (int j = 0; j < 4; j++)
                #pragma unroll
                for (int r = 0; r < 4; r++) yreg[i][j][r] = 0.f;

        const int m2 = (warp >> 1) * 32, n2 = (warp & 1) * 32;
        #pragma unroll
        for (int kb = 0; kb < 8; kb++) {
            const int kp0 = kb * 8;
            uint32_t aH[2][4], aL[2][4], bH[4][2], bL[4][2];
            #pragma unroll
            for (int mf = 0; mf < 2; mf++) {
                const int r = (m2 + lrow + mf*16) * TSTRIDE + kp0 + lkp;
                uint32_t ad = (uint32_t)__cvta_generic_to_shared(&CHs[r]);
                LDSM_X4(aH[mf][0], aH[mf][1], aH[mf][2], aH[mf][3], ad);
                ad = (uint32_t)__cvta_generic_to_shared(&CLs[r]);
                LDSM_X4(aL[mf][0], aL[mf][1], aL[mf][2], aL[mf][3], ad);
            }
            #pragma unroll
            for (int nf2 = 0; nf2 < 2; nf2++) {
                const int r = (n2 + brow + nf2*16) * TSTRIDE + kp0 + bkp;
                uint32_t bd = (uint32_t)__cvta_generic_to_shared(&XHs[r]);
                LDSM_X4(bH[2*nf2][0], bH[2*nf2][1], bH[2*nf2+1][0], bH[2*nf2+1][1], bd);
                bd = (uint32_t)__cvta_generic_to_shared(&XLs[r]);
                LDSM_X4(bL[2*nf2][0], bL[2*nf2][1], bL[2*nf2+1][0], bL[2*nf2+1][1], bd);
            }
            #pragma unroll
            for (int mf = 0; mf < 2; mf++)
                #pragma unroll
                for (int nf = 0; nf < 4; nf++)
                    MMA3B(yreg[mf][nf], aH[mf], aL[mf], bH[nf], bL[nf]);
        }

        const float Dh = Dvec[h];
        #pragma unroll
        for (int mf = 0; mf < 2; mf++) {
            int t = m2 + mf*16 + qr;
            const int sp0 = t >> 1, hi0 = t & 1;
            const int sp1 = (t + 8) >> 1, hi1 = t & 1;   // (t+8) parity == t parity
            #pragma unroll
            for (int nf = 0; nf < 4; nf++) {
                int p0 = n2 + nf*8 + ql*2;
                float x00 = ubf(XHs[p0*TSTRIDE + sp0], hi0) + ubf(XLs[p0*TSTRIDE + sp0], hi0);
                float x01 = ubf(XHs[(p0+1)*TSTRIDE + sp0], hi0) + ubf(XLs[(p0+1)*TSTRIDE + sp0], hi0);
                float x10 = ubf(XHs[p0*TSTRIDE + sp1], hi1) + ubf(XLs[p0*TSTRIDE + sp1], hi1);
                float x11 = ubf(XHs[(p0+1)*TSTRIDE + sp1], hi1) + ubf(XLs[(p0+1)*TSTRIDE + sp1], hi1);
                float2 o;
                o.x = yreg[mf][nf][0] + Dh * x00;
                o.y = yreg[mf][nf][1] + Dh * x01;
                *(float2*)&g_y[(rowbase + t)*DINNER + h*HEADDIM + p0] = o;
                o.x = yreg[mf][nf][2] + Dh * x10;
                o.y = yreg[mf][nf][3] + Dh * x11;
                *(float2*)&g_y[(rowbase + t + 8)*DINNER + h*HEADDIM + p0] = o;
            }
        }
    }

    // ================= GEMM3: S = X^T @ (w*B)  (k = s) =================
    {
        float sreg[2][4][4];
        #pragma unroll
        for (int i = 0; i < 2; i++)
            #pragma unroll
            for (int j = 0; j < 4; j++)
                #pragma unroll
                for (int r = 0; r < 4; r++) sreg[i][j][r] = 0.f;

        const int m3 = (warp >> 2) * 32, n3 = (warp & 3) * 32;
        #pragma unroll
        for (int kb = 0; kb < 8; kb++) {
            const int kp0 = kb * 8;
            uint32_t aH[2][4], aL[2][4], bH[4][2], bL[4][2];
            #pragma unroll
            for (int mf = 0; mf < 2; mf++) {
                const int r = (m3 + lrow + mf*16) * TSTRIDE + kp0 + lkp;
                uint32_t ad = (uint32_t)__cvta_generic_to_shared(&XHs[r]);
                LDSM_X4(aH[mf][0], aH[mf][1], aH[mf][2], aH[mf][3], ad);
                ad = (uint32_t)__cvta_generic_to_shared(&XLs[r]);
                LDSM_X4(aL[mf][0], aL[mf][1], aL[mf][2], aL[mf][3], ad);
            }
            #pragma unroll
            for (int nf2 = 0; nf2 < 2; nf2++) {
                const int r = (n3 + brow + nf2*16) * TSTRIDE + kp0 + bkp;
                uint32_t bd = (uint32_t)__cvta_generic_to_shared(&BHs[r]);
                LDSM_X4(bH[2*nf2][0], bH[2*nf2][1], bH[2*nf2+1][0], bH[2*nf2+1][1], bd);
                bd = (uint32_t)__cvta_generic_to_shared(&BLs[r]);
                LDSM_X4(bL[2*nf2][0], bL[2*nf2][1], bL[2*nf2+1][0], bL[2*nf2+1][1], bd);
            }
            #pragma unroll
            for (int mf = 0; mf < 2; mf++)
                #pragma unroll
                for (int nf = 0; nf < 4; nf++)
                    MMA3B(sreg[mf][nf], aH[mf], aL[mf], bH[nf], bL[nf]);
        }

        const size_t sbase = ((size_t)bh * NSEG + seg) * STATESZ;
        #pragma unroll
        for (int mf = 0; mf < 2; mf++) {
            int p = m3 + mf*16 + qr;
            #pragma unroll
            for (int nf = 0; nf < 4; nf++) {
                int n0 = n3 + nf*8 + ql*2;
                float2 o0 = make_float2(sreg[mf][nf][0], sreg[mf][nf][1]);
                float2 o1 = make_float2(sreg[mf][nf][2], sreg[mf][nf][3]);
                *(float2*)&g_states[sbase + (size_t)p * DSTATE + n0]       = o0;
                *(float2*)&g_states[sbase + (size_t)(p + 8) * DSTATE + n0] = o1;
            }
        }
    }
}

// =================================================================
// K2: combine
// =================================================================
__global__ __launch_bounds__(256) void combine_kernel(const float* __restrict__ A_log)
{
    const int bh = blockIdx.x;
    const int b = bh / NHEADS, h = bh % NHEADS;
    const int tid = threadIdx.x;

    __shared__ float part[256];
    __shared__ float Esh[NSEG];

    {
        const int k = tid >> 4, i = tid & 15;
        float s = 0.f;
        const size_t base = ((size_t)b*LSEQ + k*SEGLEN + i*8)*NHEADS + h;
        #pragma unroll
        for (int t = 0; t < 8; t++) s += g_dt[base + (size_t)t*NHEADS];
        part[tid] = s;
    }
    __syncthreads();
    if (tid < NSEG) {
        float s = 0.f;
        #pragma unroll
        for (int i = 0; i < 16; i++) s += part[tid*16 + i];
        Esh[tid] = expf(-expf(A_log[h]) * s);
    }
    __syncthreads();

    float hs[32];
    #pragma unroll
    for (int k2 = 0; k2 < 32; k2++) hs[k2] = 0.f;

    for (int seg = 0; seg < NSEG; seg++) {
        const size_t base = ((size_t)bh*NSEG + seg)*STATESZ;
        const float E = Esh[seg];
        #pragma unroll
        for (int k2 = 0; k2 < 32; k2++) {
            const size_t e = base + k2*256 + tid;
            g_hstart[e] = hs[k2];
            hs[k2] = fmaf(hs[k2], E, g_states[e]);
        }
    }
}

// =================================================================
// K3: inter-chunk — [row][kpair] + ldmatrix. 105KB smem (2 CTA/SM).
//   CH2/CL2 [128][68] rows t, kp staten; HH/HL [64][68] rows p, kp staten
// =================================================================
__global__ __launch_bounds__(256) void inter_kernel(const float* __restrict__ A_log)
{
    extern __shared__ uint32_t smu[];
    uint32_t* CH2 = smu;
    uint32_t* CL2 = smu + 8704;
    uint32_t* HHs = smu + 17408;
    uint32_t* HLs = smu + 21760;
    float*    su  = (float*)(smu + 26112);
    float*    wsum4 = (float*)(smu + 26240);

    const int blk = blockIdx.x;
    const int bh = blk >> 4, seg = blk & (NSEG - 1);
    const int b = bh / NHEADS, h = bh % NHEADS;
    const int tid = threadIdx.x, lane = tid & 31, warp = tid >> 5;
    const int qr = lane >> 2, ql = lane & 3;
    const size_t rowbase = (size_t)b * LSEQ + seg * SEGLEN;
    const size_t hbase = ((size_t)bh * NSEG + seg) * STATESZ;

    const int lrow = lane & 15;
    const int lkp  = (lane >> 4) << 2;
    const int brow = ((lane >> 4) << 3) + (lane & 7);
    const int bkp  = ((lane >> 3) & 1) << 2;

    // C tile rows t
    #pragma unroll
    for (int i = 0; i < 32; i++) {
        int e = tid + i * 256;           // < 8192
        int np = e & 63, t = e >> 6;
        const float* src = g_xBC + (rowbase + t) * CONVDIM + DINNER + DSTATE + 2*np;
        float2 cv = *(const float2*)src;
        uint32_t hh, ll;
        bsplit2(cv.x, cv.y, hh, ll);
        CH2[t*TSTRIDE + np] = hh; CL2[t*TSTRIDE + np] = ll;
    }
    // H tile rows p
    #pragma unroll
    for (int i = 0; i < 16; i++) {
        int e = tid + i * 256;           // < 4096
        int np = e & 63, p = e >> 6;
        const float* src = g_hstart + hbase + (size_t)p * DSTATE + 2*np;
        float2 hv = *(const float2*)src;
        uint32_t hh, ll;
        bsplit2(hv.x, hv.y, hh, ll);
        HHs[p*TSTRIDE + np] = hh; HLs[p*TSTRIDE + np] = ll;
    }

    // cumsum -> u_t = exp(A * a_t)
    const float Aneg = -expf(A_log[h]);
    float vdt = 0.f, acs = 0.f;
    if (tid < SEGLEN) {
        vdt = g_dt[(rowbase + tid) * NHEADS + h];
        acs = vdt;
        #pragma unroll
        for (int o = 1; o < 32; o <<= 1) {
            float nv = __shfl_up_sync(0xffffffffu, acs, o);
            if (lane >= o) acs += nv;
        }
        if (lane == 31) wsum4[warp] = acs;
    }
    __syncthreads();
    if (tid < SEGLEN) {
        float pre = 0.f;
        #pragma unroll
        for (int w2 = 0; w2 < 4; w2++) if (w2 < warp) pre += wsum4[w2];
        su[tid] = __expf(Aneg * (acs + pre));
    }
    __syncthreads();

    float yreg[2][4][4];
    #pragma unroll
    for (int i = 0; i < 2; i++)
        #pragma unroll
        for (int j = 0; j < 4; j++)
            #pragma unroll
            for (int r = 0; r < 4; r++) yreg[i][j][r] = 0.f;

    const int m2 = (warp >> 1) * 32, n2 = (warp & 1) * 32;
    #pragma unroll
    for (int kb = 0; kb < 8; kb++) {
        const int kp0 = kb * 8;
        uint32_t aH[2][4], aL[2][4], bH[4][2], bL[4][2];
        #pragma unroll
        for (int mf = 0; mf < 2; mf++) {
            const int r = (m2 + lrow + mf*16) * TSTRIDE + kp0 + lkp;
            uint32_t ad = (uint32_t)__cvta_generic_to_shared(&CH2[r]);
            LDSM_X4(aH[mf][0], aH[mf][1], aH[mf][2], aH[mf][3], ad);
            ad = (uint32_t)__cvta_generic_to_shared(&CL2[r]);
            LDSM_X4(aL[mf][0], aL[mf][1], aL[mf][2], aL[mf][3], ad);
        }
        #pragma unroll
        for (int nf2 = 0; nf2 < 2; nf2++) {
            const int r = (n2 + brow + nf2*16) * TSTRIDE + kp0 + bkp;
            uint32_t bd = (uint32_t)__cvta_generic_to_shared(&HHs[r]);
            LDSM_X4(bH[2*nf2][0], bH[2*nf2][1], bH[2*nf2+1][0], bH[2*nf2+1][1], bd);
            bd = (uint32_t)__cvta_generic_to_shared(&HLs[r]);
            LDSM_X4(bL[2*nf2][0], bL[2*nf2][1], bL[2*nf2+1][0], bL[2*nf2+1][1], bd);
        }
        #pragma unroll
        for (int mf = 0; mf < 2; mf++)
            #pragma unroll
            for (int nf = 0; nf < 4; nf++)
                MMA3B(yreg[mf][nf], aH[mf], aL[mf], bH[nf], bL[nf]);
    }

    #pragma unroll
    for (int mf = 0; mf < 2; mf++) {
        int t = m2 + mf*16 + qr;
        float u0 = su[t], u1 = su[t + 8];
        #pragma unroll
        for (int nf = 0; nf < 4; nf++) {
            int p0 = n2 + nf*8 + ql*2;
            float* addr0 = &g_y[(rowbase + t)*DINNER + h*HEADDIM + p0];
            float* addr1 = &g_y[(rowbase + t + 8)*DINNER + h*HEADDIM + p0];
            float2 o0 = *(float2*)addr0;
            float2 o1 = *(float2*)addr1;
            o0.x += u0 * yreg[mf][nf][0];  o0.y += u0 * yreg[mf][nf][1];
            o1.x += u1 * yreg[mf][nf][2];  o1.y += u1 * yreg[mf][nf][3];
            *(float2*)addr0 = o0;
            *(float2*)addr1 = o1;
        }
    }
}

// =================================================================
// gate+norm: y = y*silu(z); rmsnorm; emit packed fp16 pairs
// =================================================================
__global__ __launch_bounds__(256) void gate_norm_kernel(const float* __restrict__ norm_w)
{
    const int row = blockIdx.x;
    const int tid = threadIdx.x;
    const float* zrow = g_zxbcdt + (size_t)row * DPROJ;
    const float* yrow = g_y + (size_t)row * DINNER;

    float2 v[3];
    float ss = 0.f;
    #pragma unroll
    for (int i = 0; i < 3; i++) {
        int p = tid + i*256;
        float2 z2 = *(const float2*)&zrow[2*p];
        float2 y2 = *(const float2*)&yrow[2*p];
        float g0 = y2.x * (z2.x / (1.f + expf(-z2.x)));
        float g1 = y2.y * (z2.y / (1.f + expf(-z2.y)));
        v[i] = make_float2(g0, g1);
        ss += g0*g0 + g1*g1;
    }
    #pragma unroll
    for (int o = 16; o > 0; o >>= 1) ss += __shfl_xor_sync(0xffffffffu, ss, o);
    __shared__ float red[8];
    if ((tid & 31) == 0) red[tid >> 5] = ss;
    __syncthreads();
    if (tid < 32) {
        float s2 = (tid < 8) ? red[tid] : 0.f;
        #pragma unroll
        for (int o = 4; o > 0; o >>= 1) s2 += __shfl_xor_sync(0xffffffffu, s2, o);
        if (tid == 0) red[0] = s2;
    }
    __syncthreads();
    const float rstd = rsqrtf(red[0] * (1.f/1536.f) + 1e-5f);
    #pragma unroll
    for (int i = 0; i < 3; i++) {
        int p = tid + i*256;
        float2 w2 = *(const float2*)&norm_w[2*p];
        g_y16[(size_t)row * (DINNER/2) + p] =
            packh2(v[i].x * rstd * w2.x, v[i].y * rstd * w2.y);
    }
}

// =================================================================
extern "C" void kernel_launch(void* const* d_in, const int* in_sizes, int n_in,
                              void* d_out, int out_size)
{
    const float* feature   = (const float*)d_in[0];
    const float* in_proj_w = (const float*)d_in[1];
    const float* conv_w    = (const float*)d_in[2];
    const float* conv_b    = (const float*)d_in[3];
    const float* dt_bias   = (const float*)d_in[4];
    const float* A_log     = (const float*)d_in[5];
    const float* Dvec      = (const float*)d_in[6];
    const float* norm_w    = (const float*)d_in[7];
    const float* out_projw = (const float*)d_in[8];
    const float* gate1     = (const float*)d_in[9];
    float* out = (float*)d_out;

    float *zx;
    uint32_t *f16, *iw16, *ow16, *y16;
    cudaGetSymbolAddress((void**)&zx,   g_zxbcdt);
    cudaGetSymbolAddress((void**)&f16,  g_feat16);
    cudaGetSymbolAddress((void**)&iw16, g_ipw16);
    cudaGetSymbolAddress((void**)&ow16, g_opw16);
    cudaGetSymbolAddress((void**)&y16,  g_y16);

    cudaFuncSetAttribute(chunk_fused_kernel,
        cudaFuncAttributeMaxDynamicSharedMemorySize, K1_SMEM_U32 * 4);
    cudaFuncSetAttribute(inter_kernel,
        cudaFuncAttributeMaxDynamicSharedMemorySize, K3_SMEM_U32 * 4);

    dim3 blk(256);

    tofp16_kernel<<<(ROWS*DMODEL/2)/256, blk>>>(feature, f16);
    tofp16_kernel<<<(DPROJ*DMODEL/2)/256, blk>>>(in_proj_w, iw16);
    tofp16_kernel<<<(DMODEL*DINNER/2)/256, blk>>>(out_projw, ow16);

    gemm_fp16<<<dim3((DPROJ + 127)/128, ROWS/128), blk>>>(
        f16, iw16, zx, ROWS, DPROJ, DMODEL/2, nullptr);

    conv_silu_kernel<<<(int)(((long)ROWS * CONVDIM) / 256), blk>>>(conv_w, conv_b);
    dt_kernel<<<(ROWS * NHEADS) / 256, blk>>>(dt_bias);

    chunk_fused_kernel<<<BATCH * NHEADS * NSEG, blk, K1_SMEM_U32 * 4>>>(A_log, Dvec);
    combine_kernel<<<BATCH * NHEADS, blk>>>(A_log);
    inter_kernel<<<BATCH * NHEADS * NSEG, blk, K3_SMEM_U32 * 4>>>(A_log);

    gate_norm_kernel<<<ROWS, blk>>>(norm_w);

    gemm_fp16<<<dim3(DMODEL/128, ROWS/128), blk>>>(
        y16, ow16, out, ROWS, DMODEL, DINNER/2, gate1);
}

// round 13
// speedup vs baseline: 1.7382x; 1.0993x over previous
#include <cuda_runtime.h>
#include <cuda_fp16.h>
#include <math.h>
#include <stdint.h>

#define BATCH   4
#define LSEQ    2048
#define ROWS    (BATCH*LSEQ)      // 8192
#define DMODEL  768
#define DINNER  1536
#define NHEADS  24
#define HEADDIM 64
#define DSTATE  128
#define CONVDIM 1792
#define DPROJ   3352

#define NSEG    16
#define SEGLEN  (LSEQ/NSEG)       // 128
#define STATESZ (HEADDIM*DSTATE)  // 8192
#define STATEPAIRS (STATESZ/2)    // 4096

// -------- scratch (device globals; no allocation allowed) --------
__device__ float g_zxbcdt[(size_t)ROWS * DPROJ];
__device__ float g_xBC[(size_t)ROWS * CONVDIM];
__device__ float g_dt[ROWS * NHEADS];
__device__ float g_y[(size_t)ROWS * DINNER];
__device__ float g_states[(size_t)BATCH*NHEADS*NSEG*STATESZ];
// pre-split bf16 hi/lo of xBC's B|C columns: [row][128 pairs]
__device__ uint32_t g_bcH[(size_t)ROWS*128];
__device__ uint32_t g_bcL[(size_t)ROWS*128];
// pre-split bf16 hi/lo segment start states: [(bh*NSEG+seg)][4096 pairs]
__device__ uint32_t g_hsH[(size_t)BATCH*NHEADS*NSEG*STATEPAIRS];
__device__ uint32_t g_hsL[(size_t)BATCH*NHEADS*NSEG*STATEPAIRS];
// fp16 packed-pair operands for projection GEMMs
__device__ uint32_t g_feat16[(size_t)ROWS*DMODEL/2];
__device__ uint32_t g_ipw16[(size_t)DPROJ*DMODEL/2];
__device__ uint32_t g_opw16[(size_t)DMODEL*DINNER/2];
__device__ uint32_t g_y16[(size_t)ROWS*DINNER/2];

// =================================================================
// helpers
// =================================================================
__device__ __forceinline__ uint32_t packbf2(float f0, float f1) {
    uint32_t r;
    asm("cvt.rn.bf16x2.f32 %0, %1, %2;" : "=r"(r) : "f"(f1), "f"(f0));
    return r;
}
__device__ __forceinline__ void bsplit2(float f0, float f1, uint32_t& H, uint32_t& L) {
    H = packbf2(f0, f1);
    float h0 = __uint_as_float(H << 16);
    float h1 = __uint_as_float(H & 0xffff0000u);
    L = packbf2(f0 - h0, f1 - h1);
}
__device__ __forceinline__ uint32_t packh2(float f0, float f1) {
    __half2 h = __float22half2_rn(make_float2(f0, f1));
    return *(uint32_t*)&h;
}
__device__ __forceinline__ float ubf(uint32_t w, int hi) {
    return __uint_as_float(hi ? (w & 0xffff0000u) : (w << 16));
}

#define CPA16(dst, src) \
    asm volatile("cp.async.cg.shared.global [%0], [%1], 16;\n" \
                 :: "r"(dst), "l"(src))
#define CPA16P(dst, src, valid) \
    asm volatile("cp.async.cg.shared.global [%0], [%1], 16, %2;\n" \
                 :: "r"(dst), "l"(src), "r"((valid) ? 16 : 0))
#define CPA_COMMIT() asm volatile("cp.async.commit_group;\n" ::: "memory")
#define CPA_WAIT0()  asm volatile("cp.async.wait_group 0;\n" ::: "memory")

#define MMA_BF16(d, a, b) \
    asm volatile("mma.sync.aligned.m16n8k16.row.col.f32.bf16.bf16.f32 " \
                 "{%0,%1,%2,%3},{%4,%5,%6,%7},{%8,%9},{%0,%1,%2,%3};\n" \
                 : "+f"((d)[0]), "+f"((d)[1]), "+f"((d)[2]), "+f"((d)[3]) \
                 : "r"((a)[0]), "r"((a)[1]), "r"((a)[2]), "r"((a)[3]), \
                   "r"((b)[0]), "r"((b)[1]))
#define MMA_F16(d, a, b) \
    asm volatile("mma.sync.aligned.m16n8k16.row.col.f32.f16.f16.f32 " \
                 "{%0,%1,%2,%3},{%4,%5,%6,%7},{%8,%9},{%0,%1,%2,%3};\n" \
                 : "+f"((d)[0]), "+f"((d)[1]), "+f"((d)[2]), "+f"((d)[3]) \
                 : "r"((a)[0]), "r"((a)[1]), "r"((a)[2]), "r"((a)[3]), \
                   "r"((b)[0]), "r"((b)[1]))
#define MMA3B(d, aH, aL, bH, bL) do { \
    MMA_BF16(d, aL, bH); \
    MMA_BF16(d, aH, bL); \
    MMA_BF16(d, aH, bH); } while (0)

#define LDSM_X4(r0, r1, r2, r3, a) \
    asm volatile("ldmatrix.sync.aligned.m8n8.x4.shared.b16 {%0,%1,%2,%3}, [%4];" \
                 : "=r"(r0), "=r"(r1), "=r"(r2), "=r"(r3) : "r"(a))

#define TSTRIDE 68   // words per tile row in chunk/inter kernels

// =================================================================
// fp32 -> packed fp16 pair conversion
// =================================================================
__global__ __launch_bounds__(256) void tofp16_kernel(
    const float* __restrict__ src, uint32_t* __restrict__ dst)
{
    const int idx = blockIdx.x * 256 + threadIdx.x;
    float2 v = ((const float2*)src)[idx];
    dst[idx] = packh2(v.x, v.y);
}

// =================================================================
// bc_split: pre-split bf16 hi/lo of the B|C columns of g_xBC
// =================================================================
__global__ __launch_bounds__(256) void bc_split_kernel()
{
    const int idx = blockIdx.x * 256 + threadIdx.x;   // < ROWS*128
    const int row = idx >> 7, np = idx & 127;
    float2 v = *(const float2*)&g_xBC[(size_t)row * CONVDIM + DINNER + 2*np];
    uint32_t hh, ll;
    bsplit2(v.x, v.y, hh, ll);
    g_bcH[idx] = hh;  g_bcL[idx] = ll;
}

// =================================================================
// fp16 tensor-core GEMM (NT) — R11/R12 passing version
// =================================================================
__global__ __launch_bounds__(256) void gemm_fp16(
    const uint32_t* __restrict__ A16, const uint32_t* __restrict__ B16,
    float* __restrict__ C, int M, int N, int Kp,
    const float* __restrict__ gate)
{
    __shared__ uint32_t As[2][128][20];
    __shared__ uint32_t Bs[2][128][20];

    const int tid  = threadIdx.x;
    const int lane = tid & 31;
    const int warp = tid >> 5;
    const int wm   = warp >> 2;
    const int wn   = warp & 3;
    const int m0   = blockIdx.y * 128;
    const int n0   = blockIdx.x * 128;
    const int qr   = lane >> 2;
    const int ql   = lane & 3;

    const uint32_t* csrc[4];
    int crow[4], cg[4];
    bool cbt[4], cval[4];
    #pragma unroll
    for (int q = 0; q < 4; q++) {
        int e = tid + q * 256;
        bool isB = e >= 512;
        int r = (e & 511) >> 2;
        int g = (e & 3) * 4;
        cbt[q] = isB; crow[q] = r; cg[q] = g;
        int grow = isB ? min(n0 + r, N - 1) : (m0 + r);
        cval[q] = isB ? ((n0 + r) < N) : true;
        csrc[q] = (isB ? B16 : A16) + (size_t)grow * Kp + g;
    }

    const int a_row = wm * 64 + (lane & 15);
    const int a_kp  = (lane >> 4) << 2;
    const int b_row = wn * 32 + ((lane >> 4) << 3) + (lane & 7);
    const int b_kp  = ((lane >> 3) & 1) << 2;

    float acc[4][4][4];
    #pragma unroll
    for (int i = 0; i < 4; i++)
        #pragma unroll
        for (int j = 0; j < 4; j++)
            #pragma unroll
            for (int r = 0; r < 4; r++) acc[i][j][r] = 0.f;

    const int KT = Kp / 16;

    #define GF_FILL(kt, s)                                                       \
    {                                                                            \
        const size_t ko = (size_t)(kt) * 16;                                     \
        _Pragma("unroll")                                                        \
        for (int q = 0; q < 4; q++) {                                            \
            uint32_t d = (uint32_t)__cvta_generic_to_shared(                     \
                cbt[q] ? &Bs[s][crow[q]][cg[q]] : &As[s][crow[q]][cg[q]]);       \
            CPA16P(d, csrc[q] + ko, cval[q]);                                    \
        }                                                                        \
        CPA_COMMIT();                                                            \
    }

    GF_FILL(0, 0);

    for (int kt = 0; kt < KT; kt++) {
        const int st = kt & 1;
        CPA_WAIT0();
        __syncthreads();

        if (kt + 1 < KT) GF_FILL(kt + 1, st ^ 1);

        #pragma unroll
        for (int kb = 0; kb < 2; kb++) {
            const int kp0 = kb * 8;
            uint32_t a[4][4], b[4][2];
            #pragma unroll
            for (int mf = 0; mf < 4; mf++) {
                uint32_t ad = (uint32_t)__cvta_generic_to_shared(
                    &As[st][a_row + mf * 16][kp0 + a_kp]);
                LDSM_X4(a[mf][0], a[mf][1], a[mf][2], a[mf][3], ad);
            }
            #pragma unroll
            for (int nf2 = 0; nf2 < 2; nf2++) {
                uint32_t bd = (uint32_t)__cvta_generic_to_shared(
                    &Bs[st][b_row + nf2 * 16][kp0 + b_kp]);
                LDSM_X4(b[2*nf2][0], b[2*nf2][1], b[2*nf2+1][0], b[2*nf2+1][1], bd);
            }
            #pragma unroll
            for (int mf = 0; mf < 4; mf++)
                #pragma unroll
                for (int nf = 0; nf < 4; nf++)
                    MMA_F16(acc[mf][nf], a[mf], b[nf]);
        }
    }
    #undef GF_FILL

    float scale = 1.f;
    if (gate) { float g = *gate; scale = 1.f / (1.f + expf(-g)); }

    #pragma unroll
    for (int mf = 0; mf < 4; mf++) {
        const int r = m0 + wm * 64 + mf * 16 + qr;
        #pragma unroll
        for (int nf = 0; nf < 4; nf++) {
            const int c = n0 + wn * 32 + nf * 8 + ql * 2;
            if (c < N) {
                float2 v0 = make_float2(acc[mf][nf][0] * scale, acc[mf][nf][1] * scale);
                float2 v1 = make_float2(acc[mf][nf][2] * scale, acc[mf][nf][3] * scale);
                *(float2*)&C[(size_t)r * N + c]       = v0;
                *(float2*)&C[(size_t)(r + 8) * N + c] = v1;
            }
        }
    }
}

// =================================================================
// Causal depthwise conv1d (width 4) + bias + SiLU on xBC slice
// =================================================================
__global__ __launch_bounds__(256) void conv_silu_kernel(
    const float* __restrict__ conv_w, const float* __restrict__ conv_b)
{
    const long idx = (long)blockIdx.x * 256 + threadIdx.x;
    const int  c   = (int)(idx % CONVDIM);
    const long row = idx / CONVDIM;
    const int  l   = (int)(row % LSEQ);

    float acc = conv_b[c];
    const float w0 = conv_w[c*4+0], w1 = conv_w[c*4+1];
    const float w2 = conv_w[c*4+2], w3 = conv_w[c*4+3];
    const float* base = g_zxbcdt + (size_t)row * DPROJ + DINNER + c;
    if (l >= 3) acc = fmaf(base[-3*DPROJ], w0, acc);
    if (l >= 2) acc = fmaf(base[-2*DPROJ], w1, acc);
    if (l >= 1) acc = fmaf(base[-1*DPROJ], w2, acc);
    acc = fmaf(base[0], w3, acc);
    g_xBC[idx] = acc / (1.f + expf(-acc));
}

// =================================================================
// dt = softplus(dt_raw + dt_bias)
// =================================================================
__global__ __launch_bounds__(256) void dt_kernel(const float* __restrict__ dt_bias)
{
    const int idx = blockIdx.x * 256 + threadIdx.x;
    const int h   = idx % NHEADS;
    const int row = idx / NHEADS;
    float v  = g_zxbcdt[(size_t)row * DPROJ + (DINNER + CONVDIM) + h] + dt_bias[h];
    float sp = (v > 20.f) ? v : log1pf(expf(v));
    g_dt[idx] = sp;
}

// =================================================================
// K1: fused per-chunk kernel — 512 threads, cp.async B/C fills.
// =================================================================
#define K1_SMEM_U32 43908
#define K3_SMEM_U32 26244

__global__ __launch_bounds__(512) void chunk_fused_kernel(
    const float* __restrict__ A_log, const float* __restrict__ Dvec)
{
    extern __shared__ uint32_t smu[];
    uint32_t* CHs = smu;
    uint32_t* CLs = smu + 8704;
    uint32_t* BHs = smu + 17408;
    uint32_t* BLs = smu + 26112;
    uint32_t* XHs = smu + 34816;
    uint32_t* XLs = smu + 39168;
    float*    sa  = (float*)(smu + 43520);
    float*    sdt = (float*)(smu + 43648);
    float*    sw  = (float*)(smu + 43776);
    float*    wsum4 = (float*)(smu + 43904);

    const int blk = blockIdx.x;
    const int bh = blk >> 4, seg = blk & (NSEG - 1);
    const int b = bh / NHEADS, h = bh % NHEADS;
    const int tid = threadIdx.x, lane = tid & 31, warp = tid >> 5;
    const int qr = lane >> 2, ql = lane & 3;
    const size_t rowbase = (size_t)b * LSEQ + seg * SEGLEN;

    const int lrow = lane & 15;
    const int lkp  = (lane >> 4) << 2;
    const int brow = ((lane >> 4) << 3) + (lane & 7);
    const int bkp  = ((lane >> 3) & 1) << 2;

    // ---- cp.async fill: B tile (words 0..63 of bc row), C tile (64..127) ----
    #pragma unroll
    for (int i = 0; i < 4; i++) {
        int e = tid + i * 512;           // < 2048 chunks
        int t = e >> 4, g = (e & 15) * 4;
        const size_t srcw = (rowbase + t) * 128 + g;
        CPA16((uint32_t)__cvta_generic_to_shared(&BHs[t*TSTRIDE + g]), g_bcH + srcw);
        CPA16((uint32_t)__cvta_generic_to_shared(&BLs[t*TSTRIDE + g]), g_bcL + srcw);
        CPA16((uint32_t)__cvta_generic_to_shared(&CHs[t*TSTRIDE + g]), g_bcH + srcw + 64);
        CPA16((uint32_t)__cvta_generic_to_shared(&CLs[t*TSTRIDE + g]), g_bcL + srcw + 64);
    }
    CPA_COMMIT();

    // ---- fill X rows p, kp = s pair (local split) ----
    #pragma unroll
    for (int i = 0; i < 8; i++) {
        int e = tid + i * 512;           // < 4096
        int p = e & 63, sp = e >> 6;
        const float* s0 = g_xBC + (rowbase + 2*sp) * CONVDIM + h * HEADDIM + p;
        uint32_t hh, ll;
        bsplit2(s0[0], s0[CONVDIM], hh, ll);
        XHs[p*TSTRIDE + sp] = hh; XLs[p*TSTRIDE + sp] = ll;
    }

    // ---- dt cumsum / weights ----
    const float Aneg = -expf(A_log[h]);
    float vdt = 0.f, acs = 0.f;
    if (tid < SEGLEN) {
        vdt = g_dt[(rowbase + tid) * NHEADS + h];
        acs = vdt;
        #pragma unroll
        for (int o = 1; o < 32; o <<= 1) {
            float nv = __shfl_up_sync(0xffffffffu, acs, o);
            if (lane >= o) acs += nv;
        }
        if (lane == 31) wsum4[warp] = acs;
    }
    __syncthreads();
    if (tid < SEGLEN) {
        float tot = wsum4[0] + wsum4[1] + wsum4[2] + wsum4[3];
        float pre = 0.f;
        #pragma unroll
        for (int w2 = 0; w2 < 4; w2++) if (w2 < warp) pre += wsum4[w2];
        float a = acs + pre;
        sa[tid]  = a;
        sdt[tid] = vdt;
        sw[tid]  = vdt * __expf(Aneg * (tot - a));
    }
    CPA_WAIT0();
    __syncthreads();

    // ================= GEMM1: M = C @ B^T (16 warps, 32x32 tiles) ==========
    float mreg[2][4][4];
    #pragma unroll
    for (int i = 0; i < 2; i++)
        #pragma unroll
        for (int j = 0; j < 4; j++)
            #pragma unroll
            for (int r = 0; r < 4; r++) mreg[i][j][r] = 0.f;

    const int m1 = (warp >> 2) * 32, n1 = (warp & 3) * 32;
    #pragma unroll
    for (int kb = 0; kb < 8; kb++) {
        const int kp0 = kb * 8;
        uint32_t aH[2][4], aL[2][4], bH[4][2], bL[4][2];
        #pragma unroll
        for (int mf = 0; mf < 2; mf++) {
            const int r = (m1 + lrow + mf*16) * TSTRIDE + kp0 + lkp;
            uint32_t ad = (uint32_t)__cvta_generic_to_shared(&CHs[r]);
            LDSM_X4(aH[mf][0], aH[mf][1], aH[mf][2], aH[mf][3], ad);
            ad = (uint32_t)__cvta_generic_to_shared(&CLs[r]);
            LDSM_X4(aL[mf][0], aL[mf][1], aL[mf][2], aL[mf][3], ad);
        }
        #pragma unroll
        for (int nf2 = 0; nf2 < 2; nf2++) {
            const int r = (n1 + brow + nf2*16) * TSTRIDE + kp0 + bkp;
            uint32_t bd = (uint32_t)__cvta_generic_to_shared(&BHs[r]);
            LDSM_X4(bH[2*nf2][0], bH[2*nf2][1], bH[2*nf2+1][0], bH[2*nf2+1][1], bd);
            bd = (uint32_t)__cvta_generic_to_shared(&BLs[r]);
            LDSM_X4(bL[2*nf2][0], bL[2*nf2][1], bL[2*nf2+1][0], bL[2*nf2+1][1], bd);
        }
        #pragma unroll
        for (int mf = 0; mf < 2; mf++)
            #pragma unroll
            for (int nf = 0; nf < 4; nf++)
                MMA3B(mreg[mf][nf], aH[mf], aL[mf], bH[nf], bL[nf]);
    }
    __syncthreads();

    // ---- mask + store M~ rows t, kp = s pair ----
    #pragma unroll
    for (int mf = 0; mf < 2; mf++) {
        int tA = m1 + mf*16 + qr, tB = tA + 8;
        float aA = sa[tA], aB = sa[tB];
        #pragma unroll
        for (int nf = 0; nf < 4; nf++) {
            int sp = (n1 >> 1) + nf*4 + ql;
            int s0 = 2*sp, s1 = s0 + 1;
            float as0 = sa[s0], as1 = sa[s1];
            float d0 = sdt[s0], d1 = sdt[s1];
            float v00 = (s0 <= tA) ? mreg[mf][nf][0] * __expf(Aneg*(aA-as0)) * d0 : 0.f;
            float v01 = (s1 <= tA) ? mreg[mf][nf][1] * __expf(Aneg*(aA-as1)) * d1 : 0.f;
            float v10 = (s0 <= tB) ? mreg[mf][nf][2] * __expf(Aneg*(aB-as0)) * d0 : 0.f;
            float v11 = (s1 <= tB) ? mreg[mf][nf][3] * __expf(Aneg*(aB-as1)) * d1 : 0.f;
            uint32_t hh, ll;
            bsplit2(v00, v01, hh, ll); CHs[tA*TSTRIDE + sp] = hh; CLs[tA*TSTRIDE + sp] = ll;
            bsplit2(v10, v11, hh, ll); CHs[tB*TSTRIDE + sp] = hh; CLs[tB*TSTRIDE + sp] = ll;
        }
    }

    // ---- refill BH/BL as (w*B) rows n, kp = s pair ----
    #pragma unroll
    for (int i = 0; i < 16; i++) {
        int e = tid + i * 512;           // < 8192
        int n = e & 127, sp = e >> 7;
        const float* s0 = g_xBC + (rowbase + 2*sp) * CONVDIM + DINNER + n;
        float f0 = s0[0] * sw[2*sp];
        float f1 = s0[CONVDIM] * sw[2*sp + 1];
        uint32_t hh, ll;
        bsplit2(f0, f1, hh, ll);
        BHs[n*TSTRIDE + sp] = hh; BLs[n*TSTRIDE + sp] = ll;
    }
    __syncthreads();

    // ================= GEMM2: Y = M~ @ X  (16 warps, 16x32 tiles) ==========
    {
        float yreg[4][4];
        #pragma unroll
        for (int j = 0; j < 4; j++)
            #pragma unroll
            for (int r = 0; r < 4; r++) yreg[j][r] = 0.f;

        const int m2 = (warp >> 1) * 16, n2 = (warp & 1) * 32;
        #pragma unroll
        for (int kb = 0; kb < 8; kb++) {
            const int kp0 = kb * 8;
            uint32_t aH[4], aL[4], bH[4][2], bL[4][2];
            {
                const int r = (m2 + lrow) * TSTRIDE + kp0 + lkp;
                uint32_t ad = (uint32_t)__cvta_generic_to_shared(&CHs[r]);
                LDSM_X4(aH[0], aH[1], aH[2], aH[3], ad);
                ad = (uint32_t)__cvta_generic_to_shared(&CLs[r]);
                LDSM_X4(aL[0], aL[1], aL[2], aL[3], ad);
            }
            #pragma unroll
            for (int nf2 = 0; nf2 < 2; nf2++) {
                const int r = (n2 + brow + nf2*16) * TSTRIDE + kp0 + bkp;
                uint32_t bd = (uint32_t)__cvta_generic_to_shared(&XHs[r]);
                LDSM_X4(bH[2*nf2][0], bH[2*nf2][1], bH[2*nf2+1][0], bH[2*nf2+1][1], bd);
                bd = (uint32_t)__cvta_generic_to_shared(&XLs[r]);
                LDSM_X4(bL[2*nf2][0], bL[2*nf2][1], bL[2*nf2+1][0], bL[2*nf2+1][1], bd);
            }
            #pragma unroll
            for (int nf = 0; nf < 4; nf++)
                MMA3B(yreg[nf], aH, aL, bH[nf], bL[nf]);
        }

        const float Dh = Dvec[h];
        {
            int t = m2 + qr;
            const int sp0 = t >> 1, hi0 = t & 1;
            const int sp1 = (t + 8) >> 1, hi1 = t & 1;
            #pragma unroll
            for (int nf = 0; nf < 4; nf++) {
                int p0 = n2 + nf*8 + ql*2;
                float x00 = ubf(XHs[p0*TSTRIDE + sp0], hi0) + ubf(XLs[p0*TSTRIDE + sp0], hi0);
                float x01 = ubf(XHs[(p0+1)*TSTRIDE + sp0], hi0) + ubf(XLs[(p0+1)*TSTRIDE + sp0], hi0);
                float x10 = ubf(XHs[p0*TSTRIDE + sp1], hi1) + ubf(XLs[p0*TSTRIDE + sp1], hi1);
                float x11 = ubf(XHs[(p0+1)*TSTRIDE + sp1], hi1) + ubf(XLs[(p0+1)*TSTRIDE + sp1], hi1);
                float2 o;
                o.x = yreg[nf][0] + Dh * x00;
                o.y = yreg[nf][1] + Dh * x01;
                *(float2*)&g_y[(rowbase + t)*DINNER + h*HEADDIM + p0] = o;
                o.x = yreg[nf][2] + Dh * x10;
                o.y = yreg[nf][3] + Dh * x11;
                *(float2*)&g_y[(rowbase + t + 8)*DINNER + h*HEADDIM + p0] = o;
            }
        }
    }

    // ================= GEMM3: S = X^T @ (w*B)  (16 warps, 16x32) ===========
    {
        float sreg[4][4];
        #pragma unroll
        for (int j = 0; j < 4; j++)
            #pragma unroll
            for (int r = 0; r < 4; r++) sreg[j][r] = 0.f;

        const int m3 = (warp >> 2) * 16, n3 = (warp & 3) * 32;
        #pragma unroll
        for (int kb = 0; kb < 8; kb++) {
            const int kp0 = kb * 8;
            uint32_t aH[4], aL[4], bH[4][2], bL[4][2];
            {
                const int r = (m3 + lrow) * TSTRIDE + kp0 + lkp;
                uint32_t ad = (uint32_t)__cvta_generic_to_shared(&XHs[r]);
                LDSM_X4(aH[0], aH[1], aH[2], aH[3], ad);
                ad = (uint32_t)__cvta_generic_to_shared(&XLs[r]);
                LDSM_X4(aL[0], aL[1], aL[2], aL[3], ad);
            }
            #pragma unroll
            for (int nf2 = 0; nf2 < 2; nf2++) {
                const int r = (n3 + brow + nf2*16) * TSTRIDE + kp0 + bkp;
                uint32_t bd = (uint32_t)__cvta_generic_to_shared(&BHs[r]);
                LDSM_X4(bH[2*nf2][0], bH[2*nf2][1], bH[2*nf2+1][0], bH[2*nf2+1][1], bd);
                bd = (uint32_t)__cvta_generic_to_shared(&BLs[r]);
                LDSM_X4(bL[2*nf2][0], bL[2*nf2][1], bL[2*nf2+1][0], bL[2*nf2+1][1], bd);
            }
            #pragma unroll
            for (int nf = 0; nf < 4; nf++)
                MMA3B(sreg[nf], aH, aL, bH[nf], bL[nf]);
        }

        const size_t sbase = ((size_t)bh * NSEG + seg) * STATESZ;
        {
            int p = m3 + qr;
            #pragma unroll
            for (int nf = 0; nf < 4; nf++) {
                int n0 = n3 + nf*8 + ql*2;
                float2 o0 = make_float2(sreg[nf][0], sreg[nf][1]);
                float2 o1 = make_float2(sreg[nf][2], sreg[nf][3]);
                *(float2*)&g_states[sbase + (size_t)p * DSTATE + n0]       = o0;
                *(float2*)&g_states[sbase + (size_t)(p + 8) * DSTATE + n0] = o1;
            }
        }
    }
}

// =================================================================
// K2: combine — emits pre-split bf16 hi/lo hstart pairs
// =================================================================
__global__ __launch_bounds__(256) void combine_kernel(const float* __restrict__ A_log)
{
    const int bh = blockIdx.x;
    const int b = bh / NHEADS, h = bh % NHEADS;
    const int tid = threadIdx.x;

    __shared__ float part[256];
    __shared__ float Esh[NSEG];

    {
        const int k = tid >> 4, i = tid & 15;
        float s = 0.f;
        const size_t base = ((size_t)b*LSEQ + k*SEGLEN + i*8)*NHEADS + h;
        #pragma unroll
        for (int t = 0; t < 8; t++) s += g_dt[base + (size_t)t*NHEADS];
        part[tid] = s;
    }
    __syncthreads();
    if (tid < NSEG) {
        float s = 0.f;
        #pragma unroll
        for (int i = 0; i < 16; i++) s += part[tid*16 + i];
        Esh[tid] = expf(-expf(A_log[h]) * s);
    }
    __syncthreads();

    float2 hs[16];
    #pragma unroll
    for (int k2 = 0; k2 < 16; k2++) hs[k2] = make_float2(0.f, 0.f);

    for (int seg = 0; seg < NSEG; seg++) {
        const size_t pbase = ((size_t)bh*NSEG + seg)*STATEPAIRS;
        const float E = Esh[seg];
        #pragma unroll
        for (int k2 = 0; k2 < 16; k2++) {
            const size_t j = pbase + k2*256 + tid;
            uint32_t hh, ll;
            bsplit2(hs[k2].x, hs[k2].y, hh, ll);
            g_hsH[j] = hh;  g_hsL[j] = ll;
            float2 s = ((const float2*)g_states)[j];
            hs[k2].x = fmaf(hs[k2].x, E, s.x);
            hs[k2].y = fmaf(hs[k2].y, E, s.y);
        }
    }
}

// =================================================================
// K3: inter-chunk — 512 threads, cp.async fills from pre-split arrays
// =================================================================
__global__ __launch_bounds__(512) void inter_kernel(const float* __restrict__ A_log)
{
    extern __shared__ uint32_t smu[];
    uint32_t* CH2 = smu;
    uint32_t* CL2 = smu + 8704;
    uint32_t* HHs = smu + 17408;
    uint32_t* HLs = smu + 21760;
    float*    su  = (float*)(smu + 26112);
    float*    wsum4 = (float*)(smu + 26240);

    const int blk = blockIdx.x;
    const int bh = blk >> 4, seg = blk & (NSEG - 1);
    const int b = bh / NHEADS, h = bh % NHEADS;
    const int tid = threadIdx.x, lane = tid & 31, warp = tid >> 5;
    const int qr = lane >> 2, ql = lane & 3;
    const size_t rowbase = (size_t)b * LSEQ + seg * SEGLEN;
    const size_t hpb = ((size_t)bh * NSEG + seg) * STATEPAIRS;

    const int lrow = lane & 15;
    const int lkp  = (lane >> 4) << 2;
    const int brow = ((lane >> 4) << 3) + (lane & 7);
    const int bkp  = ((lane >> 3) & 1) << 2;

    // C tile (words 64..127 of bc row): 2048 chunks
    #pragma unroll
    for (int i = 0; i < 4; i++) {
        int e = tid + i * 512;
        int t = e >> 4, g = (e & 15) * 4;
        const size_t srcw = (rowbase + t) * 128 + 64 + g;
        CPA16((uint32_t)__cvta_generic_to_shared(&CH2[t*TSTRIDE + g]), g_bcH + srcw);
        CPA16((uint32_t)__cvta_generic_to_shared(&CL2[t*TSTRIDE + g]), g_bcL + srcw);
    }
    // H tile: rows p, 64 pair-words each: 1024 chunks
    #pragma unroll
    for (int i = 0; i < 2; i++) {
        int e = tid + i * 512;
        int p = e >> 4, g = (e & 15) * 4;
        const size_t srcw = hpb + (size_t)p * 64 + g;
        CPA16((uint32_t)__cvta_generic_to_shared(&HHs[p*TSTRIDE + g]), g_hsH + srcw);
        CPA16((uint32_t)__cvta_generic_to_shared(&HLs[p*TSTRIDE + g]), g_hsL + srcw);
    }
    CPA_COMMIT();

    // cumsum -> u_t = exp(A * a_t)
    const float Aneg = -expf(A_log[h]);
    float vdt = 0.f, acs = 0.f;
    if (tid < SEGLEN) {
        vdt = g_dt[(rowbase + tid) * NHEADS + h];
        acs = vdt;
        #pragma unroll
        for (int o = 1; o < 32; o <<= 1) {
            float nv = __shfl_up_sync(0xffffffffu, acs, o);
            if (lane >= o) acs += nv;
        }
        if (lane == 31) wsum4[warp] = acs;
    }
    __syncthreads();
    if (tid < SEGLEN) {
        float pre = 0.f;
        #pragma unroll
        for (int w2 = 0; w2 < 4; w2++) if (w2 < warp) pre += wsum4[w2];
        su[tid] = __expf(Aneg * (acs + pre));
    }
    CPA_WAIT0();
    __syncthreads();

    float yreg[4][4];
    #pragma unroll
    for (int j = 0; j < 4; j++)
        #pragma unroll
        for (int r = 0; r < 4; r++) yreg[j][r] = 0.f;

    const int m2 = (warp >> 1) * 16, n2 = (warp & 1) * 32;
    #pragma unroll
    for (int kb = 0; kb < 8; kb++) {
        const int kp0 = kb * 8;
        uint32_t aH[4], aL[4], bH[4][2], bL[4][2];
        {
            const int r = (m2 + lrow) * TSTRIDE + kp0 + lkp;
            uint32_t ad = (uint32_t)__cvta_generic_to_shared(&CH2[r]);
            LDSM_X4(aH[0], aH[1], aH[2], aH[3], ad);
            ad = (uint32_t)__cvta_generic_to_shared(&CL2[r]);
            LDSM_X4(aL[0], aL[1], aL[2], aL[3], ad);
        }
        #pragma unroll
        for (int nf2 = 0; nf2 < 2; nf2++) {
            const int r = (n2 + brow + nf2*16) * TSTRIDE + kp0 + bkp;
            uint32_t bd = (uint32_t)__cvta_generic_to_shared(&HHs[r]);
            LDSM_X4(bH[2*nf2][0], bH[2*nf2][1], bH[2*nf2+1][0], bH[2*nf2+1][1], bd);
            bd = (uint32_t)__cvta_generic_to_shared(&HLs[r]);
            LDSM_X4(bL[2*nf2][0], bL[2*nf2][1], bL[2*nf2+1][0], bL[2*nf2+1][1], bd);
        }
        #pragma unroll
        for (int nf = 0; nf < 4; nf++)
            MMA3B(yreg[nf], aH, aL, bH[nf], bL[nf]);
    }

    {
        int t = m2 + qr;
        float u0 = su[t], u1 = su[t + 8];
        #pragma unroll
        for (int nf = 0; nf < 4; nf++) {
            int p0 = n2 + nf*8 + ql*2;
            float* addr0 = &g_y[(rowbase + t)*DINNER + h*HEADDIM + p0];
            float* addr1 = &g_y[(rowbase + t + 8)*DINNER + h*HEADDIM + p0];
            float2 o0 = *(float2*)addr0;
            float2 o1 = *(float2*)addr1;
            o0.x += u0 * yreg[nf][0];  o0.y += u0 * yreg[nf][1];
            o1.x += u1 * yreg[nf][2];  o1.y += u1 * yreg[nf][3];
            *(float2*)addr0 = o0;
            *(float2*)addr1 = o1;
        }
    }
}

// =================================================================
// gate+norm: y = y*silu(z); rmsnorm; emit packed fp16 pairs
// =================================================================
__global__ __launch_bounds__(256) void gate_norm_kernel(const float* __restrict__ norm_w)
{
    const int row = blockIdx.x;
    const int tid = threadIdx.x;
    const float* zrow = g_zxbcdt + (size_t)row * DPROJ;
    const float* yrow = g_y + (size_t)row * DINNER;

    float2 v[3];
    float ss = 0.f;
    #pragma unroll
    for (int i = 0; i < 3; i++) {
        int p = tid + i*256;
        float2 z2 = *(const float2*)&zrow[2*p];
        float2 y2 = *(const float2*)&yrow[2*p];
        float g0 = y2.x * (z2.x / (1.f + expf(-z2.x)));
        float g1 = y2.y * (z2.y / (1.f + expf(-z2.y)));
        v[i] = make_float2(g0, g1);
        ss += g0*g0 + g1*g1;
    }
    #pragma unroll
    for (int o = 16; o > 0; o >>= 1) ss += __shfl_xor_sync(0xffffffffu, ss, o);
    __shared__ float red[8];
    if ((tid & 31) == 0) red[tid >> 5] = ss;
    __syncthreads();
    if (tid < 32) {
        float s2 = (tid < 8) ? red[tid] : 0.f;
        #pragma unroll
        for (int o = 4; o > 0; o >>= 1) s2 += __shfl_xor_sync(0xffffffffu, s2, o);
        if (tid == 0) red[0] = s2;
    }
    __syncthreads();
    const float rstd = rsqrtf(red[0] * (1.f/1536.f) + 1e-5f);
    #pragma unroll
    for (int i = 0; i < 3; i++) {
        int p = tid + i*256;
        float2 w2 = *(const float2*)&norm_w[2*p];
        g_y16[(size_t)row * (DINNER/2) + p] =
            packh2(v[i].x * rstd * w2.x, v[i].y * rstd * w2.y);
    }
}

// =================================================================
extern "C" void kernel_launch(void* const* d_in, const int* in_sizes, int n_in,
                              void* d_out, int out_size)
{
    const float* feature   = (const float*)d_in[0];
    const float* in_proj_w = (const float*)d_in[1];
    const float* conv_w    = (const float*)d_in[2];
    const float* conv_b    = (const float*)d_in[3];
    const float* dt_bias   = (const float*)d_in[4];
    const float* A_log     = (const float*)d_in[5];
    const float* Dvec      = (const float*)d_in[6];
    const float* norm_w    = (const float*)d_in[7];
    const float* out_projw = (const float*)d_in[8];
    const float* gate1     = (const float*)d_in[9];
    float* out = (float*)d_out;

    float *zx;
    uint32_t *f16, *iw16, *ow16, *y16;
    cudaGetSymbolAddress((void**)&zx,   g_zxbcdt);
    cudaGetSymbolAddress((void**)&f16,  g_feat16);
    cudaGetSymbolAddress((void**)&iw16, g_ipw16);
    cudaGetSymbolAddress((void**)&ow16, g_opw16);
    cudaGetSymbolAddress((void**)&y16,  g_y16);

    cudaFuncSetAttribute(chunk_fused_kernel,
        cudaFuncAttributeMaxDynamicSharedMemorySize, K1_SMEM_U32 * 4);
    cudaFuncSetAttribute(inter_kernel,
        cudaFuncAttributeMaxDynamicSharedMemorySize, K3_SMEM_U32 * 4);

    dim3 blk(256);
    dim3 blk5(512);

    tofp16_kernel<<<(ROWS*DMODEL/2)/256, blk>>>(feature, f16);
    tofp16_kernel<<<(DPROJ*DMODEL/2)/256, blk>>>(in_proj_w, iw16);
    tofp16_kernel<<<(DMODEL*DINNER/2)/256, blk>>>(out_projw, ow16);

    gemm_fp16<<<dim3((DPROJ + 127)/128, ROWS/128), blk>>>(
        f16, iw16, zx, ROWS, DPROJ, DMODEL/2, nullptr);

    conv_silu_kernel<<<(int)(((long)ROWS * CONVDIM) / 256), blk>>>(conv_w, conv_b);
    bc_split_kernel<<<(ROWS*128)/256, blk>>>();
    dt_kernel<<<(ROWS * NHEADS) / 256, blk>>>(dt_bias);

    chunk_fused_kernel<<<BATCH * NHEADS * NSEG, blk5, K1_SMEM_U32 * 4>>>(A_log, Dvec);
    combine_kernel<<<BATCH * NHEADS, blk>>>(A_log);
    inter_kernel<<<BATCH * NHEADS * NSEG, blk5, K3_SMEM_U32 * 4>>>(A_log);

    gate_norm_kernel<<<ROWS, blk>>>(norm_w);

    gemm_fp16<<<dim3(DMODEL/128, ROWS/128), blk>>>(
        y16, ow16, out, ROWS, DMODEL, DINNER/2, gate1);
}

// round 14
// speedup vs baseline: 1.8209x; 1.0476x over previous
#include <cuda_runtime.h>
#include <cuda_fp16.h>
#include <math.h>
#include <stdint.h>

#define BATCH   4
#define LSEQ    2048
#define ROWS    (BATCH*LSEQ)      // 8192
#define DMODEL  768
#define DINNER  1536
#define NHEADS  24
#define HEADDIM 64
#define DSTATE  128
#define CONVDIM 1792
#define DPROJ   3352

#define NSEG    16
#define SEGLEN  (LSEQ/NSEG)       // 128
#define STATESZ (HEADDIM*DSTATE)  // 8192
#define STATEPAIRS (STATESZ/2)    // 4096

// -------- scratch (device globals; no allocation allowed) --------
__device__ float g_zxbcdt[(size_t)ROWS * DPROJ];
__device__ float g_xBC[(size_t)ROWS * CONVDIM];
__device__ float g_dt[ROWS * NHEADS];
__device__ float g_y[(size_t)ROWS * DINNER];
__device__ float g_states[(size_t)BATCH*NHEADS*NSEG*STATESZ];
// pre-split bf16 hi/lo of xBC's B|C columns: [row][128 pairs]
__device__ uint32_t g_bcH[(size_t)ROWS*128];
__device__ uint32_t g_bcL[(size_t)ROWS*128];
// pre-split bf16 hi/lo segment start states
__device__ uint32_t g_hsH[(size_t)BATCH*NHEADS*NSEG*STATEPAIRS];
__device__ uint32_t g_hsL[(size_t)BATCH*NHEADS*NSEG*STATEPAIRS];
// fp16 packed-pair operands for projection GEMMs
__device__ uint32_t g_feat16[(size_t)ROWS*DMODEL/2];
__device__ uint32_t g_ipw16[(size_t)DPROJ*DMODEL/2];
__device__ uint32_t g_opw16[(size_t)DMODEL*DINNER/2];
__device__ uint32_t g_y16[(size_t)ROWS*DINNER/2];

// =================================================================
// helpers
// =================================================================
__device__ __forceinline__ uint32_t packbf2(float f0, float f1) {
    uint32_t r;
    asm("cvt.rn.bf16x2.f32 %0, %1, %2;" : "=r"(r) : "f"(f1), "f"(f0));
    return r;
}
__device__ __forceinline__ void bsplit2(float f0, float f1, uint32_t& H, uint32_t& L) {
    H = packbf2(f0, f1);
    float h0 = __uint_as_float(H << 16);
    float h1 = __uint_as_float(H & 0xffff0000u);
    L = packbf2(f0 - h0, f1 - h1);
}
__device__ __forceinline__ uint32_t packh2(float f0, float f1) {
    __half2 h = __float22half2_rn(make_float2(f0, f1));
    return *(uint32_t*)&h;
}
__device__ __forceinline__ float ubf(uint32_t w, int hi) {
    return __uint_as_float(hi ? (w & 0xffff0000u) : (w << 16));
}

#define CPA16(dst, src) \
    asm volatile("cp.async.cg.shared.global [%0], [%1], 16;\n" \
                 :: "r"(dst), "l"(src))
#define CPA16P(dst, src, valid) \
    asm volatile("cp.async.cg.shared.global [%0], [%1], 16, %2;\n" \
                 :: "r"(dst), "l"(src), "r"((valid) ? 16 : 0))
#define CPA_COMMIT() asm volatile("cp.async.commit_group;\n" ::: "memory")
#define CPA_WAIT0()  asm volatile("cp.async.wait_group 0;\n" ::: "memory")
#define CPA_WAIT1()  asm volatile("cp.async.wait_group 1;\n" ::: "memory")

#define MMA_BF16(d, a, b) \
    asm volatile("mma.sync.aligned.m16n8k16.row.col.f32.bf16.bf16.f32 " \
                 "{%0,%1,%2,%3},{%4,%5,%6,%7},{%8,%9},{%0,%1,%2,%3};\n" \
                 : "+f"((d)[0]), "+f"((d)[1]), "+f"((d)[2]), "+f"((d)[3]) \
                 : "r"((a)[0]), "r"((a)[1]), "r"((a)[2]), "r"((a)[3]), \
                   "r"((b)[0]), "r"((b)[1]))
#define MMA_F16(d, a, b) \
    asm volatile("mma.sync.aligned.m16n8k16.row.col.f32.f16.f16.f32 " \
                 "{%0,%1,%2,%3},{%4,%5,%6,%7},{%8,%9},{%0,%1,%2,%3};\n" \
                 : "+f"((d)[0]), "+f"((d)[1]), "+f"((d)[2]), "+f"((d)[3]) \
                 : "r"((a)[0]), "r"((a)[1]), "r"((a)[2]), "r"((a)[3]), \
                   "r"((b)[0]), "r"((b)[1]))
#define MMA3B(d, aH, aL, bH, bL) do { \
    MMA_BF16(d, aL, bH); \
    MMA_BF16(d, aH, bL); \
    MMA_BF16(d, aH, bH); } while (0)

#define LDSM_X4(r0, r1, r2, r3, a) \
    asm volatile("ldmatrix.sync.aligned.m8n8.x4.shared.b16 {%0,%1,%2,%3}, [%4];" \
                 : "=r"(r0), "=r"(r1), "=r"(r2), "=r"(r3) : "r"(a))

#define TSTRIDE 68   // words per tile row in chunk/inter kernels

// =================================================================
// fp32 -> packed fp16 pair conversion
// =================================================================
__global__ __launch_bounds__(256) void tofp16_kernel(
    const float* __restrict__ src, uint32_t* __restrict__ dst)
{
    const int idx = blockIdx.x * 256 + threadIdx.x;
    float2 v = ((const float2*)src)[idx];
    dst[idx] = packh2(v.x, v.y);
}

// =================================================================
// fp16 tensor-core GEMM (NT): 3-stage cp.async pipeline, dynamic smem
// layout: stage s at gsm + s*5120; A tile [128][20], B at +2560
// =================================================================
#define GP_STAGE 5120
#define GP_SMEM  (3 * GP_STAGE * 4)   // 61440 bytes

__global__ __launch_bounds__(256) void gemm_fp16(
    const uint32_t* __restrict__ A16, const uint32_t* __restrict__ B16,
    float* __restrict__ C, int M, int N, int Kp,
    const float* __restrict__ gate)
{
    extern __shared__ uint32_t gsm[];

    const int tid  = threadIdx.x;
    const int lane = tid & 31;
    const int warp = tid >> 5;
    const int wm   = warp >> 2;
    const int wn   = warp & 3;
    const int m0   = blockIdx.y * 128;
    const int n0   = blockIdx.x * 128;
    const int qr   = lane >> 2;
    const int ql   = lane & 3;

    const uint32_t* csrc[4];
    int coff[4];
    bool cval[4];
    #pragma unroll
    for (int q = 0; q < 4; q++) {
        int e = tid + q * 256;
        bool isB = e >= 512;
        int r = (e & 511) >> 2;
        int g = (e & 3) * 4;
        coff[q] = (isB ? 2560 : 0) + r * 20 + g;
        int grow = isB ? min(n0 + r, N - 1) : (m0 + r);
        cval[q] = isB ? ((n0 + r) < N) : true;
        csrc[q] = (isB ? B16 : A16) + (size_t)grow * Kp + g;
    }

    const int a_row = wm * 64 + (lane & 15);
    const int a_kp  = (lane >> 4) << 2;
    const int b_row = wn * 32 + ((lane >> 4) << 3) + (lane & 7);
    const int b_kp  = ((lane >> 3) & 1) << 2;

    float acc[4][4][4];
    #pragma unroll
    for (int i = 0; i < 4; i++)
        #pragma unroll
        for (int j = 0; j < 4; j++)
            #pragma unroll
            for (int r = 0; r < 4; r++) acc[i][j][r] = 0.f;

    const int KT = Kp / 16;

    #define GF_FILL(kt, s)                                                       \
    {                                                                            \
        const size_t ko = (size_t)(kt) * 16;                                     \
        uint32_t* stg = gsm + (s) * GP_STAGE;                                    \
        _Pragma("unroll")                                                        \
        for (int q = 0; q < 4; q++) {                                            \
            uint32_t d = (uint32_t)__cvta_generic_to_shared(&stg[coff[q]]);      \
            CPA16P(d, csrc[q] + ko, cval[q]);                                    \
        }                                                                        \
        CPA_COMMIT();                                                            \
    }

    GF_FILL(0, 0);
    if (KT > 1) GF_FILL(1, 1);

    int st = 0;
    for (int kt = 0; kt < KT; kt++) {
        if (kt + 1 < KT) { CPA_WAIT1(); } else { CPA_WAIT0(); }
        __syncthreads();

        if (kt + 2 < KT) {
            int ns = st + 2; if (ns >= 3) ns -= 3;
            GF_FILL(kt + 2, ns);
        }

        const uint32_t* As_ = gsm + st * GP_STAGE;
        const uint32_t* Bs_ = As_ + 2560;

        #pragma unroll
        for (int kb = 0; kb < 2; kb++) {
            const int kp0 = kb * 8;
            uint32_t a[4][4], b[4][2];
            #pragma unroll
            for (int mf = 0; mf < 4; mf++) {
                uint32_t ad = (uint32_t)__cvta_generic_to_shared(
                    &As_[(a_row + mf * 16) * 20 + kp0 + a_kp]);
                LDSM_X4(a[mf][0], a[mf][1], a[mf][2], a[mf][3], ad);
            }
            #pragma unroll
            for (int nf2 = 0; nf2 < 2; nf2++) {
                uint32_t bd = (uint32_t)__cvta_generic_to_shared(
                    &Bs_[(b_row + nf2 * 16) * 20 + kp0 + b_kp]);
                LDSM_X4(b[2*nf2][0], b[2*nf2][1], b[2*nf2+1][0], b[2*nf2+1][1], bd);
            }
            #pragma unroll
            for (int mf = 0; mf < 4; mf++)
                #pragma unroll
                for (int nf = 0; nf < 4; nf++)
                    MMA_F16(acc[mf][nf], a[mf], b[nf]);
        }

        st++; if (st >= 3) st = 0;
    }
    #undef GF_FILL

    float scale = 1.f;
    if (gate) { float g = *gate; scale = 1.f / (1.f + expf(-g)); }

    #pragma unroll
    for (int mf = 0; mf < 4; mf++) {
        const int r = m0 + wm * 64 + mf * 16 + qr;
        #pragma unroll
        for (int nf = 0; nf < 4; nf++) {
            const int c = n0 + wn * 32 + nf * 8 + ql * 2;
            if (c < N) {
                float2 v0 = make_float2(acc[mf][nf][0] * scale, acc[mf][nf][1] * scale);
                float2 v1 = make_float2(acc[mf][nf][2] * scale, acc[mf][nf][3] * scale);
                *(float2*)&C[(size_t)r * N + c]       = v0;
                *(float2*)&C[(size_t)(r + 8) * N + c] = v1;
            }
        }
    }
}

// =================================================================
// conv_silu (pairwise) + fused bf16 hi/lo split of B|C channels
// thread handles channels (2*cp, 2*cp+1); cp < 896
// =================================================================
__global__ __launch_bounds__(256) void conv_silu_kernel(
    const float* __restrict__ conv_w, const float* __restrict__ conv_b)
{
    const long idx = (long)blockIdx.x * 256 + threadIdx.x;   // < ROWS*896
    const int  cp  = (int)(idx % (CONVDIM/2));
    const long row = idx / (CONVDIM/2);
    const int  l   = (int)(row % LSEQ);
    const int  c   = cp * 2;

    float2 acc = make_float2(conv_b[c], conv_b[c+1]);
    float4 wa = *(const float4*)&conv_w[c*4];        // ch c:  w0..w3
    float4 wb = *(const float4*)&conv_w[(c+1)*4];    // ch c+1
    const float* base = g_zxbcdt + (size_t)row * DPROJ + DINNER + c;
    if (l >= 3) { float2 v = *(const float2*)(base - 3*DPROJ);
                  acc.x = fmaf(v.x, wa.x, acc.x); acc.y = fmaf(v.y, wb.x, acc.y); }
    if (l >= 2) { float2 v = *(const float2*)(base - 2*DPROJ);
                  acc.x = fmaf(v.x, wa.y, acc.x); acc.y = fmaf(v.y, wb.y, acc.y); }
    if (l >= 1) { float2 v = *(const float2*)(base - 1*DPROJ);
                  acc.x = fmaf(v.x, wa.z, acc.x); acc.y = fmaf(v.y, wb.z, acc.y); }
    { float2 v = *(const float2*)base;
      acc.x = fmaf(v.x, wa.w, acc.x); acc.y = fmaf(v.y, wb.w, acc.y); }

    acc.x = acc.x / (1.f + expf(-acc.x));
    acc.y = acc.y / (1.f + expf(-acc.y));
    *(float2*)&g_xBC[row * CONVDIM + c] = acc;

    if (c >= DINNER) {
        const int np = (c - DINNER) >> 1;
        uint32_t hh, ll;
        bsplit2(acc.x, acc.y, hh, ll);
        g_bcH[row * 128 + np] = hh;
        g_bcL[row * 128 + np] = ll;
    }
}

// =================================================================
// dt = softplus(dt_raw + dt_bias)
// =================================================================
__global__ __launch_bounds__(256) void dt_kernel(const float* __restrict__ dt_bias)
{
    const int idx = blockIdx.x * 256 + threadIdx.x;
    const int h   = idx % NHEADS;
    const int row = idx / NHEADS;
    float v  = g_zxbcdt[(size_t)row * DPROJ + (DINNER + CONVDIM) + h] + dt_bias[h];
    float sp = (v > 20.f) ? v : log1pf(expf(v));
    g_dt[idx] = sp;
}

// =================================================================
// K1: fused per-chunk kernel — 512 threads, cp.async B/C fills (R13)
// =================================================================
#define K1_SMEM_U32 43908
#define K3_SMEM_U32 26244

__global__ __launch_bounds__(512) void chunk_fused_kernel(
    const float* __restrict__ A_log, const float* __restrict__ Dvec)
{
    extern __shared__ uint32_t smu[];
    uint32_t* CHs = smu;
    uint32_t* CLs = smu + 8704;
    uint32_t* BHs = smu + 17408;
    uint32_t* BLs = smu + 26112;
    uint32_t* XHs = smu + 34816;
    uint32_t* XLs = smu + 39168;
    float*    sa  = (float*)(smu + 43520);
    float*    sdt = (float*)(smu + 43648);
    float*    sw  = (float*)(smu + 43776);
    float*    wsum4 = (float*)(smu + 43904);

    const int blk = blockIdx.x;
    const int bh = blk >> 4, seg = blk & (NSEG - 1);
    const int b = bh / NHEADS, h = bh % NHEADS;
    const int tid = threadIdx.x, lane = tid & 31, warp = tid >> 5;
    const int qr = lane >> 2, ql = lane & 3;
    const size_t rowbase = (size_t)b * LSEQ + seg * SEGLEN;

    const int lrow = lane & 15;
    const int lkp  = (lane >> 4) << 2;
    const int brow = ((lane >> 4) << 3) + (lane & 7);
    const int bkp  = ((lane >> 3) & 1) << 2;

    #pragma unroll
    for (int i = 0; i < 4; i++) {
        int e = tid + i * 512;
        int t = e >> 4, g = (e & 15) * 4;
        const size_t srcw = (rowbase + t) * 128 + g;
        CPA16((uint32_t)__cvta_generic_to_shared(&BHs[t*TSTRIDE + g]), g_bcH + srcw);
        CPA16((uint32_t)__cvta_generic_to_shared(&BLs[t*TSTRIDE + g]), g_bcL + srcw);
        CPA16((uint32_t)__cvta_generic_to_shared(&CHs[t*TSTRIDE + g]), g_bcH + srcw + 64);
        CPA16((uint32_t)__cvta_generic_to_shared(&CLs[t*TSTRIDE + g]), g_bcL + srcw + 64);
    }
    CPA_COMMIT();

    #pragma unroll
    for (int i = 0; i < 8; i++) {
        int e = tid + i * 512;
        int p = e & 63, sp = e >> 6;
        const float* s0 = g_xBC + (rowbase + 2*sp) * CONVDIM + h * HEADDIM + p;
        uint32_t hh, ll;
        bsplit2(s0[0], s0[CONVDIM], hh, ll);
        XHs[p*TSTRIDE + sp] = hh; XLs[p*TSTRIDE + sp] = ll;
    }

    const float Aneg = -expf(A_log[h]);
    float vdt = 0.f, acs = 0.f;
    if (tid < SEGLEN) {
        vdt = g_dt[(rowbase + tid) * NHEADS + h];
        acs = vdt;
        #pragma unroll
        for (int o = 1; o < 32; o <<= 1) {
            float nv = __shfl_up_sync(0xffffffffu, acs, o);
            if (lane >= o) acs += nv;
        }
        if (lane == 31) wsum4[warp] = acs;
    }
    __syncthreads();
    if (tid < SEGLEN) {
        float tot = wsum4[0] + wsum4[1] + wsum4[2] + wsum4[3];
        float pre = 0.f;
        #pragma unroll
        for (int w2 = 0; w2 < 4; w2++) if (w2 < warp) pre += wsum4[w2];
        float a = acs + pre;
        sa[tid]  = a;
        sdt[tid] = vdt;
        sw[tid]  = vdt * __expf(Aneg * (tot - a));
    }
    CPA_WAIT0();
    __syncthreads();

    // GEMM1: M = C @ B^T
    float mreg[2][4][4];
    #pragma unroll
    for (int i = 0; i < 2; i++)
        #pragma unroll
        for (int j = 0; j < 4; j++)
            #pragma unroll
            for (int r = 0; r < 4; r++) mreg[i][j][r] = 0.f;

    const int m1 = (warp >> 2) * 32, n1 = (warp & 3) * 32;
    #pragma unroll
    for (int kb = 0; kb < 8; kb++) {
        const int kp0 = kb * 8;
        uint32_t aH[2][4], aL[2][4], bH[4][2], bL[4][2];
        #pragma unroll
        for (int mf = 0; mf < 2; mf++) {
            const int r = (m1 + lrow + mf*16) * TSTRIDE + kp0 + lkp;
            uint32_t ad = (uint32_t)__cvta_generic_to_shared(&CHs[r]);
            LDSM_X4(aH[mf][0], aH[mf][1], aH[mf][2], aH[mf][3], ad);
            ad = (uint32_t)__cvta_generic_to_shared(&CLs[r]);
            LDSM_X4(aL[mf][0], aL[mf][1], aL[mf][2], aL[mf][3], ad);
        }
        #pragma unroll
        for (int nf2 = 0; nf2 < 2; nf2++) {
            const int r = (n1 + brow + nf2*16) * TSTRIDE + kp0 + bkp;
            uint32_t bd = (uint32_t)__cvta_generic_to_shared(&BHs[r]);
            LDSM_X4(bH[2*nf2][0], bH[2*nf2][1], bH[2*nf2+1][0], bH[2*nf2+1][1], bd);
            bd = (uint32_t)__cvta_generic_to_shared(&BLs[r]);
            LDSM_X4(bL[2*nf2][0], bL[2*nf2][1], bL[2*nf2+1][0], bL[2*nf2+1][1], bd);
        }
        #pragma unroll
        for (int mf = 0; mf < 2; mf++)
            #pragma unroll
            for (int nf = 0; nf < 4; nf++)
                MMA3B(mreg[mf][nf], aH[mf], aL[mf], bH[nf], bL[nf]);
    }
    __syncthreads();

    #pragma unroll
    for (int mf = 0; mf < 2; mf++) {
        int tA = m1 + mf*16 + qr, tB = tA + 8;
        float aA = sa[tA], aB = sa[tB];
        #pragma unroll
        for (int nf = 0; nf < 4; nf++) {
            int sp = (n1 >> 1) + nf*4 + ql;
            int s0 = 2*sp, s1 = s0 + 1;
            float as0 = sa[s0], as1 = sa[s1];
            float d0 = sdt[s0], d1 = sdt[s1];
            float v00 = (s0 <= tA) ? mreg[mf][nf][0] * __expf(Aneg*(aA-as0)) * d0 : 0.f;
            float v01 = (s1 <= tA) ? mreg[mf][nf][1] * __expf(Aneg*(aA-as1)) * d1 : 0.f;
            float v10 = (s0 <= tB) ? mreg[mf][nf][2] * __expf(Aneg*(aB-as0)) * d0 : 0.f;
            float v11 = (s1 <= tB) ? mreg[mf][nf][3] * __expf(Aneg*(aB-as1)) * d1 : 0.f;
            uint32_t hh, ll;
            bsplit2(v00, v01, hh, ll); CHs[tA*TSTRIDE + sp] = hh; CLs[tA*TSTRIDE + sp] = ll;
            bsplit2(v10, v11, hh, ll); CHs[tB*TSTRIDE + sp] = hh; CLs[tB*TSTRIDE + sp] = ll;
        }
    }

    #pragma unroll
    for (int i = 0; i < 16; i++) {
        int e = tid + i * 512;
        int n = e & 127, sp = e >> 7;
        const float* s0 = g_xBC + (rowbase + 2*sp) * CONVDIM + DINNER + n;
        float f0 = s0[0] * sw[2*sp];
        float f1 = s0[CONVDIM] * sw[2*sp + 1];
        uint32_t hh, ll;
        bsplit2(f0, f1, hh, ll);
        BHs[n*TSTRIDE + sp] = hh; BLs[n*TSTRIDE + sp] = ll;
    }
    __syncthreads();

    // GEMM2: Y = M~ @ X
    {
        float yreg[4][4];
        #pragma unroll
        for (int j = 0; j < 4; j++)
            #pragma unroll
            for (int r = 0; r < 4; r++) yreg[j][r] = 0.f;

        const int m2 = (warp >> 1) * 16, n2 = (warp & 1) * 32;
        #pragma unroll
        for (int kb = 0; kb < 8; kb++) {
            const int kp0 = kb * 8;
            uint32_t aH[4], aL[4], bH[4][2], bL[4][2];
            {
                const int r = (m2 + lrow) * TSTRIDE + kp0 + lkp;
                uint32_t ad = (uint32_t)__cvta_generic_to_shared(&CHs[r]);
                LDSM_X4(aH[0], aH[1], aH[2], aH[3], ad);
                ad = (uint32_t)__cvta_generic_to_shared(&CLs[r]);
                LDSM_X4(aL[0], aL[1], aL[2], aL[3], ad);
            }
            #pragma unroll
            for (int nf2 = 0; nf2 < 2; nf2++) {
                const int r = (n2 + brow + nf2*16) * TSTRIDE + kp0 + bkp;
                uint32_t bd = (uint32_t)__cvta_generic_to_shared(&XHs[r]);
                LDSM_X4(bH[2*nf2][0], bH[2*nf2][1], bH[2*nf2+1][0], bH[2*nf2+1][1], bd);
                bd = (uint32_t)__cvta_generic_to_shared(&XLs[r]);
                LDSM_X4(bL[2*nf2][0], bL[2*nf2][1], bL[2*nf2+1][0], bL[2*nf2+1][1], bd);
            }
            #pragma unroll
            for (int nf = 0; nf < 4; nf++)
                MMA3B(yreg[nf], aH, aL, bH[nf], bL[nf]);
        }

        const float Dh = Dvec[h];
        {
            int t = m2 + qr;
            const int sp0 = t >> 1, hi0 = t & 1;
            const int sp1 = (t + 8) >> 1, hi1 = t & 1;
            #pragma unroll
            for (int nf = 0; nf < 4; nf++) {
                int p0 = n2 + nf*8 + ql*2;
                float x00 = ubf(XHs[p0*TSTRIDE + sp0], hi0) + ubf(XLs[p0*TSTRIDE + sp0], hi0);
                float x01 = ubf(XHs[(p0+1)*TSTRIDE + sp0], hi0) + ubf(XLs[(p0+1)*TSTRIDE + sp0], hi0);
                float x10 = ubf(XHs[p0*TSTRIDE + sp1], hi1) + ubf(XLs[p0*TSTRIDE + sp1], hi1);
                float x11 = ubf(XHs[(p0+1)*TSTRIDE + sp1], hi1) + ubf(XLs[(p0+1)*TSTRIDE + sp1], hi1);
                float2 o;
                o.x = yreg[nf][0] + Dh * x00;
                o.y = yreg[nf][1] + Dh * x01;
                *(float2*)&g_y[(rowbase + t)*DINNER + h*HEADDIM + p0] = o;
                o.x = yreg[nf][2] + Dh * x10;
                o.y = yreg[nf][3] + Dh * x11;
                *(float2*)&g_y[(rowbase + t + 8)*DINNER + h*HEADDIM + p0] = o;
            }
        }
    }

    // GEMM3: S = X^T @ (w*B)
    {
        float sreg[4][4];
        #pragma unroll
        for (int j = 0; j < 4; j++)
            #pragma unroll
            for (int r = 0; r < 4; r++) sreg[j][r] = 0.f;

        const int m3 = (warp >> 2) * 16, n3 = (warp & 3) * 32;
        #pragma unroll
        for (int kb = 0; kb < 8; kb++) {
            const int kp0 = kb * 8;
            uint32_t aH[4], aL[4], bH[4][2], bL[4][2];
            {
                const int r = (m3 + lrow) * TSTRIDE + kp0 + lkp;
                uint32_t ad = (uint32_t)__cvta_generic_to_shared(&XHs[r]);
                LDSM_X4(aH[0], aH[1], aH[2], aH[3], ad);
                ad = (uint32_t)__cvta_generic_to_shared(&XLs[r]);
                LDSM_X4(aL[0], aL[1], aL[2], aL[3], ad);
            }
            #pragma unroll
            for (int nf2 = 0; nf2 < 2; nf2++) {
                const int r = (n3 + brow + nf2*16) * TSTRIDE + kp0 + bkp;
                uint32_t bd = (uint32_t)__cvta_generic_to_shared(&BHs[r]);
                LDSM_X4(bH[2*nf2][0], bH[2*nf2][1], bH[2*nf2+1][0], bH[2*nf2+1][1], bd);
                bd = (uint32_t)__cvta_generic_to_shared(&BLs[r]);
                LDSM_X4(bL[2*nf2][0], bL[2*nf2][1], bL[2*nf2+1][0], bL[2*nf2+1][1], bd);
            }
            #pragma unroll
            for (int nf = 0; nf < 4; nf++)
                MMA3B(sreg[nf], aH, aL, bH[nf], bL[nf]);
        }

        const size_t sbase = ((size_t)bh * NSEG + seg) * STATESZ;
        {
            int p = m3 + qr;
            #pragma unroll
            for (int nf = 0; nf < 4; nf++) {
                int n0 = n3 + nf*8 + ql*2;
                float2 o0 = make_float2(sreg[nf][0], sreg[nf][1]);
                float2 o1 = make_float2(sreg[nf][2], sreg[nf][3]);
                *(float2*)&g_states[sbase + (size_t)p * DSTATE + n0]       = o0;
                *(float2*)&g_states[sbase + (size_t)(p + 8) * DSTATE + n0] = o1;
            }
        }
    }
}

// =================================================================
// K2: combine — emits pre-split bf16 hi/lo hstart pairs
// =================================================================
__global__ __launch_bounds__(256) void combine_kernel(const float* __restrict__ A_log)
{
    const int bh = blockIdx.x;
    const int b = bh / NHEADS, h = bh % NHEADS;
    const int tid = threadIdx.x;

    __shared__ float part[256];
    __shared__ float Esh[NSEG];

    {
        const int k = tid >> 4, i = tid & 15;
        float s = 0.f;
        const size_t base = ((size_t)b*LSEQ + k*SEGLEN + i*8)*NHEADS + h;
        #pragma unroll
        for (int t = 0; t < 8; t++) s += g_dt[base + (size_t)t*NHEADS];
        part[tid] = s;
    }
    __syncthreads();
    if (tid < NSEG) {
        float s = 0.f;
        #pragma unroll
        for (int i = 0; i < 16; i++) s += part[tid*16 + i];
        Esh[tid] = expf(-expf(A_log[h]) * s);
    }
    __syncthreads();

    float2 hs[16];
    #pragma unroll
    for (int k2 = 0; k2 < 16; k2++) hs[k2] = make_float2(0.f, 0.f);

    for (int seg = 0; seg < NSEG; seg++) {
        const size_t pbase = ((size_t)bh*NSEG + seg)*STATEPAIRS;
        const float E = Esh[seg];
        #pragma unroll
        for (int k2 = 0; k2 < 16; k2++) {
            const size_t j = pbase + k2*256 + tid;
            uint32_t hh, ll;
            bsplit2(hs[k2].x, hs[k2].y, hh, ll);
            g_hsH[j] = hh;  g_hsL[j] = ll;
            float2 s = ((const float2*)g_states)[j];
            hs[k2].x = fmaf(hs[k2].x, E, s.x);
            hs[k2].y = fmaf(hs[k2].y, E, s.y);
        }
    }
}

// =================================================================
// K3: inter-chunk — 512 threads, cp.async fills (R13)
// =================================================================
__global__ __launch_bounds__(512) void inter_kernel(const float* __restrict__ A_log)
{
    extern __shared__ uint32_t smu[];
    uint32_t* CH2 = smu;
    uint32_t* CL2 = smu + 8704;
    uint32_t* HHs = smu + 17408;
    uint32_t* HLs = smu + 21760;
    float*    su  = (float*)(smu + 26112);
    float*    wsum4 = (float*)(smu + 26240);

    const int blk = blockIdx.x;
    const int bh = blk >> 4, seg = blk & (NSEG - 1);
    const int b = bh / NHEADS, h = bh % NHEADS;
    const int tid = threadIdx.x, lane = tid & 31, warp = tid >> 5;
    const int qr = lane >> 2, ql = lane & 3;
    const size_t rowbase = (size_t)b * LSEQ + seg * SEGLEN;
    const size_t hpb = ((size_t)bh * NSEG + seg) * STATEPAIRS;

    const int lrow = lane & 15;
    const int lkp  = (lane >> 4) << 2;
    const int brow = ((lane >> 4) << 3) + (lane & 7);
    const int bkp  = ((lane >> 3) & 1) << 2;

    #pragma unroll
    for (int i = 0; i < 4; i++) {
        int e = tid + i * 512;
        int t = e >> 4, g = (e & 15) * 4;
        const size_t srcw = (rowbase + t) * 128 + 64 + g;
        CPA16((uint32_t)__cvta_generic_to_shared(&CH2[t*TSTRIDE + g]), g_bcH + srcw);
        CPA16((uint32_t)__cvta_generic_to_shared(&CL2[t*TSTRIDE + g]), g_bcL + srcw);
    }
    #pragma unroll
    for (int i = 0; i < 2; i++) {
        int e = tid + i * 512;
        int p = e >> 4, g = (e & 15) * 4;
        const size_t srcw = hpb + (size_t)p * 64 + g;
        CPA16((uint32_t)__cvta_generic_to_shared(&HHs[p*TSTRIDE + g]), g_hsH + srcw);
        CPA16((uint32_t)__cvta_generic_to_shared(&HLs[p*TSTRIDE + g]), g_hsL + srcw);
    }
    CPA_COMMIT();

    const float Aneg = -expf(A_log[h]);
    float vdt = 0.f, acs = 0.f;
    if (tid < SEGLEN) {
        vdt = g_dt[(rowbase + tid) * NHEADS + h];
        acs = vdt;
        #pragma unroll
        for (int o = 1; o < 32; o <<= 1) {
            float nv = __shfl_up_sync(0xffffffffu, acs, o);
            if (lane >= o) acs += nv;
        }
        if (lane == 31) wsum4[warp] = acs;
    }
    __syncthreads();
    if (tid < SEGLEN) {
        float pre = 0.f;
        #pragma unroll
        for (int w2 = 0; w2 < 4; w2++) if (w2 < warp) pre += wsum4[w2];
        su[tid] = __expf(Aneg * (acs + pre));
    }
    CPA_WAIT0();
    __syncthreads();

    float yreg[4][4];
    #pragma unroll
    for (int j = 0; j < 4; j++)
        #pragma unroll
        for (int r = 0; r < 4; r++) yreg[j][r] = 0.f;

    const int m2 = (warp >> 1) * 16, n2 = (warp & 1) * 32;
    #pragma unroll
    for (int kb = 0; kb < 8; kb++) {
        const int kp0 = kb * 8;
        uint32_t aH[4], aL[4], bH[4][2], bL[4][2];
        {
            const int r = (m2 + lrow) * TSTRIDE + kp0 + lkp;
            uint32_t ad = (uint32_t)__cvta_generic_to_shared(&CH2[r]);
            LDSM_X4(aH[0], aH[1], aH[2], aH[3], ad);
            ad = (uint32_t)__cvta_generic_to_shared(&CL2[r]);
            LDSM_X4(aL[0], aL[1], aL[2], aL[3], ad);
        }
        #pragma unroll
        for (int nf2 = 0; nf2 < 2; nf2++) {
            const int r = (n2 + brow + nf2*16) * TSTRIDE + kp0 + bkp;
            uint32_t bd = (uint32_t)__cvta_generic_to_shared(&HHs[r]);
            LDSM_X4(bH[2*nf2][0], bH[2*nf2][1], bH[2*nf2+1][0], bH[2*nf2+1][1], bd);
            bd = (uint32_t)__cvta_generic_to_shared(&HLs[r]);
            LDSM_X4(bL[2*nf2][0], bL[2*nf2][1], bL[2*nf2+1][0], bL[2*nf2+1][1], bd);
        }
        #pragma unroll
        for (int nf = 0; nf < 4; nf++)
            MMA3B(yreg[nf], aH, aL, bH[nf], bL[nf]);
    }

    {
        int t = m2 + qr;
        float u0 = su[t], u1 = su[t + 8];
        #pragma unroll
        for (int nf = 0; nf < 4; nf++) {
            int p0 = n2 + nf*8 + ql*2;
            float* addr0 = &g_y[(rowbase + t)*DINNER + h*HEADDIM + p0];
            float* addr1 = &g_y[(rowbase + t + 8)*DINNER + h*HEADDIM + p0];
            float2 o0 = *(float2*)addr0;
            float2 o1 = *(float2*)addr1;
            o0.x += u0 * yreg[nf][0];  o0.y += u0 * yreg[nf][1];
            o1.x += u1 * yreg[nf][2];  o1.y += u1 * yreg[nf][3];
            *(float2*)addr0 = o0;
            *(float2*)addr1 = o1;
        }
    }
}

// =================================================================
// gate+norm: y = y*silu(z); rmsnorm; emit packed fp16 pairs
// =================================================================
__global__ __launch_bounds__(256) void gate_norm_kernel(const float* __restrict__ norm_w)
{
    const int row = blockIdx.x;
    const int tid = threadIdx.x;
    const float* zrow = g_zxbcdt + (size_t)row * DPROJ;
    const float* yrow = g_y + (size_t)row * DINNER;

    float2 v[3];
    float ss = 0.f;
    #pragma unroll
    for (int i = 0; i < 3; i++) {
        int p = tid + i*256;
        float2 z2 = *(const float2*)&zrow[2*p];
        float2 y2 = *(const float2*)&yrow[2*p];
        float g0 = y2.x * (z2.x / (1.f + expf(-z2.x)));
        float g1 = y2.y * (z2.y / (1.f + expf(-z2.y)));
        v[i] = make_float2(g0, g1);
        ss += g0*g0 + g1*g1;
    }
    #pragma unroll
    for (int o = 16; o > 0; o >>= 1) ss += __shfl_xor_sync(0xffffffffu, ss, o);
    __shared__ float red[8];
    if ((tid & 31) == 0) red[tid >> 5] = ss;
    __syncthreads();
    if (tid < 32) {
        float s2 = (tid < 8) ? red[tid] : 0.f;
        #pragma unroll
        for (int o = 4; o > 0; o >>= 1) s2 += __shfl_xor_sync(0xffffffffu, s2, o);
        if (tid == 0) red[0] = s2;
    }
    __syncthreads();
    const float rstd = rsqrtf(red[0] * (1.f/1536.f) + 1e-5f);
    #pragma unroll
    for (int i = 0; i < 3; i++) {
        int p = tid + i*256;
        float2 w2 = *(const float2*)&norm_w[2*p];
        g_y16[(size_t)row * (DINNER/2) + p] =
            packh2(v[i].x * rstd * w2.x, v[i].y * rstd * w2.y);
    }
}

// =================================================================
extern "C" void kernel_launch(void* const* d_in, const int* in_sizes, int n_in,
                              void* d_out, int out_size)
{
    const float* feature   = (const float*)d_in[0];
    const float* in_proj_w = (const float*)d_in[1];
    const float* conv_w    = (const float*)d_in[2];
    const float* conv_b    = (const float*)d_in[3];
    const float* dt_bias   = (const float*)d_in[4];
    const float* A_log     = (const float*)d_in[5];
    const float* Dvec      = (const float*)d_in[6];
    const float* norm_w    = (const float*)d_in[7];
    const float* out_projw = (const float*)d_in[8];
    const float* gate1     = (const float*)d_in[9];
    float* out = (float*)d_out;

    float *zx;
    uint32_t *f16, *iw16, *ow16, *y16;
    cudaGetSymbolAddress((void**)&zx,   g_zxbcdt);
    cudaGetSymbolAddress((void**)&f16,  g_feat16);
    cudaGetSymbolAddress((void**)&iw16, g_ipw16);
    cudaGetSymbolAddress((void**)&ow16, g_opw16);
    cudaGetSymbolAddress((void**)&y16,  g_y16);

    cudaFuncSetAttribute(gemm_fp16,
        cudaFuncAttributeMaxDynamicSharedMemorySize, GP_SMEM);
    cudaFuncSetAttribute(chunk_fused_kernel,
        cudaFuncAttributeMaxDynamicSharedMemorySize, K1_SMEM_U32 * 4);
    cudaFuncSetAttribute(inter_kernel,
        cudaFuncAttributeMaxDynamicSharedMemorySize, K3_SMEM_U32 * 4);

    dim3 blk(256);
    dim3 blk5(512);

    tofp16_kernel<<<(ROWS*DMODEL/2)/256, blk>>>(feature, f16);
    tofp16_kernel<<<(DPROJ*DMODEL/2)/256, blk>>>(in_proj_w, iw16);
    tofp16_kernel<<<(DMODEL*DINNER/2)/256, blk>>>(out_projw, ow16);

    gemm_fp16<<<dim3((DPROJ + 127)/128, ROWS/128), blk, GP_SMEM>>>(
        f16, iw16, zx, ROWS, DPROJ, DMODEL/2, nullptr);

    conv_silu_kernel<<<(int)(((long)ROWS * (CONVDIM/2)) / 256), blk>>>(conv_w, conv_b);
    dt_kernel<<<(ROWS * NHEADS) / 256, blk>>>(dt_bias);

    chunk_fused_kernel<<<BATCH * NHEADS * NSEG, blk5, K1_SMEM_U32 * 4>>>(A_log, Dvec);
    combine_kernel<<<BATCH * NHEADS, blk>>>(A_log);
    inter_kernel<<<BATCH * NHEADS * NSEG, blk5, K3_SMEM_U32 * 4>>>(A_log);

    gate_norm_kernel<<<ROWS, blk>>>(norm_w);

    gemm_fp16<<<dim3(DMODEL/128, ROWS/128), blk, GP_SMEM>>>(
        y16, ow16, out, ROWS, DMODEL, DINNER/2, gate1);
}

// round 15
// speedup vs baseline: 1.9060x; 1.0467x over previous
#include <cuda_runtime.h>
#include <cuda_fp16.h>
#include <math.h>
#include <stdint.h>

#define BATCH   4
#define LSEQ    2048
#define ROWS    (BATCH*LSEQ)      // 8192
#define DMODEL  768
#define DINNER  1536
#define NHEADS  24
#define HEADDIM 64
#define DSTATE  128
#define CONVDIM 1792
#define DPROJ   3352

#define NSEG    32
#define SEGLEN  (LSEQ/NSEG)       // 64
#define STATESZ (HEADDIM*DSTATE)  // 8192
#define STATEPAIRS (STATESZ/2)    // 4096

// -------- scratch (device globals; no allocation allowed) --------
__device__ float g_zxbcdt[(size_t)ROWS * DPROJ];
__device__ float g_xBC[(size_t)ROWS * CONVDIM];
__device__ float g_dt[ROWS * NHEADS];
__device__ float g_y[(size_t)ROWS * DINNER];
__device__ float g_states[(size_t)BATCH*NHEADS*NSEG*STATESZ];
// pre-split bf16 hi/lo of xBC's B|C columns: [row][128 pairs]
__device__ uint32_t g_bcH[(size_t)ROWS*128];
__device__ uint32_t g_bcL[(size_t)ROWS*128];
// pre-split bf16 hi/lo segment start states
__device__ uint32_t g_hsH[(size_t)BATCH*NHEADS*NSEG*STATEPAIRS];
__device__ uint32_t g_hsL[(size_t)BATCH*NHEADS*NSEG*STATEPAIRS];
// fp16 packed-pair operands for projection GEMMs
__device__ uint32_t g_feat16[(size_t)ROWS*DMODEL/2];
__device__ uint32_t g_ipw16[(size_t)DPROJ*DMODEL/2];
__device__ uint32_t g_opw16[(size_t)DMODEL*DINNER/2];
__device__ uint32_t g_y16[(size_t)ROWS*DINNER/2];

// =================================================================
// helpers
// =================================================================
__device__ __forceinline__ uint32_t packbf2(float f0, float f1) {
    uint32_t r;
    asm("cvt.rn.bf16x2.f32 %0, %1, %2;" : "=r"(r) : "f"(f1), "f"(f0));
    return r;
}
__device__ __forceinline__ void bsplit2(float f0, float f1, uint32_t& H, uint32_t& L) {
    H = packbf2(f0, f1);
    float h0 = __uint_as_float(H << 16);
    float h1 = __uint_as_float(H & 0xffff0000u);
    L = packbf2(f0 - h0, f1 - h1);
}
__device__ __forceinline__ uint32_t packh2(float f0, float f1) {
    __half2 h = __float22half2_rn(make_float2(f0, f1));
    return *(uint32_t*)&h;
}
__device__ __forceinline__ float ubf(uint32_t w, int hi) {
    return __uint_as_float(hi ? (w & 0xffff0000u) : (w << 16));
}

#define CPA16(dst, src) \
    asm volatile("cp.async.cg.shared.global [%0], [%1], 16;\n" \
                 :: "r"(dst), "l"(src))
#define CPA16P(dst, src, valid) \
    asm volatile("cp.async.cg.shared.global [%0], [%1], 16, %2;\n" \
                 :: "r"(dst), "l"(src), "r"((valid) ? 16 : 0))
#define CPA_COMMIT() asm volatile("cp.async.commit_group;\n" ::: "memory")
#define CPA_WAIT0()  asm volatile("cp.async.wait_group 0;\n" ::: "memory")
#define CPA_WAIT1()  asm volatile("cp.async.wait_group 1;\n" ::: "memory")

#define MMA_BF16(d, a, b) \
    asm volatile("mma.sync.aligned.m16n8k16.row.col.f32.bf16.bf16.f32 " \
                 "{%0,%1,%2,%3},{%4,%5,%6,%7},{%8,%9},{%0,%1,%2,%3};\n" \
                 : "+f"((d)[0]), "+f"((d)[1]), "+f"((d)[2]), "+f"((d)[3]) \
                 : "r"((a)[0]), "r"((a)[1]), "r"((a)[2]), "r"((a)[3]), \
                   "r"((b)[0]), "r"((b)[1]))
#define MMA_F16(d, a, b) \
    asm volatile("mma.sync.aligned.m16n8k16.row.col.f32.f16.f16.f32 " \
                 "{%0,%1,%2,%3},{%4,%5,%6,%7},{%8,%9},{%0,%1,%2,%3};\n" \
                 : "+f"((d)[0]), "+f"((d)[1]), "+f"((d)[2]), "+f"((d)[3]) \
                 : "r"((a)[0]), "r"((a)[1]), "r"((a)[2]), "r"((a)[3]), \
                   "r"((b)[0]), "r"((b)[1]))
#define MMA3B(d, aH, aL, bH, bL) do { \
    MMA_BF16(d, aL, bH); \
    MMA_BF16(d, aH, bL); \
    MMA_BF16(d, aH, bH); } while (0)

#define LDSM_X4(r0, r1, r2, r3, a) \
    asm volatile("ldmatrix.sync.aligned.m8n8.x4.shared.b16 {%0,%1,%2,%3}, [%4];" \
                 : "=r"(r0), "=r"(r1), "=r"(r2), "=r"(r3) : "r"(a))

#define TSTRIDE 68   // words per 64-pair tile row (C/B initial, inter tiles)
#define XSTRIDE 36   // words per 32-pair tile row (X, M~ k, wB)

// =================================================================
// fp32 -> packed fp16 pair conversion
// =================================================================
__global__ __launch_bounds__(256) void tofp16_kernel(
    const float* __restrict__ src, uint32_t* __restrict__ dst)
{
    const int idx = blockIdx.x * 256 + threadIdx.x;
    float2 v = ((const float2*)src)[idx];
    dst[idx] = packh2(v.x, v.y);
}

// =================================================================
// fp16 tensor-core GEMM (NT): 3-stage cp.async pipeline (R14 passing)
// =================================================================
#define GP_STAGE 5120
#define GP_SMEM  (3 * GP_STAGE * 4)

__global__ __launch_bounds__(256) void gemm_fp16(
    const uint32_t* __restrict__ A16, const uint32_t* __restrict__ B16,
    float* __restrict__ C, int M, int N, int Kp,
    const float* __restrict__ gate)
{
    extern __shared__ uint32_t gsm[];

    const int tid  = threadIdx.x;
    const int lane = tid & 31;
    const int warp = tid >> 5;
    const int wm   = warp >> 2;
    const int wn   = warp & 3;
    const int m0   = blockIdx.y * 128;
    const int n0   = blockIdx.x * 128;
    const int qr   = lane >> 2;
    const int ql   = lane & 3;

    const uint32_t* csrc[4];
    int coff[4];
    bool cval[4];
    #pragma unroll
    for (int q = 0; q < 4; q++) {
        int e = tid + q * 256;
        bool isB = e >= 512;
        int r = (e & 511) >> 2;
        int g = (e & 3) * 4;
        coff[q] = (isB ? 2560 : 0) + r * 20 + g;
        int grow = isB ? min(n0 + r, N - 1) : (m0 + r);
        cval[q] = isB ? ((n0 + r) < N) : true;
        csrc[q] = (isB ? B16 : A16) + (size_t)grow * Kp + g;
    }

    const int a_row = wm * 64 + (lane & 15);
    const int a_kp  = (lane >> 4) << 2;
    const int b_row = wn * 32 + ((lane >> 4) << 3) + (lane & 7);
    const int b_kp  = ((lane >> 3) & 1) << 2;

    float acc[4][4][4];
    #pragma unroll
    for (int i = 0; i < 4; i++)
        #pragma unroll
        for (int j = 0; j < 4; j++)
            #pragma unroll
            for (int r = 0; r < 4; r++) acc[i][j][r] = 0.f;

    const int KT = Kp / 16;

    #define GF_FILL(kt, s)                                                       \
    {                                                                            \
        const size_t ko = (size_t)(kt) * 16;                                     \
        uint32_t* stg = gsm + (s) * GP_STAGE;                                    \
        _Pragma("unroll")                                                        \
        for (int q = 0; q < 4; q++) {                                            \
            uint32_t d = (uint32_t)__cvta_generic_to_shared(&stg[coff[q]]);      \
            CPA16P(d, csrc[q] + ko, cval[q]);                                    \
        }                                                                        \
        CPA_COMMIT();                                                            \
    }

    GF_FILL(0, 0);
    if (KT > 1) GF_FILL(1, 1);

    int st = 0;
    for (int kt = 0; kt < KT; kt++) {
        if (kt + 1 < KT) { CPA_WAIT1(); } else { CPA_WAIT0(); }
        __syncthreads();

        if (kt + 2 < KT) {
            int ns = st + 2; if (ns >= 3) ns -= 3;
            GF_FILL(kt + 2, ns);
        }

        const uint32_t* As_ = gsm + st * GP_STAGE;
        const uint32_t* Bs_ = As_ + 2560;

        #pragma unroll
        for (int kb = 0; kb < 2; kb++) {
            const int kp0 = kb * 8;
            uint32_t a[4][4], b[4][2];
            #pragma unroll
            for (int mf = 0; mf < 4; mf++) {
                uint32_t ad = (uint32_t)__cvta_generic_to_shared(
                    &As_[(a_row + mf * 16) * 20 + kp0 + a_kp]);
                LDSM_X4(a[mf][0], a[mf][1], a[mf][2], a[mf][3], ad);
            }
            #pragma unroll
            for (int nf2 = 0; nf2 < 2; nf2++) {
                uint32_t bd = (uint32_t)__cvta_generic_to_shared(
                    &Bs_[(b_row + nf2 * 16) * 20 + kp0 + b_kp]);
                LDSM_X4(b[2*nf2][0], b[2*nf2][1], b[2*nf2+1][0], b[2*nf2+1][1], bd);
            }
            #pragma unroll
            for (int mf = 0; mf < 4; mf++)
                #pragma unroll
                for (int nf = 0; nf < 4; nf++)
                    MMA_F16(acc[mf][nf], a[mf], b[nf]);
        }

        st++; if (st >= 3) st = 0;
    }
    #undef GF_FILL

    float scale = 1.f;
    if (gate) { float g = *gate; scale = 1.f / (1.f + expf(-g)); }

    #pragma unroll
    for (int mf = 0; mf < 4; mf++) {
        const int r = m0 + wm * 64 + mf * 16 + qr;
        #pragma unroll
        for (int nf = 0; nf < 4; nf++) {
            const int c = n0 + wn * 32 + nf * 8 + ql * 2;
            if (c < N) {
                float2 v0 = make_float2(acc[mf][nf][0] * scale, acc[mf][nf][1] * scale);
                float2 v1 = make_float2(acc[mf][nf][2] * scale, acc[mf][nf][3] * scale);
                *(float2*)&C[(size_t)r * N + c]       = v0;
                *(float2*)&C[(size_t)(r + 8) * N + c] = v1;
            }
        }
    }
}

// =================================================================
// conv_silu (pairwise) + fused bf16 hi/lo split of B|C channels (R14)
// =================================================================
__global__ __launch_bounds__(256) void conv_silu_kernel(
    const float* __restrict__ conv_w, const float* __restrict__ conv_b)
{
    const long idx = (long)blockIdx.x * 256 + threadIdx.x;
    const int  cp  = (int)(idx % (CONVDIM/2));
    const long row = idx / (CONVDIM/2);
    const int  l   = (int)(row % LSEQ);
    const int  c   = cp * 2;

    float2 acc = make_float2(conv_b[c], conv_b[c+1]);
    float4 wa = *(const float4*)&conv_w[c*4];
    float4 wb = *(const float4*)&conv_w[(c+1)*4];
    const float* base = g_zxbcdt + (size_t)row * DPROJ + DINNER + c;
    if (l >= 3) { float2 v = *(const float2*)(base - 3*DPROJ);
                  acc.x = fmaf(v.x, wa.x, acc.x); acc.y = fmaf(v.y, wb.x, acc.y); }
    if (l >= 2) { float2 v = *(const float2*)(base - 2*DPROJ);
                  acc.x = fmaf(v.x, wa.y, acc.x); acc.y = fmaf(v.y, wb.y, acc.y); }
    if (l >= 1) { float2 v = *(const float2*)(base - 1*DPROJ);
                  acc.x = fmaf(v.x, wa.z, acc.x); acc.y = fmaf(v.y, wb.z, acc.y); }
    { float2 v = *(const float2*)base;
      acc.x = fmaf(v.x, wa.w, acc.x); acc.y = fmaf(v.y, wb.w, acc.y); }

    acc.x = acc.x / (1.f + expf(-acc.x));
    acc.y = acc.y / (1.f + expf(-acc.y));
    *(float2*)&g_xBC[row * CONVDIM + c] = acc;

    if (c >= DINNER) {
        const int np = (c - DINNER) >> 1;
        uint32_t hh, ll;
        bsplit2(acc.x, acc.y, hh, ll);
        g_bcH[row * 128 + np] = hh;
        g_bcL[row * 128 + np] = ll;
    }
}

// =================================================================
// dt = softplus(dt_raw + dt_bias)
// =================================================================
__global__ __launch_bounds__(256) void dt_kernel(const float* __restrict__ dt_bias)
{
    const int idx = blockIdx.x * 256 + threadIdx.x;
    const int h   = idx % NHEADS;
    const int row = idx / NHEADS;
    float v  = g_zxbcdt[(size_t)row * DPROJ + (DINNER + CONVDIM) + h] + dt_bias[h];
    float sp = (v > 20.f) ? v : log1pf(expf(v));
    g_dt[idx] = sp;
}

// =================================================================
// K1: fused per-chunk kernel — T=64, 256 threads, 8 warps.
// smem (u32 words):
//   CHs [64][68]@0  CLs@4352   (C; later M~ rows t, kp=s pairs<32)
//   BHs@8704 (4608) BLs@13312  (B [64][68]; later wB [128][36])
//   XHs@17920 (2304, [64][36]) XLs@20224
//   sa@22528 sdt@22592 sw@22656 wsum@22720
// =================================================================
#define K1_SMEM_U32 22724
#define K3_SMEM_U32 17476

__global__ __launch_bounds__(256) void chunk_fused_kernel(
    const float* __restrict__ A_log, const float* __restrict__ Dvec)
{
    extern __shared__ uint32_t smu[];
    uint32_t* CHs = smu;
    uint32_t* CLs = smu + 4352;
    uint32_t* BHs = smu + 8704;
    uint32_t* BLs = smu + 13312;
    uint32_t* XHs = smu + 17920;
    uint32_t* XLs = smu + 20224;
    float*    sa  = (float*)(smu + 22528);
    float*    sdt = (float*)(smu + 22592);
    float*    sw  = (float*)(smu + 22656);
    float*    wsum2 = (float*)(smu + 22720);

    const int blk = blockIdx.x;
    const int bh = blk >> 5, seg = blk & (NSEG - 1);
    const int b = bh / NHEADS, h = bh % NHEADS;
    const int tid = threadIdx.x, lane = tid & 31, warp = tid >> 5;
    const int qr = lane >> 2, ql = lane & 3;
    const size_t rowbase = (size_t)b * LSEQ + seg * SEGLEN;

    const int lrow = lane & 15;
    const int lkp  = (lane >> 4) << 2;
    const int brow = ((lane >> 4) << 3) + (lane & 7);
    const int bkp  = ((lane >> 3) & 1) << 2;

    // ---- cp.async fill: B tile (bc words 0..63), C tile (64..127), 64 rows ----
    #pragma unroll
    for (int i = 0; i < 4; i++) {
        int e = tid + i * 256;           // < 1024
        int t = e >> 4, g = (e & 15) * 4;
        const size_t srcw = (rowbase + t) * 128 + g;
        CPA16((uint32_t)__cvta_generic_to_shared(&BHs[t*TSTRIDE + g]), g_bcH + srcw);
        CPA16((uint32_t)__cvta_generic_to_shared(&BLs[t*TSTRIDE + g]), g_bcL + srcw);
        CPA16((uint32_t)__cvta_generic_to_shared(&CHs[t*TSTRIDE + g]), g_bcH + srcw + 64);
        CPA16((uint32_t)__cvta_generic_to_shared(&CLs[t*TSTRIDE + g]), g_bcL + srcw + 64);
    }
    CPA_COMMIT();

    // ---- fill X rows p<64, sp<32 ----
    #pragma unroll
    for (int i = 0; i < 8; i++) {
        int e = tid + i * 256;           // < 2048
        int p = e & 63, sp = e >> 6;
        const float* s0 = g_xBC + (rowbase + 2*sp) * CONVDIM + h * HEADDIM + p;
        uint32_t hh, ll;
        bsplit2(s0[0], s0[CONVDIM], hh, ll);
        XHs[p*XSTRIDE + sp] = hh; XLs[p*XSTRIDE + sp] = ll;
    }

    // ---- dt cumsum / weights (tid < 64, warps 0..1) ----
    const float Aneg = -expf(A_log[h]);
    float vdt = 0.f, acs = 0.f;
    if (tid < SEGLEN) {
        vdt = g_dt[(rowbase + tid) * NHEADS + h];
        acs = vdt;
        #pragma unroll
        for (int o = 1; o < 32; o <<= 1) {
            float nv = __shfl_up_sync(0xffffffffu, acs, o);
            if (lane >= o) acs += nv;
        }
        if (lane == 31) wsum2[warp] = acs;
    }
    __syncthreads();
    if (tid < SEGLEN) {
        float tot = wsum2[0] + wsum2[1];
        float pre = (warp == 1) ? wsum2[0] : 0.f;
        float a = acs + pre;
        sa[tid]  = a;
        sdt[tid] = vdt;
        sw[tid]  = vdt * __expf(Aneg * (tot - a));
    }
    CPA_WAIT0();
    __syncthreads();

    // ================= GEMM1: M = C @ B^T (64x64, K=128) =================
    // warp grid: 4m x 2n, tile 16 x 32
    float mreg[4][4];
    #pragma unroll
    for (int j = 0; j < 4; j++)
        #pragma unroll
        for (int r = 0; r < 4; r++) mreg[j][r] = 0.f;

    const int m1 = (warp >> 1) * 16, n1 = (warp & 1) * 32;
    if (n1 < m1 + 16) {   // skip fully-masked (strictly upper-triangle) tiles
        #pragma unroll
        for (int kb = 0; kb < 8; kb++) {
            const int kp0 = kb * 8;
            uint32_t aH[4], aL[4], bH[4][2], bL[4][2];
            {
                const int r = (m1 + lrow) * TSTRIDE + kp0 + lkp;
                uint32_t ad = (uint32_t)__cvta_generic_to_shared(&CHs[r]);
                LDSM_X4(aH[0], aH[1], aH[2], aH[3], ad);
                ad = (uint32_t)__cvta_generic_to_shared(&CLs[r]);
                LDSM_X4(aL[0], aL[1], aL[2], aL[3], ad);
            }
            #pragma unroll
            for (int nf2 = 0; nf2 < 2; nf2++) {
                const int r = (n1 + brow + nf2*16) * TSTRIDE + kp0 + bkp;
                uint32_t bd = (uint32_t)__cvta_generic_to_shared(&BHs[r]);
                LDSM_X4(bH[2*nf2][0], bH[2*nf2][1], bH[2*nf2+1][0], bH[2*nf2+1][1], bd);
                bd = (uint32_t)__cvta_generic_to_shared(&BLs[r]);
                LDSM_X4(bL[2*nf2][0], bL[2*nf2][1], bL[2*nf2+1][0], bL[2*nf2+1][1], bd);
            }
            #pragma unroll
            for (int nf = 0; nf < 4; nf++)
                MMA3B(mreg[nf], aH, aL, bH[nf], bL[nf]);
        }
    }
    __syncthreads();   // all warps done reading CHs/BHs

    // ---- mask + store M~ rows t, kp = s pair (sp < 32) ----
    {
        int tA = m1 + qr, tB = tA + 8;
        float aA = sa[tA], aB = sa[tB];
        #pragma unroll
        for (int nf = 0; nf < 4; nf++) {
            int sp = (n1 >> 1) + nf*4 + ql;
            int s0 = 2*sp, s1 = s0 + 1;
            float as0 = sa[s0], as1 = sa[s1];
            float d0 = sdt[s0], d1 = sdt[s1];
            float v00 = (s0 <= tA) ? mreg[nf][0] * __expf(Aneg*(aA-as0)) * d0 : 0.f;
            float v01 = (s1 <= tA) ? mreg[nf][1] * __expf(Aneg*(aA-as1)) * d1 : 0.f;
            float v10 = (s0 <= tB) ? mreg[nf][2] * __expf(Aneg*(aB-as0)) * d0 : 0.f;
            float v11 = (s1 <= tB) ? mreg[nf][3] * __expf(Aneg*(aB-as1)) * d1 : 0.f;
            uint32_t hh, ll;
            bsplit2(v00, v01, hh, ll); CHs[tA*TSTRIDE + sp] = hh; CLs[tA*TSTRIDE + sp] = ll;
            bsplit2(v10, v11, hh, ll); CHs[tB*TSTRIDE + sp] = hh; CLs[tB*TSTRIDE + sp] = ll;
        }
    }

    // ---- refill BH/BL as (w*B) rows n<128, sp<32, stride 36 ----
    #pragma unroll
    for (int i = 0; i < 16; i++) {
        int e = tid + i * 256;           // < 4096
        int n = e & 127, sp = e >> 7;
        const float* s0 = g_xBC + (rowbase + 2*sp) * CONVDIM + DINNER + n;
        float f0 = s0[0] * sw[2*sp];
        float f1 = s0[CONVDIM] * sw[2*sp + 1];
        uint32_t hh, ll;
        bsplit2(f0, f1, hh, ll);
        BHs[n*XSTRIDE + sp] = hh; BLs[n*XSTRIDE + sp] = ll;
    }
    __syncthreads();

    // ================= GEMM2: Y = M~ @ X (64t x 64p, K=64) ================
    {
        float yreg[4][4];
        #pragma unroll
        for (int j = 0; j < 4; j++)
            #pragma unroll
            for (int r = 0; r < 4; r++) yreg[j][r] = 0.f;

        const int m2 = (warp >> 1) * 16, n2 = (warp & 1) * 32;
        #pragma unroll
        for (int kb = 0; kb < 4; kb++) {
            const int kp0 = kb * 8;
            uint32_t aH[4], aL[4], bH[4][2], bL[4][2];
            {
                const int r = (m2 + lrow) * TSTRIDE + kp0 + lkp;
                uint32_t ad = (uint32_t)__cvta_generic_to_shared(&CHs[r]);
                LDSM_X4(aH[0], aH[1], aH[2], aH[3], ad);
                ad = (uint32_t)__cvta_generic_to_shared(&CLs[r]);
                LDSM_X4(aL[0], aL[1], aL[2], aL[3], ad);
            }
            #pragma unroll
            for (int nf2 = 0; nf2 < 2; nf2++) {
                const int r = (n2 + brow + nf2*16) * XSTRIDE + kp0 + bkp;
                uint32_t bd = (uint32_t)__cvta_generic_to_shared(&XHs[r]);
                LDSM_X4(bH[2*nf2][0], bH[2*nf2][1], bH[2*nf2+1][0], bH[2*nf2+1][1], bd);
                bd = (uint32_t)__cvta_generic_to_shared(&XLs[r]);
                LDSM_X4(bL[2*nf2][0], bL[2*nf2][1], bL[2*nf2+1][0], bL[2*nf2+1][1], bd);
            }
            #pragma unroll
            for (int nf = 0; nf < 4; nf++)
                MMA3B(yreg[nf], aH, aL, bH[nf], bL[nf]);
        }

        const float Dh = Dvec[h];
        {
            int t = m2 + qr;
            const int sp0 = t >> 1, hi0 = t & 1;
            const int sp1 = (t + 8) >> 1, hi1 = t & 1;
            #pragma unroll
            for (int nf = 0; nf < 4; nf++) {
                int p0 = n2 + nf*8 + ql*2;
                float x00 = ubf(XHs[p0*XSTRIDE + sp0], hi0) + ubf(XLs[p0*XSTRIDE + sp0], hi0);
                float x01 = ubf(XHs[(p0+1)*XSTRIDE + sp0], hi0) + ubf(XLs[(p0+1)*XSTRIDE + sp0], hi0);
                float x10 = ubf(XHs[p0*XSTRIDE + sp1], hi1) + ubf(XLs[p0*XSTRIDE + sp1], hi1);
                float x11 = ubf(XHs[(p0+1)*XSTRIDE + sp1], hi1) + ubf(XLs[(p0+1)*XSTRIDE + sp1], hi1);
                float2 o;
                o.x = yreg[nf][0] + Dh * x00;
                o.y = yreg[nf][1] + Dh * x01;
                *(float2*)&g_y[(rowbase + t)*DINNER + h*HEADDIM + p0] = o;
                o.x = yreg[nf][2] + Dh * x10;
                o.y = yreg[nf][3] + Dh * x11;
                *(float2*)&g_y[(rowbase + t + 8)*DINNER + h*HEADDIM + p0] = o;
            }
        }
    }

    // ================= GEMM3: S = X^T @ (w*B) (64p x 128n, K=64) ==========
    {
        float sreg[2][4][4];
        #pragma unroll
        for (int i = 0; i < 2; i++)
            #pragma unroll
            for (int j = 0; j < 4; j++)
                #pragma unroll
                for (int r = 0; r < 4; r++) sreg[i][j][r] = 0.f;

        const int m3 = (warp >> 2) * 32, n3 = (warp & 3) * 32;
        #pragma unroll
        for (int kb = 0; kb < 4; kb++) {
            const int kp0 = kb * 8;
            uint32_t aH[2][4], aL[2][4], bH[4][2], bL[4][2];
            #pragma unroll
            for (int mf = 0; mf < 2; mf++) {
                const int r = (m3 + lrow + mf*16) * XSTRIDE + kp0 + lkp;
                uint32_t ad = (uint32_t)__cvta_generic_to_shared(&XHs[r]);
                LDSM_X4(aH[mf][0], aH[mf][1], aH[mf][2], aH[mf][3], ad);
                ad = (uint32_t)__cvta_generic_to_shared(&XLs[r]);
                LDSM_X4(aL[mf][0], aL[mf][1], aL[mf][2], aL[mf][3], ad);
            }
            #pragma unroll
            for (int nf2 = 0; nf2 < 2; nf2++) {
                const int r = (n3 + brow + nf2*16) * XSTRIDE + kp0 + bkp;
                uint32_t bd = (uint32_t)__cvta_generic_to_shared(&BHs[r]);
                LDSM_X4(bH[2*nf2][0], bH[2*nf2][1], bH[2*nf2+1][0], bH[2*nf2+1][1], bd);
                bd = (uint32_t)__cvta_generic_to_shared(&BLs[r]);
                LDSM_X4(bL[2*nf2][0], bL[2*nf2][1], bL[2*nf2+1][0], bL[2*nf2+1][1], bd);
            }
            #pragma unroll
            for (int mf = 0; mf < 2; mf++)
                #pragma unroll
                for (int nf = 0; nf < 4; nf++)
                    MMA3B(sreg[mf][nf], aH[mf], aL[mf], bH[nf], bL[nf]);
        }

        const size_t sbase = ((size_t)bh * NSEG + seg) * STATESZ;
        #pragma unroll
        for (int mf = 0; mf < 2; mf++) {
            int p = m3 + mf*16 + qr;
            #pragma unroll
            for (int nf = 0; nf < 4; nf++) {
                int n0 = n3 + nf*8 + ql*2;
                float2 o0 = make_float2(sreg[mf][nf][0], sreg[mf][nf][1]);
                float2 o1 = make_float2(sreg[mf][nf][2], sreg[mf][nf][3]);
                *(float2*)&g_states[sbase + (size_t)p * DSTATE + n0]       = o0;
                *(float2*)&g_states[sbase + (size_t)(p + 8) * DSTATE + n0] = o1;
            }
        }
    }
}

// =================================================================
// K2: combine — NSEG=32, emits pre-split bf16 hi/lo hstart pairs
// =================================================================
__global__ __launch_bounds__(256) void combine_kernel(const float* __restrict__ A_log)
{
    const int bh = blockIdx.x;
    const int b = bh / NHEADS, h = bh % NHEADS;
    const int tid = threadIdx.x;

    __shared__ float part[256];
    __shared__ float Esh[NSEG];

    {
        const int k = tid >> 3, i = tid & 7;     // 32 segs x 8 partials
        float s = 0.f;
        const size_t base = ((size_t)b*LSEQ + k*SEGLEN + i*8)*NHEADS + h;
        #pragma unroll
        for (int t = 0; t < 8; t++) s += g_dt[base + (size_t)t*NHEADS];
        part[tid] = s;
    }
    __syncthreads();
    if (tid < NSEG) {
        float s = 0.f;
        #pragma unroll
        for (int i = 0; i < 8; i++) s += part[tid*8 + i];
        Esh[tid] = expf(-expf(A_log[h]) * s);
    }
    __syncthreads();

    float2 hs[16];
    #pragma unroll
    for (int k2 = 0; k2 < 16; k2++) hs[k2] = make_float2(0.f, 0.f);

    for (int seg = 0; seg < NSEG; seg++) {
        const size_t pbase = ((size_t)bh*NSEG + seg)*STATEPAIRS;
        const float E = Esh[seg];
        #pragma unroll
        for (int k2 = 0; k2 < 16; k2++) {
            const size_t j = pbase + k2*256 + tid;
            uint32_t hh, ll;
            bsplit2(hs[k2].x, hs[k2].y, hh, ll);
            g_hsH[j] = hh;  g_hsL[j] = ll;
            float2 s = ((const float2*)g_states)[j];
            hs[k2].x = fmaf(hs[k2].x, E, s.x);
            hs[k2].y = fmaf(hs[k2].y, E, s.y);
        }
    }
}

// =================================================================
// K3: inter-chunk — T=64, 256 threads, ~70KB smem (3 CTA/SM)
// CH2/CL2 [64][68]@0/@4352; HHs/HLs [64][68]@8704/@13056; su@17408
// =================================================================
__global__ __launch_bounds__(256) void inter_kernel(const float* __restrict__ A_log)
{
    extern __shared__ uint32_t smu[];
    uint32_t* CH2 = smu;
    uint32_t* CL2 = smu + 4352;
    uint32_t* HHs = smu + 8704;
    uint32_t* HLs = smu + 13056;
    float*    su  = (float*)(smu + 17408);
    float*    wsum2 = (float*)(smu + 17472);

    const int blk = blockIdx.x;
    const int bh = blk >> 5, seg = blk & (NSEG - 1);
    const int b = bh / NHEADS, h = bh % NHEADS;
    const int tid = threadIdx.x, lane = tid & 31, warp = tid >> 5;
    const int qr = lane >> 2, ql = lane & 3;
    const size_t rowbase = (size_t)b * LSEQ + seg * SEGLEN;
    const size_t hpb = ((size_t)bh * NSEG + seg) * STATEPAIRS;

    const int lrow = lane & 15;
    const int lkp  = (lane >> 4) << 2;
    const int brow = ((lane >> 4) << 3) + (lane & 7);
    const int bkp  = ((lane >> 3) & 1) << 2;

    // C tile: 64 rows x 64 pairs (bc words 64..127)
    #pragma unroll
    for (int i = 0; i < 4; i++) {
        int e = tid + i * 256;           // < 1024
        int t = e >> 4, g = (e & 15) * 4;
        const size_t srcw = (rowbase + t) * 128 + 64 + g;
        CPA16((uint32_t)__cvta_generic_to_shared(&CH2[t*TSTRIDE + g]), g_bcH + srcw);
        CPA16((uint32_t)__cvta_generic_to_shared(&CL2[t*TSTRIDE + g]), g_bcL + srcw);
    }
    // H tile: 64 p rows x 64 pairs
    #pragma unroll
    for (int i = 0; i < 4; i++) {
        int e = tid + i * 256;           // < 1024
        int p = e >> 4, g = (e & 15) * 4;
        const size_t srcw = hpb + (size_t)p * 64 + g;
        CPA16((uint32_t)__cvta_generic_to_shared(&HHs[p*TSTRIDE + g]), g_hsH + srcw);
        CPA16((uint32_t)__cvta_generic_to_shared(&HLs[p*TSTRIDE + g]), g_hsL + srcw);
    }
    CPA_COMMIT();

    const float Aneg = -expf(A_log[h]);
    float vdt = 0.f, acs = 0.f;
    if (tid < SEGLEN) {
        vdt = g_dt[(rowbase + tid) * NHEADS + h];
        acs = vdt;
        #pragma unroll
        for (int o = 1; o < 32; o <<= 1) {
            float nv = __shfl_up_sync(0xffffffffu, acs, o);
            if (lane >= o) acs += nv;
        }
        if (lane == 31) wsum2[warp] = acs;
    }
    __syncthreads();
    if (tid < SEGLEN) {
        float pre = (warp == 1) ? wsum2[0] : 0.f;
        su[tid] = __expf(Aneg * (acs + pre));
    }
    CPA_WAIT0();
    __syncthreads();

    float yreg[4][4];
    #pragma unroll
    for (int j = 0; j < 4; j++)
        #pragma unroll
        for (int r = 0; r < 4; r++) yreg[j][r] = 0.f;

    const int m2 = (warp >> 1) * 16, n2 = (warp & 1) * 32;
    #pragma unroll
    for (int kb = 0; kb < 8; kb++) {
        const int kp0 = kb * 8;
        uint32_t aH[4], aL[4], bH[4][2], bL[4][2];
        {
            const int r = (m2 + lrow) * TSTRIDE + kp0 + lkp;
            uint32_t ad = (uint32_t)__cvta_generic_to_shared(&CH2[r]);
            LDSM_X4(aH[0], aH[1], aH[2], aH[3], ad);
            ad = (uint32_t)__cvta_generic_to_shared(&CL2[r]);
            LDSM_X4(aL[0], aL[1], aL[2], aL[3], ad);
        }
        #pragma unroll
        for (int nf2 = 0; nf2 < 2; nf2++) {
            const int r = (n2 + brow + nf2*16) * TSTRIDE + kp0 + bkp;
            uint32_t bd = (uint32_t)__cvta_generic_to_shared(&HHs[r]);
            LDSM_X4(bH[2*nf2][0], bH[2*nf2][1], bH[2*nf2+1][0], bH[2*nf2+1][1], bd);
            bd = (uint32_t)__cvta_generic_to_shared(&HLs[r]);
            LDSM_X4(bL[2*nf2][0], bL[2*nf2][1], bL[2*nf2+1][0], bL[2*nf2+1][1], bd);
        }
        #pragma unroll
        for (int nf = 0; nf < 4; nf++)
            MMA3B(yreg[nf], aH, aL, bH[nf], bL[nf]);
    }

    {
        int t = m2 + qr;
        float u0 = su[t], u1 = su[t + 8];
        #pragma unroll
        for (int nf = 0; nf < 4; nf++) {
            int p0 = n2 + nf*8 + ql*2;
            float* addr0 = &g_y[(rowbase + t)*DINNER + h*HEADDIM + p0];
            float* addr1 = &g_y[(rowbase + t + 8)*DINNER + h*HEADDIM + p0];
            float2 o0 = *(float2*)addr0;
            float2 o1 = *(float2*)addr1;
            o0.x += u0 * yreg[nf][0];  o0.y += u0 * yreg[nf][1];
            o1.x += u1 * yreg[nf][2];  o1.y += u1 * yreg[nf][3];
            *(float2*)addr0 = o0;
            *(float2*)addr1 = o1;
        }
    }
}

// =================================================================
// gate+norm: y = y*silu(z); rmsnorm; emit packed fp16 pairs
// =================================================================
__global__ __launch_bounds__(256) void gate_norm_kernel(const float* __restrict__ norm_w)
{
    const int row = blockIdx.x;
    const int tid = threadIdx.x;
    const float* zrow = g_zxbcdt + (size_t)row * DPROJ;
    const float* yrow = g_y + (size_t)row * DINNER;

    float2 v[3];
    float ss = 0.f;
    #pragma unroll
    for (int i = 0; i < 3; i++) {
        int p = tid + i*256;
        float2 z2 = *(const float2*)&zrow[2*p];
        float2 y2 = *(const float2*)&yrow[2*p];
        float g0 = y2.x * (z2.x / (1.f + expf(-z2.x)));
        float g1 = y2.y * (z2.y / (1.f + expf(-z2.y)));
        v[i] = make_float2(g0, g1);
        ss += g0*g0 + g1*g1;
    }
    #pragma unroll
    for (int o = 16; o > 0; o >>= 1) ss += __shfl_xor_sync(0xffffffffu, ss, o);
    __shared__ float red[8];
    if ((tid & 31) == 0) red[tid >> 5] = ss;
    __syncthreads();
    if (tid < 32) {
        float s2 = (tid < 8) ? red[tid] : 0.f;
        #pragma unroll
        for (int o = 4; o > 0; o >>= 1) s2 += __shfl_xor_sync(0xffffffffu, s2, o);
        if (tid == 0) red[0] = s2;
    }
    __syncthreads();
    const float rstd = rsqrtf(red[0] * (1.f/1536.f) + 1e-5f);
    #pragma unroll
    for (int i = 0; i < 3; i++) {
        int p = tid + i*256;
        float2 w2 = *(const float2*)&norm_w[2*p];
        g_y16[(size_t)row * (DINNER/2) + p] =
            packh2(v[i].x * rstd * w2.x, v[i].y * rstd * w2.y);
    }
}

// =================================================================
extern "C" void kernel_launch(void* const* d_in, const int* in_sizes, int n_in,
                              void* d_out, int out_size)
{
    const float* feature   = (const float*)d_in[0];
    const float* in_proj_w = (const float*)d_in[1];
    const float* conv_w    = (const float*)d_in[2];
    const float* conv_b    = (const float*)d_in[3];
    const float* dt_bias   = (const float*)d_in[4];
    const float* A_log     = (const float*)d_in[5];
    const float* Dvec      = (const float*)d_in[6];
    const float* norm_w    = (const float*)d_in[7];
    const float* out_projw = (const float*)d_in[8];
    const float* gate1     = (const float*)d_in[9];
    float* out = (float*)d_out;

    float *zx;
    uint32_t *f16, *iw16, *ow16, *y16;
    cudaGetSymbolAddress((void**)&zx,   g_zxbcdt);
    cudaGetSymbolAddress((void**)&f16,  g_feat16);
    cudaGetSymbolAddress((void**)&iw16, g_ipw16);
    cudaGetSymbolAddress((void**)&ow16, g_opw16);
    cudaGetSymbolAddress((void**)&y16,  g_y16);

    cudaFuncSetAttribute(gemm_fp16,
        cudaFuncAttributeMaxDynamicSharedMemorySize, GP_SMEM);
    cudaFuncSetAttribute(chunk_fused_kernel,
        cudaFuncAttributeMaxDynamicSharedMemorySize, K1_SMEM_U32 * 4);
    cudaFuncSetAttribute(inter_kernel,
        cudaFuncAttributeMaxDynamicSharedMemorySize, K3_SMEM_U32 * 4);

    dim3 blk(256);

    tofp16_kernel<<<(ROWS*DMODEL/2)/256, blk>>>(feature, f16);
    tofp16_kernel<<<(DPROJ*DMODEL/2)/256, blk>>>(in_proj_w, iw16);
    tofp16_kernel<<<(DMODEL*DINNER/2)/256, blk>>>(out_projw, ow16);

    gemm_fp16<<<dim3((DPROJ + 127)/128, ROWS/128), blk, GP_SMEM>>>(
        f16, iw16, zx, ROWS, DPROJ, DMODEL/2, nullptr);

    conv_silu_kernel<<<(int)(((long)ROWS * (CONVDIM/2)) / 256), blk>>>(conv_w, conv_b);
    dt_kernel<<<(ROWS * NHEADS) / 256, blk>>>(dt_bias);

    chunk_fused_kernel<<<BATCH * NHEADS * NSEG, blk, K1_SMEM_U32 * 4>>>(A_log, Dvec);
    combine_kernel<<<BATCH * NHEADS, blk>>>(A_log);
    inter_kernel<<<BATCH * NHEADS * NSEG, blk, K3_SMEM_U32 * 4>>>(A_log);

    gate_norm_kernel<<<ROWS, blk>>>(norm_w);

    gemm_fp16<<<dim3(DMODEL/128, ROWS/128), blk, GP_SMEM>>>(
        y16, ow16, out, ROWS, DMODEL, DINNER/2, gate1);
}